// round 1
// baseline (speedup 1.0000x reference)
#include <cuda_runtime.h>
#include <math.h>

#define Bn 16
#define Dn 256
#define Ln 200
#define Tn 1000
#define TT 10

#define OFF_MEAN ((size_t)0)
#define OFF_LOG  ((size_t)4096000)
#define OFF_FM   ((size_t)8192000)
#define OFF_FL   ((size_t)8208000)
#define OFF_W    ((size_t)8208016)

// ---------------- device scratch (no allocs allowed) ----------------
__device__ float g_sk[Bn*Ln];
__device__ int   g_plen[Bn];
__device__ int   g_flen[Bn];
__device__ float g_phonT[(size_t)Bn*Ln*Dn];          // [b][l][d]
__device__ float g_hw[(size_t)Bn*Ln*8];              // [b][l][o]
__device__ float g_hc[(size_t)Bn*Ln*8];
__device__ float g_Ceff[2*8*3*Dn];                   // [which][o][k][d']
__device__ float g_beff[2*8*3];                      // [which][o][variant]
__device__ float g_P[(size_t)Bn*Ln*4*Dn];            // [b][l][q][d]

__device__ __forceinline__ float silu_f(float x){ return x/(1.f+__expf(-x)); }

// ---------------- K1: durations scan, frame mask/lengths ----------------
__global__ void k_setup(const float* __restrict__ dur, float* __restrict__ out){
  int b = blockIdx.x, tid = threadIdx.x;
  __shared__ float s[Ln];
  __shared__ int sfl;
  if (tid < Ln) s[tid] = dur[b*Ln+tid];
  __syncthreads();
  if (tid == 0){
    float acc = 0.f; int plen = 0;
    for (int l=0;l<Ln;l++){ g_sk[b*Ln+l]=acc; float d=s[l]; acc+=d; if (d>0.f) plen=l+1; }
    g_plen[b]=plen;
    int fl = (int)rintf(acc); fl = fl<0?0:(fl>Tn?Tn:fl);
    g_flen[b]=fl; sfl=fl;
    out[OFF_FL + b] = (float)fl;
  }
  __syncthreads();
  int fl = sfl;
  for (int t=tid;t<Tn;t+=blockDim.x) out[OFF_FM + (size_t)b*Tn + t] = (t<fl)?1.f:0.f;
}

// ---------------- K2: fold pointwise W into conv kernel ----------------
__global__ void k_ceff(const float* __restrict__ Cw, const float* __restrict__ Wpw,
                       const float* __restrict__ Cc, const float* __restrict__ Wpc){
  int o=blockIdx.x, k=blockIdx.y, which=blockIdx.z, dp=threadIdx.x;
  const float* C = which? Cc : Cw;
  const float* W = which? Wpc : Wpw;
  float acc=0.f;
  for (int d=0; d<Dn; d++)
    acc = fmaf(C[(o*Dn+d)*3+k], W[d*Dn+dp], acc);
  g_Ceff[((which*8+o)*3+k)*Dn + dp] = acc;
}

__global__ void k_beff(const float* __restrict__ Cw, const float* __restrict__ bpw, const float* __restrict__ cbw,
                       const float* __restrict__ Cc, const float* __restrict__ bpc, const float* __restrict__ cbc){
  int id = threadIdx.x; if (id>=48) return;
  int which = id/24, rem = id%24, o = rem/3, var = rem%3;
  const float* C = which? Cc: Cw; const float* bp = which? bpc : bpw; const float* cb = which? cbc : cbw;
  int k0 = (var==0)?1:0, k1 = (var==2)?1:2;   // SAME-pad edge tap sets
  float acc = cb[o];
  for (int d=0;d<Dn;d++)
    for (int k=k0;k<=k1;k++) acc = fmaf(C[(o*Dn+d)*3+k], bp[d], acc);
  g_beff[(which*8+o)*3+var] = acc;
}

// ---------------- K3: phoneme transpose [b][d][l] -> [b][l][d] ----------------
__global__ void k_transpose(const float* __restrict__ phon){
  __shared__ float tile[32][33];
  int b=blockIdx.z, d0=blockIdx.y*32, l0=blockIdx.x*32;
  int lx = l0+threadIdx.x, dy = d0+threadIdx.y;
  if (lx < Ln) tile[threadIdx.y][threadIdx.x] = phon[((size_t)b*Dn+dy)*Ln + lx];
  __syncthreads();
  int dx = d0+threadIdx.x, ly = l0+threadIdx.y;
  if (ly < Ln) g_phonT[((size_t)b*Ln+ly)*Dn + dx] = tile[threadIdx.x][threadIdx.y];
}

// ---------------- K4: fused conv+silu -> h_w, h_c ----------------
__global__ void k_conv(){
  __shared__ float xs[10][Dn];
  int b = blockIdx.y, l0 = blockIdx.x*8;
  int tid = threadIdx.x;
  for (int i=tid; i<10*Dn; i+=256){
    int r = i>>8, dp = i&255, col = l0-1+r;
    xs[r][dp] = (col>=0 && col<Ln) ? g_phonT[((size_t)b*Ln+col)*Dn+dp] : 0.f;
  }
  __syncthreads();
  int warp = tid>>5, lane = tid&31;
  int l = l0 + warp;
  int plen = g_plen[b];
  for (int idx=0; idx<16; idx++){
    int which = idx>>3, o = idx&7;
    const float* ce = g_Ceff + ((which*8+o)*3)*Dn;
    float acc = 0.f;
    for (int i=lane; i<3*Dn; i+=32){
      int k = i>>8, dp = i&255;
      acc = fmaf(ce[k*Dn+dp], xs[(l-l0)+k][dp], acc);
    }
    #pragma unroll
    for (int off=16; off; off>>=1) acc += __shfl_xor_sync(0xffffffffu, acc, off);
    if (lane==0){
      int var = (l==0)?0:((l==Ln-1)?2:1);
      float h = silu_f(acc + g_beff[(which*8+o)*3+var]);
      h = (l < plen) ? h : 0.f;
      float* dst = which ? g_hc : g_hw;
      dst[((size_t)b*Ln+l)*8 + o] = h;
    }
  }
}

// ---------------- K5: P[b,l,q,:] = phonT[b,l,:] @ Lw_q ----------------
__global__ void k_P(const float* __restrict__ Lw){
  __shared__ float A[16][Dn];
  int c = blockIdx.x, q = blockIdx.y, b = blockIdx.z;
  int l0 = c*16, nl = min(16, Ln - l0);
  int tid = threadIdx.x;
  for (int i=tid; i<16*Dn; i+=256){
    int li = i>>8, dp = i&255;
    A[li][dp] = (li < nl) ? g_phonT[((size_t)b*Ln + l0+li)*Dn + dp] : 0.f;
  }
  __syncthreads();
  float acc[16];
  #pragma unroll
  for (int i=0;i<16;i++) acc[i]=0.f;
  const float* LwQ = Lw + (size_t)q*Dn*Dn;
  for (int dd=0; dd<Dn; dd++){
    float lw = LwQ[dd*Dn + tid];
    #pragma unroll
    for (int i=0;i<16;i++) acc[i] = fmaf(A[i][dd], lw, acc[i]);
  }
  for (int i=0;i<nl;i++)
    g_P[(((size_t)b*Ln + l0+i)*4 + q)*Dn + tid] = acc[i];
}

// ---------------- K6: main fused kernel, one block = (b, 10 frames) ----------------
__global__ __launch_bounds__(256) void k_main(
  const float* __restrict__ dur,
  const float* __restrict__ Mw, const float* __restrict__ mbw,
  const float* __restrict__ Mc, const float* __restrict__ mbc,
  const float* __restrict__ lbw, const float* __restrict__ Lcm, const float* __restrict__ lbc,
  const float* __restrict__ Wo, const float* __restrict__ bo,
  float* __restrict__ out)
{
  __shared__ __align__(16) char smbuf[48584];
  float4* w_s  = (float4*)smbuf;                 // [TT][Ln]  32000B
  float2* c_s  = (float2*)(smbuf + 32000);       // [TT][Ln]  16000B
  float*  y_s  = (float*)(smbuf + 32000);        // alias [TT][Dn] (after c dead)
  float*  wc_s = (float*)(smbuf + 48000);        // [TT][8]   320B
  float*  prm  = (float*)(smbuf + 48320);        // 66 floats

  int b = blockIdx.y;
  int t0 = blockIdx.x * TT;
  int tid = threadIdx.x;
  int plen = g_plen[b], flen = g_flen[b];

  if (tid < 40)      prm[tid] = Mw[tid];
  else if (tid < 44) prm[tid] = mbw[tid-40];
  else if (tid < 64) prm[tid] = Mc[tid-44];
  else if (tid < 66) prm[tid] = mbc[tid-64];
  __syncthreads();

  // phase 1: per-l MLP features (silu), per-thread l
  if (tid < Ln){
    int l = tid;
    float d  = dur[b*Ln + l];
    float sk = g_sk[b*Ln + l];
    const float* hwp = g_hw + ((size_t)b*Ln+l)*8;
    const float* hcp = g_hc + ((size_t)b*Ln+l)*8;
    float bw[4], bc[2];
    #pragma unroll
    for (int q=0;q<4;q++){
      float a = prm[40+q] + d*prm[4+q];
      #pragma unroll
      for (int j=0;j<8;j++) a = fmaf(hwp[j], prm[(2+j)*4+q], a);
      bw[q]=a;
    }
    #pragma unroll
    for (int p=0;p<2;p++){
      float a = prm[64+p] + d*prm[44+2+p];
      #pragma unroll
      for (int j=0;j<8;j++) a = fmaf(hcp[j], prm[44+(2+j)*2+p], a);
      bc[p]=a;
    }
    bool lv = l < plen;
    #pragma unroll
    for (int t=0;t<TT;t++){
      int tt = t0+t;
      float4 av = {0.f,0.f,0.f,0.f}; float2 cv = {0.f,0.f};
      if (lv && tt < flen){
        float S = (float)(tt+1) - sk;
        av.x = silu_f(fmaf(S, prm[0], bw[0]));
        av.y = silu_f(fmaf(S, prm[1], bw[1]));
        av.z = silu_f(fmaf(S, prm[2], bw[2]));
        av.w = silu_f(fmaf(S, prm[3], bw[3]));
        cv.x = silu_f(fmaf(S, prm[44], bc[0]));
        cv.y = silu_f(fmaf(S, prm[45], bc[1]));
      }
      w_s[t*Ln + l] = av;
      c_s[t*Ln + l] = cv;
    }
  }
  __syncthreads();

  // phase 2: softmax over l per (t,q), write w output, reduce wc
  int warp = tid>>5, lane = tid&31;
  for (int job=warp; job<TT*4; job+=8){
    int t = job>>2, q = job&3, tt = t0+t;
    size_t wbase = OFF_W + ((size_t)(b*4+q)*Tn + tt)*Ln;
    float* wq = (float*)(w_s + t*Ln) + q;   // element l at wq[4*l]
    if (tt >= flen){
      for (int l=lane; l<Ln; l+=32) out[wbase + l] = 0.f;
      if (lane==0){ wc_s[t*8+2*q]=0.f; wc_s[t*8+2*q+1]=0.f; }
      continue;
    }
    float m = -3.0e38f;
    for (int l=lane;l<plen;l+=32) m = fmaxf(m, wq[4*l]);
    #pragma unroll
    for (int off=16;off;off>>=1) m = fmaxf(m, __shfl_xor_sync(0xffffffffu,m,off));
    float s=0.f;
    for (int l=lane;l<plen;l+=32){ float e=__expf(wq[4*l]-m); wq[4*l]=e; s+=e; }
    #pragma unroll
    for (int off=16;off;off>>=1) s += __shfl_xor_sync(0xffffffffu,s,off);
    float inv = 1.f/s;
    float s0=0.f, s1=0.f;
    for (int l=lane;l<plen;l+=32){
      float v = wq[4*l]*inv; wq[4*l]=v;
      out[wbase+l]=v;
      float2 cc = c_s[t*Ln+l];
      s0 = fmaf(v, cc.x, s0); s1 = fmaf(v, cc.y, s1);
    }
    for (int l=plen+lane; l<Ln; l+=32) out[wbase+l]=0.f;
    #pragma unroll
    for (int off=16;off;off>>=1){
      s0 += __shfl_xor_sync(0xffffffffu,s0,off);
      s1 += __shfl_xor_sync(0xffffffffu,s1,off);
    }
    if (lane==0){ wc_s[t*8+2*q]=s0; wc_s[t*8+2*q+1]=s1; }
  }
  __syncthreads();

  // phase 3: y[t,d] = lbw+lbc + wc@Lc + sum_{l,q} w[t,l,q] * P[b,l,q,d]
  int d = tid;
  float y[TT];
  {
    float lb = lbw[d] + lbc[d];
    #pragma unroll
    for (int t=0;t<TT;t++){
      int tt=t0+t;
      if (tt<flen){
        float a = lb;
        #pragma unroll
        for (int i=0;i<8;i++) a = fmaf(wc_s[t*8+i], Lcm[i*Dn+d], a);
        y[t]=a;
      } else y[t]=0.f;
    }
  }
  const float* Pb = g_P + (size_t)b*Ln*4*Dn;
  for (int l=0;l<plen;l++){
    const float* pl = Pb + (size_t)l*4*Dn + d;
    float p0=pl[0], p1=pl[Dn], p2=pl[2*Dn], p3=pl[3*Dn];
    #pragma unroll
    for (int t=0;t<TT;t++){
      float4 wv = w_s[t*Ln+l];
      y[t] = fmaf(wv.x,p0,fmaf(wv.y,p1,fmaf(wv.z,p2,fmaf(wv.w,p3,y[t]))));
    }
  }
  #pragma unroll
  for (int t=0;t<TT;t++) y_s[t*Dn + d] = y[t];   // c_s dead, safe alias
  __syncthreads();

  // phase 4: out = y @ Wo + bo  (thread handles column tid and tid+256)
  float a0[TT], a1[TT];
  float b0 = bo[tid], b1 = bo[tid+Dn];
  #pragma unroll
  for (int t=0;t<TT;t++){ a0[t]=b0; a1[t]=b1; }
  for (int dd=0; dd<Dn; dd++){
    float w0 = Wo[dd*2*Dn + tid];
    float w1 = Wo[dd*2*Dn + tid + Dn];
    #pragma unroll
    for (int t=0;t<TT;t++){
      float yv = y_s[t*Dn+dd];
      a0[t] = fmaf(yv,w0,a0[t]);
      a1[t] = fmaf(yv,w1,a1[t]);
    }
  }
  size_t base_m = OFF_MEAN + ((size_t)b*Dn + tid)*Tn + t0;
  size_t base_l = OFF_LOG  + ((size_t)b*Dn + tid)*Tn + t0;
  #pragma unroll
  for (int t=0;t<TT;t++){
    out[base_m + t] = a0[t];
    out[base_l + t] = a1[t];
  }
}

// ---------------- launcher ----------------
extern "C" void kernel_launch(void* const* d_in, const int* in_sizes, int n_in,
                              void* d_out, int out_size){
  (void)in_sizes; (void)n_in; (void)out_size;
  const float* dur = (const float*)d_in[0];
  const float* phon= (const float*)d_in[1];
  // d_in[2] = phoneme_mask (bool) — unused; pm derived from durations > 0
  const float* Wpw = (const float*)d_in[3];
  const float* bpw = (const float*)d_in[4];
  const float* Cw  = (const float*)d_in[5];
  const float* cbw = (const float*)d_in[6];
  const float* Mw  = (const float*)d_in[7];
  const float* mbw = (const float*)d_in[8];
  const float* Lw  = (const float*)d_in[9];
  const float* lbw = (const float*)d_in[10];
  const float* Wpc = (const float*)d_in[11];
  const float* bpc = (const float*)d_in[12];
  const float* Cc  = (const float*)d_in[13];
  const float* cbc = (const float*)d_in[14];
  const float* Mc  = (const float*)d_in[15];
  const float* mbc = (const float*)d_in[16];
  const float* Lcm = (const float*)d_in[17];
  const float* lbc = (const float*)d_in[18];
  const float* Wo  = (const float*)d_in[19];
  const float* bo  = (const float*)d_in[20];
  float* out = (float*)d_out;

  k_setup<<<16,256>>>(dur, out);
  k_ceff<<<dim3(8,3,2),256>>>(Cw,Wpw,Cc,Wpc);
  k_beff<<<1,64>>>(Cw,bpw,cbw,Cc,bpc,cbc);
  k_transpose<<<dim3(7,8,16),dim3(32,32)>>>(phon);
  k_conv<<<dim3(25,16),256>>>();
  k_P<<<dim3(13,4,16),256>>>(Lw);
  k_main<<<dim3(100,16),256>>>(dur,Mw,mbw,Mc,mbc,lbw,Lcm,lbc,Wo,bo,out);
}

// round 3
// speedup vs baseline: 1.0785x; 1.0785x over previous
#include <cuda_runtime.h>
#include <math.h>

typedef unsigned long long ull;

#define Bn 16
#define Dn 256
#define Ln 200
#define Tn 1000
#define TT 20
#define NB (Tn/TT)

#define OFF_MEAN ((size_t)0)
#define OFF_LOG  ((size_t)4096000)
#define OFF_FM   ((size_t)8192000)
#define OFF_FL   ((size_t)8208000)
#define OFF_W    ((size_t)8208016)

// ---------------- device scratch ----------------
__device__ float g_sk[Bn*Ln];
__device__ int   g_plen[Bn];
__device__ int   g_flen[Bn];
__device__ float g_phonT[(size_t)Bn*Ln*Dn];          // [b][l][d]
__device__ float g_hw[(size_t)Bn*Ln*8];
__device__ float g_hc[(size_t)Bn*Ln*8];
__device__ float g_Ceff[2*8*3*Dn];
__device__ float g_beff[2*8*3];
__device__ float g_P[(size_t)Bn*Ln*Dn*4];            // [b][l][d][q]  (float4 per (l,d))

__device__ __forceinline__ float silu_f(float x){ return __fdividef(x, 1.f + __expf(-x)); }

__device__ __forceinline__ ull pack2(float a, float b){
  ull r; asm("mov.b64 %0,{%1,%2};" : "=l"(r) : "f"(a), "f"(b)); return r;
}
__device__ __forceinline__ ull fma2(ull a, ull b, ull c){
  ull d; asm("fma.rn.f32x2 %0,%1,%2,%3;" : "=l"(d) : "l"(a), "l"(b), "l"(c)); return d;
}
__device__ __forceinline__ void unpack2(ull v, float& a, float& b){
  asm("mov.b64 {%0,%1},%2;" : "=f"(a), "=f"(b) : "l"(v));
}

// ---------------- K1: durations scan, frame mask/lengths ----------------
__global__ void k_setup(const float* __restrict__ dur, float* __restrict__ out){
  int b = blockIdx.x, tid = threadIdx.x;
  __shared__ float s[Ln];
  __shared__ int sfl;
  if (tid < Ln) s[tid] = dur[b*Ln+tid];
  __syncthreads();
  if (tid == 0){
    float acc = 0.f; int plen = 0;
    for (int l=0;l<Ln;l++){ g_sk[b*Ln+l]=acc; float d=s[l]; acc+=d; if (d>0.f) plen=l+1; }
    g_plen[b]=plen;
    int fl = (int)rintf(acc); fl = fl<0?0:(fl>Tn?Tn:fl);
    g_flen[b]=fl; sfl=fl;
    out[OFF_FL + b] = (float)fl;
  }
  __syncthreads();
  int fl = sfl;
  for (int t=tid;t<Tn;t+=blockDim.x) out[OFF_FM + (size_t)b*Tn + t] = (t<fl)?1.f:0.f;
}

// ---------------- K2: fold pointwise W into conv kernel ----------------
__global__ void k_ceff(const float* __restrict__ Cw, const float* __restrict__ Wpw,
                       const float* __restrict__ Cc, const float* __restrict__ Wpc){
  int o=blockIdx.x, k=blockIdx.y, which=blockIdx.z, dp=threadIdx.x;
  const float* C = which? Cc : Cw;
  const float* W = which? Wpc : Wpw;
  float acc=0.f;
  for (int d=0; d<Dn; d++)
    acc = fmaf(C[(o*Dn+d)*3+k], W[d*Dn+dp], acc);
  g_Ceff[((which*8+o)*3+k)*Dn + dp] = acc;
}

__global__ void k_beff(const float* __restrict__ Cw, const float* __restrict__ bpw, const float* __restrict__ cbw,
                       const float* __restrict__ Cc, const float* __restrict__ bpc, const float* __restrict__ cbc){
  int id = threadIdx.x; if (id>=48) return;
  int which = id/24, rem = id%24, o = rem/3, var = rem%3;
  const float* C = which? Cc: Cw; const float* bp = which? bpc : bpw; const float* cb = which? cbc : cbw;
  int k0 = (var==0)?1:0, k1 = (var==2)?1:2;
  float acc = cb[o];
  for (int d=0;d<Dn;d++)
    for (int k=k0;k<=k1;k++) acc = fmaf(C[(o*Dn+d)*3+k], bp[d], acc);
  g_beff[(which*8+o)*3+var] = acc;
}

// ---------------- K3: phoneme transpose ----------------
__global__ void k_transpose(const float* __restrict__ phon){
  __shared__ float tile[32][33];
  int b=blockIdx.z, d0=blockIdx.y*32, l0=blockIdx.x*32;
  int lx = l0+threadIdx.x, dy = d0+threadIdx.y;
  if (lx < Ln) tile[threadIdx.y][threadIdx.x] = phon[((size_t)b*Dn+dy)*Ln + lx];
  __syncthreads();
  int dx = d0+threadIdx.x, ly = l0+threadIdx.y;
  if (ly < Ln) g_phonT[((size_t)b*Ln+ly)*Dn + dx] = tile[threadIdx.x][threadIdx.y];
}

// ---------------- K4: fused conv+silu -> h_w, h_c ----------------
__global__ void k_conv(){
  __shared__ float xs[10][Dn];
  int b = blockIdx.y, l0 = blockIdx.x*8;
  int tid = threadIdx.x;
  for (int i=tid; i<10*Dn; i+=256){
    int r = i>>8, dp = i&255, col = l0-1+r;
    xs[r][dp] = (col>=0 && col<Ln) ? g_phonT[((size_t)b*Ln+col)*Dn+dp] : 0.f;
  }
  __syncthreads();
  int warp = tid>>5, lane = tid&31;
  int l = l0 + warp;
  int plen = g_plen[b];
  for (int idx=0; idx<16; idx++){
    int which = idx>>3, o = idx&7;
    const float* ce = g_Ceff + ((which*8+o)*3)*Dn;
    float acc = 0.f;
    for (int i=lane; i<3*Dn; i+=32){
      int k = i>>8, dp = i&255;
      acc = fmaf(ce[k*Dn+dp], xs[(l-l0)+k][dp], acc);
    }
    #pragma unroll
    for (int off=16; off; off>>=1) acc += __shfl_xor_sync(0xffffffffu, acc, off);
    if (lane==0){
      int var = (l==0)?0:((l==Ln-1)?2:1);
      float h = silu_f(acc + g_beff[(which*8+o)*3+var]);
      h = (l < plen) ? h : 0.f;
      float* dst = which ? g_hc : g_hw;
      dst[((size_t)b*Ln+l)*8 + o] = h;
    }
  }
}

// ---------------- K5: P[b,l,:,q] = phonT[b,l,:] @ Lw_q  (packed f32x2 over l) ----------------
__global__ void k_P(const float* __restrict__ Lw){
  __shared__ float A[Dn*16];   // [dd][li]
  int c = blockIdx.x, q = blockIdx.y, b = blockIdx.z;
  int l0 = c*16, nl = min(16, Ln - l0);
  int tid = threadIdx.x;
  for (int i=tid; i<16*Dn; i+=256){
    int li = i>>8, dp = i&255;
    A[dp*16+li] = (li < nl) ? g_phonT[((size_t)b*Ln + l0+li)*Dn + dp] : 0.f;
  }
  __syncthreads();
  ull acc[8];
  #pragma unroll
  for (int j=0;j<8;j++) acc[j]=pack2(0.f,0.f);
  const float* LwQ = Lw + (size_t)q*Dn*Dn;
  for (int dd=0; dd<Dn; dd++){
    float lw = LwQ[dd*Dn + tid];
    ull lw2 = pack2(lw, lw);
    const ulonglong2* ap = (const ulonglong2*)(A + dd*16);
    #pragma unroll
    for (int j=0;j<4;j++){
      ulonglong2 av = ap[j];
      acc[2*j]   = fma2(av.x, lw2, acc[2*j]);
      acc[2*j+1] = fma2(av.y, lw2, acc[2*j+1]);
    }
  }
  #pragma unroll
  for (int j=0;j<8;j++){
    float a,b2; unpack2(acc[j], a, b2);
    int i0 = 2*j, i1 = 2*j+1;
    if (i0 < nl) g_P[(((size_t)b*Ln + l0+i0)*Dn + tid)*4 + q] = a;
    if (i1 < nl) g_P[(((size_t)b*Ln + l0+i1)*Dn + tid)*4 + q] = b2;
  }
}

// ---------------- K6: main fused kernel: one block = (b, 20 frames) ----------------
// dyn smem layout (floats):
//  w_s  : [l][ t*4+q ]  stride 84/l          0     .. 16800
//  y_s  : [dd][t]       stride 20            16800 .. 21920
//  sk_s : [l]                                21920 .. 22120
//  bc_s : [l][2]                             22120 .. 22520
//  wc_s : [t][8]                             22520 .. 22680
//  prm  : 66                                 22680 .. 22746
#define SMEM_FLOATS 22746

__global__ __launch_bounds__(256,2) void k_main(
  const float* __restrict__ dur,
  const float* __restrict__ Mw, const float* __restrict__ mbw,
  const float* __restrict__ Mc, const float* __restrict__ mbc,
  const float* __restrict__ lbw, const float* __restrict__ Lcm, const float* __restrict__ lbc,
  const float* __restrict__ Wo, const float* __restrict__ bo,
  float* __restrict__ out)
{
  extern __shared__ float sm[];
  float* w_s  = sm;
  float* y_s  = sm + 16800;
  float* sk_s = sm + 21920;
  float* bc_s = sm + 22120;
  float* wc_s = sm + 22520;
  float* prm  = sm + 22680;

  int b = blockIdx.y;
  int t0 = blockIdx.x * TT;
  int tid = threadIdx.x;
  int plen = g_plen[b], flen = g_flen[b];

  if (tid < 40)      prm[tid] = Mw[tid];
  else if (tid < 44) prm[tid] = mbw[tid-40];
  else if (tid < 64) prm[tid] = Mc[tid-44];
  else if (tid < 66) prm[tid] = mbc[tid-64];
  __syncthreads();

  // ---- phase 1: per-l features; w pre-softmax into w_s, c-bias into bc_s ----
  if (tid < Ln){
    int l = tid;
    float dv = dur[b*Ln + l];
    float sk = g_sk[b*Ln + l];
    sk_s[l] = sk;
    const float* hwp = g_hw + ((size_t)b*Ln+l)*8;
    const float* hcp = g_hc + ((size_t)b*Ln+l)*8;
    float bw[4], bc[2];
    #pragma unroll
    for (int q=0;q<4;q++){
      float a = prm[40+q] + dv*prm[4+q];
      #pragma unroll
      for (int j=0;j<8;j++) a = fmaf(hwp[j], prm[(2+j)*4+q], a);
      bw[q]=a;
    }
    #pragma unroll
    for (int p=0;p<2;p++){
      float a = prm[64+p] + dv*prm[46+p];
      #pragma unroll
      for (int j=0;j<8;j++) a = fmaf(hcp[j], prm[44+(2+j)*2+p], a);
      bc[p]=a;
    }
    bc_s[2*l]   = bc[0];
    bc_s[2*l+1] = bc[1];
    bool lv = l < plen;
    float4* wl = (float4*)(w_s + l*84);
    #pragma unroll
    for (int t=0;t<TT;t++){
      int tt = t0+t;
      float4 av = {0.f,0.f,0.f,0.f};
      if (lv && tt < flen){
        float S = (float)(tt+1) - sk;
        av.x = silu_f(fmaf(S, prm[0], bw[0]));
        av.y = silu_f(fmaf(S, prm[1], bw[1]));
        av.z = silu_f(fmaf(S, prm[2], bw[2]));
        av.w = silu_f(fmaf(S, prm[3], bw[3]));
      }
      wl[t] = av;
    }
  }
  __syncthreads();

  // ---- phase 2: softmax over l per (t,q); write w out; reduce wc (c recomputed) ----
  int warp = tid>>5, lane = tid&31;
  float mc0 = prm[44], mc1 = prm[45];
  for (int job=warp; job<TT*4; job+=8){
    int t = job>>2, q = job&3, tt = t0+t;
    size_t wbase = OFF_W + ((size_t)(b*4+q)*Tn + tt)*Ln;
    if (tt >= flen){
      for (int l=lane; l<Ln; l+=32) out[wbase + l] = 0.f;
      if (lane==0){ wc_s[t*8+2*q]=0.f; wc_s[t*8+2*q+1]=0.f; }
      continue;
    }
    float m = -3.0e38f;
    for (int l=lane;l<plen;l+=32) m = fmaxf(m, w_s[l*84+t*4+q]);
    #pragma unroll
    for (int off=16;off;off>>=1) m = fmaxf(m, __shfl_xor_sync(0xffffffffu,m,off));
    float s=0.f;
    for (int l=lane;l<plen;l+=32){
      int idx = l*84+t*4+q;
      float e=__expf(w_s[idx]-m); w_s[idx]=e; s+=e;
    }
    #pragma unroll
    for (int off=16;off;off>>=1) s += __shfl_xor_sync(0xffffffffu,s,off);
    float inv = 1.f/s;
    float Sb = (float)(tt+1);
    float s0=0.f, s1=0.f;
    for (int l=lane;l<plen;l+=32){
      int idx = l*84+t*4+q;
      float v = w_s[idx]*inv; w_s[idx]=v;
      out[wbase+l]=v;
      float S = Sb - sk_s[l];
      float cx = silu_f(fmaf(S, mc0, bc_s[2*l]));
      float cy = silu_f(fmaf(S, mc1, bc_s[2*l+1]));
      s0 = fmaf(v, cx, s0); s1 = fmaf(v, cy, s1);
    }
    for (int l=plen+lane; l<Ln; l+=32) out[wbase+l]=0.f;
    #pragma unroll
    for (int off=16;off;off>>=1){
      s0 += __shfl_xor_sync(0xffffffffu,s0,off);
      s1 += __shfl_xor_sync(0xffffffffu,s1,off);
    }
    if (lane==0){ wc_s[t*8+2*q]=s0; wc_s[t*8+2*q+1]=s1; }
  }
  __syncthreads();

  // ---- phase 3: y[t,d] = init + sum_{l,q} w[t,l,q]*P[b,l,d,q]  (f32x2 packed) ----
  {
    int d = tid;
    float lc[8];
    #pragma unroll
    for (int i=0;i<8;i++) lc[i] = Lcm[i*Dn+d];
    float lb = lbw[d] + lbc[d];
    ull yA[TT];
    #pragma unroll
    for (int t=0;t<TT;t++){
      int tt=t0+t;
      float a = 0.f;
      if (tt<flen){
        a = lb;
        #pragma unroll
        for (int i=0;i<8;i++) a = fmaf(wc_s[t*8+i], lc[i], a);
      }
      yA[t] = pack2(a, 0.f);
    }
    const float4* Pb4 = ((const float4*)g_P) + (size_t)b*Ln*Dn;
    float4 pf0 = Pb4[d];
    float4 pf1 = Pb4[Dn + d];
    for (int l=0;l<plen;l++){
      float4 nv;
      if (l+2 < plen) nv = Pb4[(size_t)(l+2)*Dn + d];
      else nv = make_float4(0.f,0.f,0.f,0.f);
      ull pq01 = pack2(pf0.x, pf0.y);
      ull pq23 = pack2(pf0.z, pf0.w);
      const ulonglong2* wl = (const ulonglong2*)(w_s + l*84);
      #pragma unroll
      for (int t=0;t<TT;t++){
        ulonglong2 wv = wl[t];
        yA[t] = fma2(wv.y, pq23, fma2(wv.x, pq01, yA[t]));
      }
      pf0 = pf1; pf1 = nv;
    }
    ull* yrow = (ull*)(y_s + d*TT);
    #pragma unroll
    for (int t=0;t<TT;t+=2){
      float a,b2,c2,d2;
      unpack2(yA[t],   a, b2);
      unpack2(yA[t+1], c2, d2);
      yrow[t>>1] = pack2(a+b2, c2+d2);
    }
  }
  __syncthreads();

  // ---- phase 4: out = y @ Wo + bo  (packed pairs over t) ----
  {
    ull a0p[TT/2], a1p[TT/2];
    float b0 = bo[tid], b1 = bo[tid+Dn];
    #pragma unroll
    for (int i=0;i<TT/2;i++){ a0p[i]=pack2(b0,b0); a1p[i]=pack2(b1,b1); }
    for (int dd=0; dd<Dn; dd++){
      float w0 = Wo[dd*2*Dn + tid];
      float w1 = Wo[dd*2*Dn + tid + Dn];
      ull w0p = pack2(w0,w0);
      ull w1p = pack2(w1,w1);
      const ull* yrow = (const ull*)(y_s + dd*TT);
      #pragma unroll
      for (int i=0;i<TT/2;i++){
        ull yv = yrow[i];
        a0p[i] = fma2(yv, w0p, a0p[i]);
        a1p[i] = fma2(yv, w1p, a1p[i]);
      }
    }
    size_t base_m = OFF_MEAN + ((size_t)b*Dn + tid)*Tn + t0;
    size_t base_l = OFF_LOG  + ((size_t)b*Dn + tid)*Tn + t0;
    #pragma unroll
    for (int i=0;i<TT/2;i++){
      *(ull*)&out[base_m + 2*i] = a0p[i];
      *(ull*)&out[base_l + 2*i] = a1p[i];
    }
  }
}

// ---------------- launcher ----------------
extern "C" void kernel_launch(void* const* d_in, const int* in_sizes, int n_in,
                              void* d_out, int out_size){
  (void)in_sizes; (void)n_in; (void)out_size;
  const float* dur = (const float*)d_in[0];
  const float* phon= (const float*)d_in[1];
  const float* Wpw = (const float*)d_in[3];
  const float* bpw = (const float*)d_in[4];
  const float* Cw  = (const float*)d_in[5];
  const float* cbw = (const float*)d_in[6];
  const float* Mw  = (const float*)d_in[7];
  const float* mbw = (const float*)d_in[8];
  const float* Lw  = (const float*)d_in[9];
  const float* lbw = (const float*)d_in[10];
  const float* Wpc = (const float*)d_in[11];
  const float* bpc = (const float*)d_in[12];
  const float* Cc  = (const float*)d_in[13];
  const float* cbc = (const float*)d_in[14];
  const float* Mc  = (const float*)d_in[15];
  const float* mbc = (const float*)d_in[16];
  const float* Lcm = (const float*)d_in[17];
  const float* lbc = (const float*)d_in[18];
  const float* Wo  = (const float*)d_in[19];
  const float* bo  = (const float*)d_in[20];
  float* out = (float*)d_out;

  static int smem_set = 0;
  cudaFuncSetAttribute((const void*)k_main, cudaFuncAttributeMaxDynamicSharedMemorySize,
                       SMEM_FLOATS*4);
  (void)smem_set;

  k_setup<<<16,256>>>(dur, out);
  k_ceff<<<dim3(8,3,2),256>>>(Cw,Wpw,Cc,Wpc);
  k_beff<<<1,64>>>(Cw,bpw,cbw,Cc,bpc,cbc);
  k_transpose<<<dim3(7,8,16),dim3(32,32)>>>(phon);
  k_conv<<<dim3(25,16),256>>>();
  k_P<<<dim3(13,4,16),256>>>(Lw);
  k_main<<<dim3(NB,Bn),256,SMEM_FLOATS*4>>>(dur,Mw,mbw,Mc,mbc,lbw,Lcm,lbc,Wo,bo,out);
}

// round 5
// speedup vs baseline: 1.2586x; 1.1670x over previous
#include <cuda_runtime.h>
#include <math.h>

typedef unsigned long long ull;

#define Bn 16
#define Dn 256
#define Ln 200
#define Tn 1000
#define TT 16
#define NB 63            // ceil(1000/16)

#define OFF_MEAN ((size_t)0)
#define OFF_LOG  ((size_t)4096000)
#define OFF_FM   ((size_t)8192000)
#define OFF_FL   ((size_t)8208000)
#define OFF_W    ((size_t)8208016)

// ---------------- device scratch ----------------
__device__ float g_sk[Bn*Ln];
__device__ int   g_plen[Bn];
__device__ int   g_flen[Bn];
__device__ float g_phonT[(size_t)Bn*Ln*Dn];          // [b][l][d]
__device__ float g_hw[(size_t)Bn*Ln*8];
__device__ float g_hc[(size_t)Bn*Ln*8];
__device__ float g_Ceff[2*8*3*Dn];
__device__ float g_beff[2*8*3];
__device__ float g_P[(size_t)Bn*Ln*Dn*4];            // [b][l][d][q]

__device__ __forceinline__ float silu_f(float x){ return __fdividef(x, 1.f + __expf(-x)); }

__device__ __forceinline__ ull pack2(float a, float b){
  ull r; asm("mov.b64 %0,{%1,%2};" : "=l"(r) : "f"(a), "f"(b)); return r;
}
__device__ __forceinline__ ull fma2(ull a, ull b, ull c){
  ull d; asm("fma.rn.f32x2 %0,%1,%2,%3;" : "=l"(d) : "l"(a), "l"(b), "l"(c)); return d;
}
__device__ __forceinline__ void unpack2(ull v, float& a, float& b){
  asm("mov.b64 {%0,%1},%2;" : "=f"(a), "=f"(b) : "l"(v));
}

// ================= K_PRE: setup + ceff + beff + transpose (fused) =================
// blocks 0..895: transpose tiles; 896..943: ceff; 944: beff; 945..960: setup
__global__ void k_pre(const float* __restrict__ dur, const float* __restrict__ phon,
                      const float* __restrict__ Cw, const float* __restrict__ Wpw,
                      const float* __restrict__ Cc, const float* __restrict__ Wpc,
                      const float* __restrict__ bpw, const float* __restrict__ cbw,
                      const float* __restrict__ bpc, const float* __restrict__ cbc,
                      float* __restrict__ out){
  __shared__ float tile[32][33];
  __shared__ int sfl;
  int bi = blockIdx.x, tid = threadIdx.x;

  if (bi < 896){
    // ---- transpose ----
    int l0 = (bi%7)*32, d0 = ((bi/7)%8)*32, b = bi/56;
    int tx = tid&31, ty = tid>>5;
    #pragma unroll
    for (int r=0;r<4;r++){
      int dy = d0+ty+8*r, lx = l0+tx;
      tile[ty+8*r][tx] = (lx<Ln) ? phon[((size_t)b*Dn+dy)*Ln+lx] : 0.f;
    }
    __syncthreads();
    #pragma unroll
    for (int r=0;r<4;r++){
      int ly = l0+ty+8*r, dx = d0+tx;
      if (ly<Ln) g_phonT[((size_t)b*Ln+ly)*Dn+dx] = tile[tx][ty+8*r];
    }
  } else if (bi < 944){
    // ---- ceff ----
    int idx = bi-896;
    int o = idx&7, k = (idx>>3)%3, which = idx/24;
    const float* C = which? Cc : Cw;
    const float* W = which? Wpc : Wpw;
    float acc=0.f;
    for (int d=0; d<Dn; d++)
      acc = fmaf(C[(o*Dn+d)*3+k], W[d*Dn+tid], acc);
    g_Ceff[((which*8+o)*3+k)*Dn + tid] = acc;
  } else if (bi == 944){
    // ---- beff ----
    if (tid < 48){
      int which = tid/24, rem = tid%24, o = rem/3, var = rem%3;
      const float* C = which? Cc: Cw; const float* bp = which? bpc : bpw; const float* cb = which? cbc : cbw;
      int k0 = (var==0)?1:0, k1 = (var==2)?1:2;
      float acc = cb[o];
      for (int d=0;d<Dn;d++)
        for (int k=k0;k<=k1;k++) acc = fmaf(C[(o*Dn+d)*3+k], bp[d], acc);
      g_beff[(which*8+o)*3+var] = acc;
    }
  } else {
    // ---- setup ----
    int b = bi-945;
    float* s = &tile[0][0];
    if (tid < Ln) s[tid] = dur[b*Ln+tid];
    __syncthreads();
    if (tid == 0){
      float acc = 0.f; int plen = 0;
      for (int l=0;l<Ln;l++){ g_sk[b*Ln+l]=acc; float d=s[l]; acc+=d; if (d>0.f) plen=l+1; }
      g_plen[b]=plen;
      int fl = (int)rintf(acc); fl = fl<0?0:(fl>Tn?Tn:fl);
      g_flen[b]=fl; sfl=fl;
      out[OFF_FL + b] = (float)fl;
    }
    __syncthreads();
    int fl = sfl;
    for (int t=tid;t<Tn;t+=256) out[OFF_FM + (size_t)b*Tn + t] = (t<fl)?1.f:0.f;
  }
}

// ================= K_MID: conv (blocks 0..399) + P GEMM (blocks 400..1231) =================
__global__ void k_mid(const float* __restrict__ Lw){
  __shared__ float sbuf[4096];
  int bi = blockIdx.x, tid = threadIdx.x;

  if (bi < 400){
    // ---- conv+silu -> h_w, h_c ----
    float* xs = sbuf;   // [10][256]
    int b = bi/25, l0 = (bi%25)*8;
    for (int i=tid; i<10*Dn; i+=256){
      int r = i>>8, dp = i&255, col = l0-1+r;
      xs[r*Dn+dp] = (col>=0 && col<Ln) ? g_phonT[((size_t)b*Ln+col)*Dn+dp] : 0.f;
    }
    __syncthreads();
    int warp = tid>>5, lane = tid&31;
    int l = l0 + warp;
    int plen = g_plen[b];
    for (int idx=0; idx<16; idx++){
      int which = idx>>3, o = idx&7;
      const float* ce = g_Ceff + ((which*8+o)*3)*Dn;
      float acc = 0.f;
      for (int i=lane; i<3*Dn; i+=32){
        int k = i>>8, dp = i&255;
        acc = fmaf(ce[k*Dn+dp], xs[((l-l0)+k)*Dn+dp], acc);
      }
      #pragma unroll
      for (int off=16; off; off>>=1) acc += __shfl_xor_sync(0xffffffffu, acc, off);
      if (lane==0){
        int var = (l==0)?0:((l==Ln-1)?2:1);
        float h = silu_f(acc + g_beff[(which*8+o)*3+var]);
        h = (l < plen) ? h : 0.f;
        float* dst = which ? g_hc : g_hw;
        dst[((size_t)b*Ln+l)*8 + o] = h;
      }
    }
  } else {
    // ---- P[b,l,:,q] = phonT[b,l,:] @ Lw_q ----
    float* A = sbuf;    // [dd][li] 16 l's
    int idx = bi-400;
    int c = idx%13, q = (idx/13)&3, b = idx/52;
    int l0 = c*16, nl = min(16, Ln - l0);
    for (int i=tid; i<16*Dn; i+=256){
      int li = i>>8, dp = i&255;
      A[dp*16+li] = (li < nl) ? g_phonT[((size_t)b*Ln + l0+li)*Dn + dp] : 0.f;
    }
    __syncthreads();
    ull acc[8];
    #pragma unroll
    for (int j=0;j<8;j++) acc[j]=pack2(0.f,0.f);
    const float* LwQ = Lw + (size_t)q*Dn*Dn;
    for (int dd=0; dd<Dn; dd++){
      float lw = LwQ[dd*Dn + tid];
      ull lw2 = pack2(lw, lw);
      const ulonglong2* ap = (const ulonglong2*)(A + dd*16);
      #pragma unroll
      for (int j=0;j<4;j++){
        ulonglong2 av = ap[j];
        acc[2*j]   = fma2(av.x, lw2, acc[2*j]);
        acc[2*j+1] = fma2(av.y, lw2, acc[2*j+1]);
      }
    }
    #pragma unroll
    for (int j=0;j<8;j++){
      float a,b2; unpack2(acc[j], a, b2);
      int i0 = 2*j, i1 = 2*j+1;
      if (i0 < nl) g_P[(((size_t)b*Ln + l0+i0)*Dn + tid)*4 + q] = a;
      if (i1 < nl) g_P[(((size_t)b*Ln + l0+i1)*Dn + tid)*4 + q] = b2;
    }
  }
}

// ================= K_MAIN =================
// dyn smem (floats):
//  w_s  : [l][t*4+q] stride 64      0     .. 12800
//  y_s  : [d][18]                   12800 .. 17408
//  sk_s : [l]                       17408 .. 17608
//  bc_s : [l][2]                    17608 .. 18008
//  wc_s : [t][8]                    18008 .. 18136
//  prm  : 66                        18136 .. 18202
#define SMEM_BYTES 72832

__global__ __launch_bounds__(256,3) void k_main(
  const float* __restrict__ dur,
  const float* __restrict__ Mw, const float* __restrict__ mbw,
  const float* __restrict__ Mc, const float* __restrict__ mbc,
  const float* __restrict__ lbw, const float* __restrict__ Lcm, const float* __restrict__ lbc,
  const float* __restrict__ Wo, const float* __restrict__ bo,
  float* __restrict__ out)
{
  extern __shared__ float sm[];
  float* w_s  = sm;
  float* y_s  = sm + 12800;
  float* sk_s = sm + 17408;
  float* bc_s = sm + 17608;
  float* wc_s = sm + 18008;
  float* prm  = sm + 18136;

  int b = blockIdx.y;
  int t0 = blockIdx.x * TT;
  int tid = threadIdx.x;
  int plen = g_plen[b], flen = g_flen[b];

  if (tid < 40)      prm[tid] = Mw[tid];
  else if (tid < 44) prm[tid] = mbw[tid-40];
  else if (tid < 64) prm[tid] = Mc[tid-44];
  else if (tid < 66) prm[tid] = mbc[tid-64];
  __syncthreads();

  // ---- phase 1: per-l features; pre-softmax w into w_s; c-bias into bc_s ----
  if (tid < Ln){
    int l = tid;
    float dv = dur[b*Ln + l];
    float sk = g_sk[b*Ln + l];
    sk_s[l] = sk;
    const float* hwp = g_hw + ((size_t)b*Ln+l)*8;
    const float* hcp = g_hc + ((size_t)b*Ln+l)*8;
    float bw[4], bc[2];
    #pragma unroll
    for (int q=0;q<4;q++){
      float a = prm[40+q] + dv*prm[4+q];
      #pragma unroll
      for (int j=0;j<8;j++) a = fmaf(hwp[j], prm[(2+j)*4+q], a);
      bw[q]=a;
    }
    #pragma unroll
    for (int p=0;p<2;p++){
      float a = prm[64+p] + dv*prm[46+p];
      #pragma unroll
      for (int j=0;j<8;j++) a = fmaf(hcp[j], prm[44+(2+j)*2+p], a);
      bc[p]=a;
    }
    bc_s[2*l]   = bc[0];
    bc_s[2*l+1] = bc[1];
    bool lv = l < plen;
    float4* wl = (float4*)(w_s + l*64);
    #pragma unroll
    for (int t=0;t<TT;t++){
      int tt = t0+t;
      float4 av = {0.f,0.f,0.f,0.f};
      if (lv && tt < flen){
        float S = (float)(tt+1) - sk;
        av.x = silu_f(fmaf(S, prm[0], bw[0]));
        av.y = silu_f(fmaf(S, prm[1], bw[1]));
        av.z = silu_f(fmaf(S, prm[2], bw[2]));
        av.w = silu_f(fmaf(S, prm[3], bw[3]));
      }
      wl[t] = av;
    }
  }
  __syncthreads();

  // ---- phase 2: one job per t: all-4q softmax, w out, wc reduce ----
  {
    int wp = tid>>5, lane = tid&31;
    float mc0 = prm[44], mc1 = prm[45];
    const size_t qs = (size_t)Tn*Ln;
    for (int t=wp; t<TT; t+=8){
      int tt = t0+t;
      if (tt >= Tn) continue;
      size_t wb = OFF_W + ((size_t)(b*4)*Tn + tt)*Ln;
      if (tt >= flen){
        for (int l=lane; l<Ln; l+=32){
          out[wb+l]=0.f; out[wb+qs+l]=0.f; out[wb+2*qs+l]=0.f; out[wb+3*qs+l]=0.f;
        }
        if (lane<8) wc_s[t*8+lane]=0.f;
        continue;
      }
      float4 wv[7];
      float m0=-3e38f,m1=-3e38f,m2=-3e38f,m3=-3e38f;
      #pragma unroll
      for (int i=0;i<7;i++){
        int l = lane + 32*i;
        if (l < plen){
          wv[i] = *(const float4*)(w_s + l*64 + t*4);
          m0=fmaxf(m0,wv[i].x); m1=fmaxf(m1,wv[i].y); m2=fmaxf(m2,wv[i].z); m3=fmaxf(m3,wv[i].w);
        }
      }
      #pragma unroll
      for (int off=16;off;off>>=1){
        m0=fmaxf(m0,__shfl_xor_sync(0xffffffffu,m0,off));
        m1=fmaxf(m1,__shfl_xor_sync(0xffffffffu,m1,off));
        m2=fmaxf(m2,__shfl_xor_sync(0xffffffffu,m2,off));
        m3=fmaxf(m3,__shfl_xor_sync(0xffffffffu,m3,off));
      }
      float s0=0.f,s1=0.f,s2=0.f,s3=0.f;
      #pragma unroll
      for (int i=0;i<7;i++){
        int l = lane + 32*i;
        if (l < plen){
          wv[i].x=__expf(wv[i].x-m0); wv[i].y=__expf(wv[i].y-m1);
          wv[i].z=__expf(wv[i].z-m2); wv[i].w=__expf(wv[i].w-m3);
          s0+=wv[i].x; s1+=wv[i].y; s2+=wv[i].z; s3+=wv[i].w;
        }
      }
      #pragma unroll
      for (int off=16;off;off>>=1){
        s0+=__shfl_xor_sync(0xffffffffu,s0,off);
        s1+=__shfl_xor_sync(0xffffffffu,s1,off);
        s2+=__shfl_xor_sync(0xffffffffu,s2,off);
        s3+=__shfl_xor_sync(0xffffffffu,s3,off);
      }
      float i0=__fdividef(1.f,s0), i1=__fdividef(1.f,s1), i2=__fdividef(1.f,s2), i3=__fdividef(1.f,s3);
      float Sb = (float)(tt+1);
      float r0=0.f,r1=0.f,r2=0.f,r3=0.f,r4=0.f,r5=0.f,r6=0.f,r7=0.f;
      #pragma unroll
      for (int i=0;i<7;i++){
        int l = lane + 32*i;
        if (l < plen){
          float4 v; v.x=wv[i].x*i0; v.y=wv[i].y*i1; v.z=wv[i].z*i2; v.w=wv[i].w*i3;
          *(float4*)(w_s + l*64 + t*4) = v;
          out[wb+l]=v.x; out[wb+qs+l]=v.y; out[wb+2*qs+l]=v.z; out[wb+3*qs+l]=v.w;
          float S = Sb - sk_s[l];
          float cx = silu_f(fmaf(S, mc0, bc_s[2*l]));
          float cy = silu_f(fmaf(S, mc1, bc_s[2*l+1]));
          r0=fmaf(v.x,cx,r0); r1=fmaf(v.x,cy,r1);
          r2=fmaf(v.y,cx,r2); r3=fmaf(v.y,cy,r3);
          r4=fmaf(v.z,cx,r4); r5=fmaf(v.z,cy,r5);
          r6=fmaf(v.w,cx,r6); r7=fmaf(v.w,cy,r7);
        } else if (l < Ln){
          out[wb+l]=0.f; out[wb+qs+l]=0.f; out[wb+2*qs+l]=0.f; out[wb+3*qs+l]=0.f;
        }
      }
      #pragma unroll
      for (int off=16;off;off>>=1){
        r0+=__shfl_xor_sync(0xffffffffu,r0,off); r1+=__shfl_xor_sync(0xffffffffu,r1,off);
        r2+=__shfl_xor_sync(0xffffffffu,r2,off); r3+=__shfl_xor_sync(0xffffffffu,r3,off);
        r4+=__shfl_xor_sync(0xffffffffu,r4,off); r5+=__shfl_xor_sync(0xffffffffu,r5,off);
        r6+=__shfl_xor_sync(0xffffffffu,r6,off); r7+=__shfl_xor_sync(0xffffffffu,r7,off);
      }
      if (lane==0){
        wc_s[t*8+0]=r0; wc_s[t*8+1]=r1; wc_s[t*8+2]=r2; wc_s[t*8+3]=r3;
        wc_s[t*8+4]=r4; wc_s[t*8+5]=r5; wc_s[t*8+6]=r6; wc_s[t*8+7]=r7;
      }
    }
  }
  __syncthreads();

  // ---- phase 3: y[t,d] = init + sum_{l} w4[t,l] . P[l,d,:]   warp = 8t x 64d ----
  {
    int wp = tid>>5, lane = tid&31;
    int th = (wp & 1) * 8;                       // t-half
    int d0 = ((((wp>>1)<<5) + lane) << 1);       // even d, thread owns d0,d0+1
    float2 lb2;
    lb2.x = lbw[d0] + lbc[d0];
    lb2.y = lbw[d0+1] + lbc[d0+1];
    float2 lc2[8];
    #pragma unroll
    for (int j=0;j<8;j++) lc2[j] = *(const float2*)(Lcm + j*Dn + d0);
    ull yA0[8], yA1[8];
    #pragma unroll
    for (int i=0;i<8;i++){
      int tt = t0 + th + i;
      float v0=0.f, v1=0.f;
      if (tt < flen){
        v0 = lb2.x; v1 = lb2.y;
        #pragma unroll
        for (int j=0;j<8;j++){
          float wc = wc_s[(th+i)*8+j];
          v0 = fmaf(wc, lc2[j].x, v0);
          v1 = fmaf(wc, lc2[j].y, v1);
        }
      }
      yA0[i] = pack2(v0, 0.f);
      yA1[i] = pack2(v1, 0.f);
    }
    const ulonglong2* Pb = ((const ulonglong2*)g_P) + (size_t)b*Ln*Dn;
    ulonglong2 z2; z2.x=0ull; z2.y=0ull;
    ulonglong2 pA0 = Pb[d0], pB0 = Pb[d0+1];
    ulonglong2 pA1 = (plen>1)? Pb[Dn+d0] : z2;
    ulonglong2 pB1 = (plen>1)? Pb[Dn+d0+1] : z2;
    for (int l=0;l<plen;l++){
      ulonglong2 nA=z2, nB=z2;
      if (l+2 < plen){
        nA = Pb[(size_t)(l+2)*Dn + d0];
        nB = Pb[(size_t)(l+2)*Dn + d0+1];
      }
      const ulonglong2* wl = (const ulonglong2*)(w_s + l*64 + th*4);
      #pragma unroll
      for (int i=0;i<8;i++){
        ulonglong2 wv = wl[i];
        yA0[i] = fma2(wv.y, pA0.y, fma2(wv.x, pA0.x, yA0[i]));
        yA1[i] = fma2(wv.y, pB0.y, fma2(wv.x, pB0.x, yA1[i]));
      }
      pA0=pA1; pB0=pB1; pA1=nA; pB1=nB;
    }
    #pragma unroll
    for (int i=0;i<8;i++){
      float a,b2;
      unpack2(yA0[i], a, b2); y_s[d0*18 + th + i]     = a + b2;
      unpack2(yA1[i], a, b2); y_s[(d0+1)*18 + th + i] = a + b2;
    }
  }
  __syncthreads();

  // ---- phase 4: out = y @ Wo + bo  (packed t-pairs) ----
  {
    int npair = (Tn - t0 >= TT) ? (TT/2) : ((Tn - t0) >> 1);
    ull a0p[TT/2], a1p[TT/2];
    float b0 = bo[tid], b1 = bo[tid+Dn];
    #pragma unroll
    for (int i=0;i<TT/2;i++){ a0p[i]=pack2(b0,b0); a1p[i]=pack2(b1,b1); }
    for (int dd=0; dd<Dn; dd++){
      float w0 = Wo[dd*2*Dn + tid];
      float w1 = Wo[dd*2*Dn + tid + Dn];
      ull w0p = pack2(w0,w0);
      ull w1p = pack2(w1,w1);
      const ull* yrow = (const ull*)(y_s + dd*18);
      #pragma unroll
      for (int i=0;i<TT/2;i++){
        ull yv = yrow[i];
        a0p[i] = fma2(yv, w0p, a0p[i]);
        a1p[i] = fma2(yv, w1p, a1p[i]);
      }
    }
    size_t base_m = OFF_MEAN + ((size_t)b*Dn + tid)*Tn + t0;
    size_t base_l = OFF_LOG  + ((size_t)b*Dn + tid)*Tn + t0;
    #pragma unroll
    for (int i=0;i<TT/2;i++){
      if (i < npair){
        *(ull*)&out[base_m + 2*i] = a0p[i];
        *(ull*)&out[base_l + 2*i] = a1p[i];
      }
    }
  }
}

// ---------------- launcher ----------------
extern "C" void kernel_launch(void* const* d_in, const int* in_sizes, int n_in,
                              void* d_out, int out_size){
  (void)in_sizes; (void)n_in; (void)out_size;
  const float* dur = (const float*)d_in[0];
  const float* phon= (const float*)d_in[1];
  const float* Wpw = (const float*)d_in[3];
  const float* bpw = (const float*)d_in[4];
  const float* Cw  = (const float*)d_in[5];
  const float* cbw = (const float*)d_in[6];
  const float* Mw  = (const float*)d_in[7];
  const float* mbw = (const float*)d_in[8];
  const float* Lw  = (const float*)d_in[9];
  const float* lbw = (const float*)d_in[10];
  const float* Wpc = (const float*)d_in[11];
  const float* bpc = (const float*)d_in[12];
  const float* Cc  = (const float*)d_in[13];
  const float* cbc = (const float*)d_in[14];
  const float* Mc  = (const float*)d_in[15];
  const float* mbc = (const float*)d_in[16];
  const float* Lcm = (const float*)d_in[17];
  const float* lbc = (const float*)d_in[18];
  const float* Wo  = (const float*)d_in[19];
  const float* bo  = (const float*)d_in[20];
  float* out = (float*)d_out;

  cudaFuncSetAttribute((const void*)k_main, cudaFuncAttributeMaxDynamicSharedMemorySize,
                       SMEM_BYTES);

  k_pre<<<961,256>>>(dur, phon, Cw, Wpw, Cc, Wpc, bpw, cbw, bpc, cbc, out);
  k_mid<<<1232,256>>>(Lw);
  k_main<<<dim3(NB,Bn),256,SMEM_BYTES>>>(dur,Mw,mbw,Mc,mbc,lbw,Lcm,lbc,Wo,bo,out);
}

// round 6
// speedup vs baseline: 1.5217x; 1.2090x over previous
#include <cuda_runtime.h>
#include <math.h>

typedef unsigned long long ull;

#define Bn 16
#define Dn 256
#define Ln 200
#define Tn 1000
#define TT 16
#define NB 63            // ceil(1000/16)
#define YS 20            // y_s row stride (floats), 16B-aligned

#define OFF_MEAN ((size_t)0)
#define OFF_LOG  ((size_t)4096000)
#define OFF_FM   ((size_t)8192000)
#define OFF_FL   ((size_t)8208000)
#define OFF_W    ((size_t)8208016)

// ---------------- device scratch ----------------
__device__ float g_sk[Bn*Ln];
__device__ int   g_plen[Bn];
__device__ int   g_flen[Bn];
__device__ float g_phonT[(size_t)Bn*Ln*Dn];          // [b][l][d]
__device__ float g_hw[(size_t)Bn*Ln*8];
__device__ float g_hc[(size_t)Bn*Ln*8];
__device__ float g_Ceff[2*8*3*Dn];
__device__ float g_beff[2*8*3];
__device__ float g_P[(size_t)Bn*Ln*Dn*4];            // [b][l][d][q]
__device__ float2 g_WoT2[Dn*Dn];                     // [dd][j] = (Wo[dd,j], Wo[dd,j+256])

__device__ __forceinline__ float silu_f(float x){ return __fdividef(x, 1.f + __expf(-x)); }

__device__ __forceinline__ ull pack2(float a, float b){
  ull r; asm("mov.b64 %0,{%1,%2};" : "=l"(r) : "f"(a), "f"(b)); return r;
}
__device__ __forceinline__ ull fma2(ull a, ull b, ull c){
  ull d; asm("fma.rn.f32x2 %0,%1,%2,%3;" : "=l"(d) : "l"(a), "l"(b), "l"(c)); return d;
}
__device__ __forceinline__ void unpack2(ull v, float& a, float& b){
  asm("mov.b64 {%0,%1},%2;" : "=f"(a), "=f"(b) : "l"(v));
}

// ================= K_PRE =================
// blocks 0..895 transpose | 896..943 ceff | 944..945 beff | 946..961 setup | 962..965 WoT pack
__global__ void k_pre(const float* __restrict__ dur, const float* __restrict__ phon,
                      const float* __restrict__ Cw, const float* __restrict__ Wpw,
                      const float* __restrict__ Cc, const float* __restrict__ Wpc,
                      const float* __restrict__ bpw, const float* __restrict__ cbw,
                      const float* __restrict__ bpc, const float* __restrict__ cbc,
                      const float* __restrict__ Wo,
                      float* __restrict__ out){
  __shared__ float tile[32][33];
  __shared__ float cs[Dn];
  __shared__ int sfl;
  int bi = blockIdx.x, tid = threadIdx.x;

  if (bi < 896){
    // ---- transpose ----
    int l0 = (bi%7)*32, d0 = ((bi/7)%8)*32, b = bi/56;
    int tx = tid&31, ty = tid>>5;
    #pragma unroll
    for (int r=0;r<4;r++){
      int dy = d0+ty+8*r, lx = l0+tx;
      tile[ty+8*r][tx] = (lx<Ln) ? phon[((size_t)b*Dn+dy)*Ln+lx] : 0.f;
    }
    __syncthreads();
    #pragma unroll
    for (int r=0;r<4;r++){
      int ly = l0+ty+8*r, dx = d0+tx;
      if (ly<Ln) g_phonT[((size_t)b*Ln+ly)*Dn+dx] = tile[tx][ty+8*r];
    }
  } else if (bi < 944){
    // ---- ceff: stage C row in smem, batched W loads ----
    int idx = bi-896;
    int o = idx&7, k = (idx>>3)%3, which = idx/24;
    const float* C = which? Cc : Cw;
    const float* W = which? Wpc : Wpw;
    cs[tid] = C[(o*Dn+tid)*3+k];
    __syncthreads();
    float acc=0.f;
    #pragma unroll 8
    for (int d=0; d<Dn; d++)
      acc = fmaf(cs[d], W[d*Dn+tid], acc);
    g_Ceff[((which*8+o)*3+k)*Dn + tid] = acc;
  } else if (bi < 946){
    // ---- beff: warp per (o,var), lanes over d ----
    int which = bi-944;
    const float* C = which? Cc: Cw; const float* bp = which? bpc : bpw; const float* cb = which? cbc : cbw;
    int wp = tid>>5, lane = tid&31;
    for (int pr=wp; pr<24; pr+=8){
      int o = pr/3, var = pr%3;
      int k0 = (var==0)?1:0, k1 = (var==2)?1:2;
      float acc = 0.f;
      #pragma unroll
      for (int i=0;i<8;i++){
        int d = lane + 32*i;
        float bv = bp[d];
        for (int k=k0;k<=k1;k++) acc = fmaf(C[(o*Dn+d)*3+k], bv, acc);
      }
      #pragma unroll
      for (int off=16;off;off>>=1) acc += __shfl_xor_sync(0xffffffffu, acc, off);
      if (lane==0) g_beff[(which*8+o)*3+var] = acc + cb[o];
    }
  } else if (bi < 962){
    // ---- setup ----
    int b = bi-946;
    float* s = &tile[0][0];
    if (tid < Ln) s[tid] = dur[b*Ln+tid];
    __syncthreads();
    if (tid == 0){
      float acc = 0.f; int plen = 0;
      for (int l=0;l<Ln;l++){ g_sk[b*Ln+l]=acc; float d=s[l]; acc+=d; if (d>0.f) plen=l+1; }
      g_plen[b]=plen;
      int fl = (int)rintf(acc); fl = fl<0?0:(fl>Tn?Tn:fl);
      g_flen[b]=fl; sfl=fl;
      out[OFF_FL + b] = (float)fl;
    }
    __syncthreads();
    int fl = sfl;
    for (int t=tid;t<Tn;t+=256) out[OFF_FM + (size_t)b*Tn + t] = (t<fl)?1.f:0.f;
  } else {
    // ---- WoT pack ----
    int dd0 = (bi-962)*64;
    for (int i=0;i<64;i++){
      int dd = dd0+i;
      g_WoT2[dd*Dn + tid] = make_float2(Wo[dd*2*Dn + tid], Wo[dd*2*Dn + Dn + tid]);
    }
  }
}

// ================= K_MID: conv (0..399) + P GEMM (400..1231) =================
__global__ void k_mid(const float* __restrict__ Lw){
  __shared__ float sbuf[4096];
  int bi = blockIdx.x, tid = threadIdx.x;

  if (bi < 400){
    float* xs = sbuf;   // [10][256]
    int b = bi/25, l0 = (bi%25)*8;
    for (int i=tid; i<10*Dn; i+=256){
      int r = i>>8, dp = i&255, col = l0-1+r;
      xs[r*Dn+dp] = (col>=0 && col<Ln) ? g_phonT[((size_t)b*Ln+col)*Dn+dp] : 0.f;
    }
    __syncthreads();
    int warp = tid>>5, lane = tid&31;
    int l = l0 + warp;
    int plen = g_plen[b];
    for (int idx=0; idx<16; idx++){
      int which = idx>>3, o = idx&7;
      const float* ce = g_Ceff + ((which*8+o)*3)*Dn;
      float acc = 0.f;
      for (int i=lane; i<3*Dn; i+=32){
        int k = i>>8, dp = i&255;
        acc = fmaf(ce[k*Dn+dp], xs[((l-l0)+k)*Dn+dp], acc);
      }
      #pragma unroll
      for (int off=16; off; off>>=1) acc += __shfl_xor_sync(0xffffffffu, acc, off);
      if (lane==0){
        int var = (l==0)?0:((l==Ln-1)?2:1);
        float h = silu_f(acc + g_beff[(which*8+o)*3+var]);
        h = (l < plen) ? h : 0.f;
        float* dst = which ? g_hc : g_hw;
        dst[((size_t)b*Ln+l)*8 + o] = h;
      }
    }
  } else {
    float* A = sbuf;    // [dd][li]
    int idx = bi-400;
    int c = idx%13, q = (idx/13)&3, b = idx/52;
    int l0 = c*16, nl = min(16, Ln - l0);
    for (int i=tid; i<16*Dn; i+=256){
      int li = i>>8, dp = i&255;
      A[dp*16+li] = (li < nl) ? g_phonT[((size_t)b*Ln + l0+li)*Dn + dp] : 0.f;
    }
    __syncthreads();
    ull acc[8];
    #pragma unroll
    for (int j=0;j<8;j++) acc[j]=pack2(0.f,0.f);
    const float* LwQ = Lw + (size_t)q*Dn*Dn;
    for (int dd=0; dd<Dn; dd++){
      float lw = LwQ[dd*Dn + tid];
      ull lw2 = pack2(lw, lw);
      const ulonglong2* ap = (const ulonglong2*)(A + dd*16);
      #pragma unroll
      for (int j=0;j<4;j++){
        ulonglong2 av = ap[j];
        acc[2*j]   = fma2(av.x, lw2, acc[2*j]);
        acc[2*j+1] = fma2(av.y, lw2, acc[2*j+1]);
      }
    }
    #pragma unroll
    for (int j=0;j<8;j++){
      float a,b2; unpack2(acc[j], a, b2);
      int i0 = 2*j, i1 = 2*j+1;
      if (i0 < nl) g_P[(((size_t)b*Ln + l0+i0)*Dn + tid)*4 + q] = a;
      if (i1 < nl) g_P[(((size_t)b*Ln + l0+i1)*Dn + tid)*4 + q] = b2;
    }
  }
}

// ================= K_MAIN =================
// dyn smem (floats):
//  w_s  : [l][t*4+q] stride 64      0     .. 12800
//  y_s  : [d][YS=20]                12800 .. 17920
//  sk_s : [l]                       17920 .. 18120
//  bc_s : [l][2]                    18120 .. 18520
//  wc_s : [t][8]                    18520 .. 18648
//  prm  : 66                        18648 .. 18714
#define SMEM_BYTES 74880

__global__ __launch_bounds__(256,3) void k_main(
  const float* __restrict__ dur,
  const float* __restrict__ Mw, const float* __restrict__ mbw,
  const float* __restrict__ Mc, const float* __restrict__ mbc,
  const float* __restrict__ lbw, const float* __restrict__ Lcm, const float* __restrict__ lbc,
  const float* __restrict__ bo,
  float* __restrict__ out)
{
  extern __shared__ float sm[];
  float* w_s  = sm;
  float* y_s  = sm + 12800;
  float* sk_s = sm + 17920;
  float* bc_s = sm + 18120;
  float* wc_s = sm + 18520;
  float* prm  = sm + 18648;

  int b = blockIdx.y;
  int t0 = blockIdx.x * TT;
  int tid = threadIdx.x;
  int plen = g_plen[b], flen = g_flen[b];
  bool active = (t0 < flen);          // block-uniform

  if (active){
    if (tid < 40)      prm[tid] = Mw[tid];
    else if (tid < 44) prm[tid] = mbw[tid-40];
    else if (tid < 64) prm[tid] = Mc[tid-44];
    else if (tid < 66) prm[tid] = mbc[tid-64];
    __syncthreads();

    // ---- phase 1 ----
    if (tid < Ln){
      int l = tid;
      float dv = dur[b*Ln + l];
      float sk = g_sk[b*Ln + l];
      sk_s[l] = sk;
      const float* hwp = g_hw + ((size_t)b*Ln+l)*8;
      const float* hcp = g_hc + ((size_t)b*Ln+l)*8;
      float bw[4], bc[2];
      #pragma unroll
      for (int q=0;q<4;q++){
        float a = prm[40+q] + dv*prm[4+q];
        #pragma unroll
        for (int j=0;j<8;j++) a = fmaf(hwp[j], prm[(2+j)*4+q], a);
        bw[q]=a;
      }
      #pragma unroll
      for (int p=0;p<2;p++){
        float a = prm[64+p] + dv*prm[46+p];
        #pragma unroll
        for (int j=0;j<8;j++) a = fmaf(hcp[j], prm[44+(2+j)*2+p], a);
        bc[p]=a;
      }
      bc_s[2*l]   = bc[0];
      bc_s[2*l+1] = bc[1];
      bool lv = l < plen;
      float4* wl = (float4*)(w_s + l*64);
      #pragma unroll
      for (int t=0;t<TT;t++){
        int tt = t0+t;
        float4 av = {0.f,0.f,0.f,0.f};
        if (lv && tt < flen){
          float S = (float)(tt+1) - sk;
          av.x = silu_f(fmaf(S, prm[0], bw[0]));
          av.y = silu_f(fmaf(S, prm[1], bw[1]));
          av.z = silu_f(fmaf(S, prm[2], bw[2]));
          av.w = silu_f(fmaf(S, prm[3], bw[3]));
        }
        wl[t] = av;
      }
    }
    __syncthreads();

    // ---- phase 2 ----
    {
      int wp = tid>>5, lane = tid&31;
      float mc0 = prm[44], mc1 = prm[45];
      const size_t qs = (size_t)Tn*Ln;
      for (int t=wp; t<TT; t+=8){
        int tt = t0+t;
        if (tt >= Tn) continue;
        size_t wb = OFF_W + ((size_t)(b*4)*Tn + tt)*Ln;
        if (tt >= flen){
          for (int l=lane; l<Ln; l+=32){
            out[wb+l]=0.f; out[wb+qs+l]=0.f; out[wb+2*qs+l]=0.f; out[wb+3*qs+l]=0.f;
          }
          if (lane<8) wc_s[t*8+lane]=0.f;
          continue;
        }
        float4 wv[7];
        float m0=-3e38f,m1=-3e38f,m2=-3e38f,m3=-3e38f;
        #pragma unroll
        for (int i=0;i<7;i++){
          int l = lane + 32*i;
          if (l < plen){
            wv[i] = *(const float4*)(w_s + l*64 + t*4);
            m0=fmaxf(m0,wv[i].x); m1=fmaxf(m1,wv[i].y); m2=fmaxf(m2,wv[i].z); m3=fmaxf(m3,wv[i].w);
          }
        }
        #pragma unroll
        for (int off=16;off;off>>=1){
          m0=fmaxf(m0,__shfl_xor_sync(0xffffffffu,m0,off));
          m1=fmaxf(m1,__shfl_xor_sync(0xffffffffu,m1,off));
          m2=fmaxf(m2,__shfl_xor_sync(0xffffffffu,m2,off));
          m3=fmaxf(m3,__shfl_xor_sync(0xffffffffu,m3,off));
        }
        float s0=0.f,s1=0.f,s2=0.f,s3=0.f;
        #pragma unroll
        for (int i=0;i<7;i++){
          int l = lane + 32*i;
          if (l < plen){
            wv[i].x=__expf(wv[i].x-m0); wv[i].y=__expf(wv[i].y-m1);
            wv[i].z=__expf(wv[i].z-m2); wv[i].w=__expf(wv[i].w-m3);
            s0+=wv[i].x; s1+=wv[i].y; s2+=wv[i].z; s3+=wv[i].w;
          }
        }
        #pragma unroll
        for (int off=16;off;off>>=1){
          s0+=__shfl_xor_sync(0xffffffffu,s0,off);
          s1+=__shfl_xor_sync(0xffffffffu,s1,off);
          s2+=__shfl_xor_sync(0xffffffffu,s2,off);
          s3+=__shfl_xor_sync(0xffffffffu,s3,off);
        }
        float i0=__fdividef(1.f,s0), i1=__fdividef(1.f,s1), i2=__fdividef(1.f,s2), i3=__fdividef(1.f,s3);
        float Sb = (float)(tt+1);
        float r0=0.f,r1=0.f,r2=0.f,r3=0.f,r4=0.f,r5=0.f,r6=0.f,r7=0.f;
        #pragma unroll
        for (int i=0;i<7;i++){
          int l = lane + 32*i;
          if (l < plen){
            float4 v; v.x=wv[i].x*i0; v.y=wv[i].y*i1; v.z=wv[i].z*i2; v.w=wv[i].w*i3;
            *(float4*)(w_s + l*64 + t*4) = v;
            out[wb+l]=v.x; out[wb+qs+l]=v.y; out[wb+2*qs+l]=v.z; out[wb+3*qs+l]=v.w;
            float S = Sb - sk_s[l];
            float cx = silu_f(fmaf(S, mc0, bc_s[2*l]));
            float cy = silu_f(fmaf(S, mc1, bc_s[2*l+1]));
            r0=fmaf(v.x,cx,r0); r1=fmaf(v.x,cy,r1);
            r2=fmaf(v.y,cx,r2); r3=fmaf(v.y,cy,r3);
            r4=fmaf(v.z,cx,r4); r5=fmaf(v.z,cy,r5);
            r6=fmaf(v.w,cx,r6); r7=fmaf(v.w,cy,r7);
          } else if (l < Ln){
            out[wb+l]=0.f; out[wb+qs+l]=0.f; out[wb+2*qs+l]=0.f; out[wb+3*qs+l]=0.f;
          }
        }
        #pragma unroll
        for (int off=16;off;off>>=1){
          r0+=__shfl_xor_sync(0xffffffffu,r0,off); r1+=__shfl_xor_sync(0xffffffffu,r1,off);
          r2+=__shfl_xor_sync(0xffffffffu,r2,off); r3+=__shfl_xor_sync(0xffffffffu,r3,off);
          r4+=__shfl_xor_sync(0xffffffffu,r4,off); r5+=__shfl_xor_sync(0xffffffffu,r5,off);
          r6+=__shfl_xor_sync(0xffffffffu,r6,off); r7+=__shfl_xor_sync(0xffffffffu,r7,off);
        }
        if (lane==0){
          wc_s[t*8+0]=r0; wc_s[t*8+1]=r1; wc_s[t*8+2]=r2; wc_s[t*8+3]=r3;
          wc_s[t*8+4]=r4; wc_s[t*8+5]=r5; wc_s[t*8+6]=r6; wc_s[t*8+7]=r7;
        }
      }
    }
    __syncthreads();

    // ---- phase 3 ----
    {
      int wp = tid>>5, lane = tid&31;
      int th = (wp & 1) * 8;
      int d0 = ((((wp>>1)<<5) + lane) << 1);
      float2 lb2;
      lb2.x = lbw[d0] + lbc[d0];
      lb2.y = lbw[d0+1] + lbc[d0+1];
      float2 lc2[8];
      #pragma unroll
      for (int j=0;j<8;j++) lc2[j] = *(const float2*)(Lcm + j*Dn + d0);
      ull yA0[8], yA1[8];
      #pragma unroll
      for (int i=0;i<8;i++){
        int tt = t0 + th + i;
        float v0=0.f, v1=0.f;
        if (tt < flen){
          v0 = lb2.x; v1 = lb2.y;
          #pragma unroll
          for (int j=0;j<8;j++){
            float wc = wc_s[(th+i)*8+j];
            v0 = fmaf(wc, lc2[j].x, v0);
            v1 = fmaf(wc, lc2[j].y, v1);
          }
        }
        yA0[i] = pack2(v0, 0.f);
        yA1[i] = pack2(v1, 0.f);
      }
      const ulonglong2* Pb = ((const ulonglong2*)g_P) + (size_t)b*Ln*Dn;
      ulonglong2 z2; z2.x=0ull; z2.y=0ull;
      ulonglong2 pA0 = Pb[d0], pB0 = Pb[d0+1];
      ulonglong2 pA1 = (plen>1)? Pb[Dn+d0] : z2;
      ulonglong2 pB1 = (plen>1)? Pb[Dn+d0+1] : z2;
      for (int l=0;l<plen;l++){
        ulonglong2 nA=z2, nB=z2;
        if (l+2 < plen){
          nA = Pb[(size_t)(l+2)*Dn + d0];
          nB = Pb[(size_t)(l+2)*Dn + d0+1];
        }
        const ulonglong2* wl = (const ulonglong2*)(w_s + l*64 + th*4);
        #pragma unroll
        for (int i=0;i<8;i++){
          ulonglong2 wv = wl[i];
          yA0[i] = fma2(wv.y, pA0.y, fma2(wv.x, pA0.x, yA0[i]));
          yA1[i] = fma2(wv.y, pB0.y, fma2(wv.x, pB0.x, yA1[i]));
        }
        pA0=pA1; pB0=pB1; pA1=nA; pB1=nB;
      }
      #pragma unroll
      for (int i=0;i<8;i++){
        float a,b2;
        unpack2(yA0[i], a, b2); y_s[d0*YS + th + i]     = a + b2;
        unpack2(yA1[i], a, b2); y_s[(d0+1)*YS + th + i] = a + b2;
      }
    }
    __syncthreads();

    // ---- phase 4: out = y @ Wo + bo  (packed Wo, LDS.128 y reads) ----
    {
      int npair = (Tn - t0 >= TT) ? (TT/2) : ((Tn - t0) >> 1);
      ull a0p[TT/2], a1p[TT/2];
      float b0 = bo[tid], b1 = bo[tid+Dn];
      #pragma unroll
      for (int i=0;i<TT/2;i++){ a0p[i]=pack2(b0,b0); a1p[i]=pack2(b1,b1); }
      const float2* wt = g_WoT2 + tid;
      #pragma unroll 2
      for (int dd=0; dd<Dn; dd++){
        float2 wv = wt[dd*Dn];
        ull w0p = pack2(wv.x,wv.x);
        ull w1p = pack2(wv.y,wv.y);
        const ulonglong2* yr = (const ulonglong2*)(y_s + dd*YS);
        #pragma unroll
        for (int j=0;j<4;j++){
          ulonglong2 yv = yr[j];
          a0p[2*j]   = fma2(yv.x, w0p, a0p[2*j]);
          a0p[2*j+1] = fma2(yv.y, w0p, a0p[2*j+1]);
          a1p[2*j]   = fma2(yv.x, w1p, a1p[2*j]);
          a1p[2*j+1] = fma2(yv.y, w1p, a1p[2*j+1]);
        }
      }
      size_t base_m = OFF_MEAN + ((size_t)b*Dn + tid)*Tn + t0;
      size_t base_l = OFF_LOG  + ((size_t)b*Dn + tid)*Tn + t0;
      #pragma unroll
      for (int i=0;i<TT/2;i++){
        if (i < npair){
          *(ull*)&out[base_m + 2*i] = a0p[i];
          *(ull*)&out[base_l + 2*i] = a1p[i];
        }
      }
    }
  } else {
    // ======== inactive block: w=0, out=bias ========
    int wp = tid>>5, lane = tid&31;
    const size_t qs = (size_t)Tn*Ln;
    for (int t=wp; t<TT; t+=8){
      int tt = t0+t;
      if (tt >= Tn) continue;
      size_t wb = OFF_W + ((size_t)(b*4)*Tn + tt)*Ln;
      for (int l=lane; l<Ln; l+=32){
        out[wb+l]=0.f; out[wb+qs+l]=0.f; out[wb+2*qs+l]=0.f; out[wb+3*qs+l]=0.f;
      }
    }
    int npair = (Tn - t0 >= TT) ? (TT/2) : ((Tn - t0) >> 1);
    float b0 = bo[tid], b1 = bo[tid+Dn];
    ull bp0 = pack2(b0,b0), bp1 = pack2(b1,b1);
    size_t base_m = OFF_MEAN + ((size_t)b*Dn + tid)*Tn + t0;
    size_t base_l = OFF_LOG  + ((size_t)b*Dn + tid)*Tn + t0;
    for (int i=0;i<npair;i++){
      *(ull*)&out[base_m + 2*i] = bp0;
      *(ull*)&out[base_l + 2*i] = bp1;
    }
  }
}

// ---------------- launcher ----------------
extern "C" void kernel_launch(void* const* d_in, const int* in_sizes, int n_in,
                              void* d_out, int out_size){
  (void)in_sizes; (void)n_in; (void)out_size;
  const float* dur = (const float*)d_in[0];
  const float* phon= (const float*)d_in[1];
  const float* Wpw = (const float*)d_in[3];
  const float* bpw = (const float*)d_in[4];
  const float* Cw  = (const float*)d_in[5];
  const float* cbw = (const float*)d_in[6];
  const float* Mw  = (const float*)d_in[7];
  const float* mbw = (const float*)d_in[8];
  const float* Lw  = (const float*)d_in[9];
  const float* lbw = (const float*)d_in[10];
  const float* Wpc = (const float*)d_in[11];
  const float* bpc = (const float*)d_in[12];
  const float* Cc  = (const float*)d_in[13];
  const float* cbc = (const float*)d_in[14];
  const float* Mc  = (const float*)d_in[15];
  const float* mbc = (const float*)d_in[16];
  const float* Lcm = (const float*)d_in[17];
  const float* lbc = (const float*)d_in[18];
  const float* Wo  = (const float*)d_in[19];
  const float* bo  = (const float*)d_in[20];
  float* out = (float*)d_out;

  cudaFuncSetAttribute((const void*)k_main, cudaFuncAttributeMaxDynamicSharedMemorySize,
                       SMEM_BYTES);

  k_pre<<<966,256>>>(dur, phon, Cw, Wpw, Cc, Wpc, bpw, cbw, bpc, cbc, Wo, out);
  k_mid<<<1232,256>>>(Lw);
  k_main<<<dim3(NB,Bn),256,SMEM_BYTES>>>(dur,Mw,mbw,Mc,mbc,lbw,Lcm,lbc,bo,out);
}

// round 9
// speedup vs baseline: 1.6495x; 1.0840x over previous
#include <cuda_runtime.h>
#include <cuda_bf16.h>
#include <cstdint>
#include <math.h>

typedef unsigned long long ull;

#define Bn 16
#define Dn 256
#define Ln 200
#define Tn 1000
#define TT 16
#define NB 63            // ceil(1000/16)

#define OFF_MEAN ((size_t)0)
#define OFF_LOG  ((size_t)4096000)
#define OFF_FM   ((size_t)8192000)
#define OFF_FL   ((size_t)8208000)
#define OFF_W    ((size_t)8208016)

// ---------------- device scratch ----------------
__device__ float g_sk[Bn*Ln];
__device__ int   g_plen[Bn];
__device__ int   g_flen[Bn];
__device__ float g_phonT[(size_t)Bn*Ln*Dn];          // [b][l][d]
__device__ float g_hw[(size_t)Bn*Ln*8];
__device__ float g_hc[(size_t)Bn*Ln*8];
__device__ float g_Ceff[2*8*3*Dn];
__device__ float g_beff[2*8*3];
__device__ float g_P[(size_t)Bn*Ln*Dn*4];            // [b][l][d][q]
__device__ unsigned short g_yhi[(size_t)Bn*Tn*Dn];   // bf16 hi of y, [m=b*1000+t][d]
__device__ unsigned short g_ylo[(size_t)Bn*Tn*Dn];   // bf16 lo
__device__ unsigned short g_woThi[512*256];          // bf16 WoT [n][k]
__device__ unsigned short g_woTlo[512*256];

__device__ __forceinline__ float silu_f(float x){ return __fdividef(x, 1.f + __expf(-x)); }

__device__ __forceinline__ ull pack2(float a, float b){
  ull r; asm("mov.b64 %0,{%1,%2};" : "=l"(r) : "f"(a), "f"(b)); return r;
}
__device__ __forceinline__ ull fma2(ull a, ull b, ull c){
  ull d; asm("fma.rn.f32x2 %0,%1,%2,%3;" : "=l"(d) : "l"(a), "l"(b), "l"(c)); return d;
}
__device__ __forceinline__ void unpack2(ull v, float& a, float& b){
  asm("mov.b64 {%0,%1},%2;" : "=f"(a), "=f"(b) : "l"(v));
}
__device__ __forceinline__ uint32_t smem_u32(const void* p){
  uint32_t a;
  asm("{ .reg .u64 t; cvta.to.shared.u64 t, %1; cvt.u32.u64 %0, t; }" : "=r"(a) : "l"(p));
  return a;
}

// ---------------- mma.sync helpers (baseline PTX, valid at compute_103) ----------------
__device__ __forceinline__ void ldsm4(uint32_t& r0, uint32_t& r1, uint32_t& r2, uint32_t& r3,
                                      uint32_t addr){
  asm volatile("ldmatrix.sync.aligned.m8n8.x4.shared.b16 {%0,%1,%2,%3}, [%4];"
    : "=r"(r0), "=r"(r1), "=r"(r2), "=r"(r3) : "r"(addr));
}
__device__ __forceinline__ void mma16816(float* d, const uint32_t* a, uint32_t b0, uint32_t b1){
  asm volatile("mma.sync.aligned.m16n8k16.row.col.f32.bf16.bf16.f32 "
    "{%0,%1,%2,%3},{%4,%5,%6,%7},{%8,%9},{%0,%1,%2,%3};"
    : "+f"(d[0]), "+f"(d[1]), "+f"(d[2]), "+f"(d[3])
    : "r"(a[0]), "r"(a[1]), "r"(a[2]), "r"(a[3]), "r"(b0), "r"(b1));
}

// ================= K_PRE =================
// 0..895 transpose | 896..943 ceff | 944..945 beff | 946..961 setup | 962..963 WoT split
__global__ void k_pre(const float* __restrict__ dur, const float* __restrict__ phon,
                      const float* __restrict__ Cw, const float* __restrict__ Wpw,
                      const float* __restrict__ Cc, const float* __restrict__ Wpc,
                      const float* __restrict__ bpw, const float* __restrict__ cbw,
                      const float* __restrict__ bpc, const float* __restrict__ cbc,
                      const float* __restrict__ Wo,
                      float* __restrict__ out){
  __shared__ float tile[32][33];
  __shared__ float cs[Dn];
  __shared__ int sfl;
  int bi = blockIdx.x, tid = threadIdx.x;

  if (bi < 896){
    int l0 = (bi%7)*32, d0 = ((bi/7)%8)*32, b = bi/56;
    int tx = tid&31, ty = tid>>5;
    #pragma unroll
    for (int r=0;r<4;r++){
      int dy = d0+ty+8*r, lx = l0+tx;
      tile[ty+8*r][tx] = (lx<Ln) ? phon[((size_t)b*Dn+dy)*Ln+lx] : 0.f;
    }
    __syncthreads();
    #pragma unroll
    for (int r=0;r<4;r++){
      int ly = l0+ty+8*r, dx = d0+tx;
      if (ly<Ln) g_phonT[((size_t)b*Ln+ly)*Dn+dx] = tile[tx][ty+8*r];
    }
  } else if (bi < 944){
    int idx = bi-896;
    int o = idx&7, k = (idx>>3)%3, which = idx/24;
    const float* C = which? Cc : Cw;
    const float* W = which? Wpc : Wpw;
    cs[tid] = C[(o*Dn+tid)*3+k];
    __syncthreads();
    float acc=0.f;
    #pragma unroll 8
    for (int d=0; d<Dn; d++)
      acc = fmaf(cs[d], W[d*Dn+tid], acc);
    g_Ceff[((which*8+o)*3+k)*Dn + tid] = acc;
  } else if (bi < 946){
    int which = bi-944;
    const float* C = which? Cc: Cw; const float* bp = which? bpc : bpw; const float* cb = which? cbc : cbw;
    int wp = tid>>5, lane = tid&31;
    for (int pr=wp; pr<24; pr+=8){
      int o = pr/3, var = pr%3;
      int k0 = (var==0)?1:0, k1 = (var==2)?1:2;
      float acc = 0.f;
      #pragma unroll
      for (int i=0;i<8;i++){
        int d = lane + 32*i;
        float bv = bp[d];
        for (int k=k0;k<=k1;k++) acc = fmaf(C[(o*Dn+d)*3+k], bv, acc);
      }
      #pragma unroll
      for (int off=16;off;off>>=1) acc += __shfl_xor_sync(0xffffffffu, acc, off);
      if (lane==0) g_beff[(which*8+o)*3+var] = acc + cb[o];
    }
  } else if (bi < 962){
    int b = bi-946;
    float* s = &tile[0][0];
    if (tid < Ln) s[tid] = dur[b*Ln+tid];
    __syncthreads();
    if (tid == 0){
      float acc = 0.f; int plen = 0;
      for (int l=0;l<Ln;l++){ g_sk[b*Ln+l]=acc; float d=s[l]; acc+=d; if (d>0.f) plen=l+1; }
      g_plen[b]=plen;
      int fl = (int)rintf(acc); fl = fl<0?0:(fl>Tn?Tn:fl);
      g_flen[b]=fl; sfl=fl;
      out[OFF_FL + b] = (float)fl;
    }
    __syncthreads();
    int fl = sfl;
    for (int t=tid;t<Tn;t+=256) out[OFF_FM + (size_t)b*Tn + t] = (t<fl)?1.f:0.f;
  } else {
    // WoT hi/lo split: [n][k] bf16
    int n = (bi-962)*256 + tid;
    for (int kc=0;kc<32;kc++){
      __align__(16) unsigned short h8[8];
      __align__(16) unsigned short l8[8];
      #pragma unroll
      for (int j=0;j<8;j++){
        float w = Wo[(size_t)(kc*8+j)*512 + n];
        __nv_bfloat16 hb = __float2bfloat16(w);
        float hf = __bfloat162float(hb);
        __nv_bfloat16 lb = __float2bfloat16(w - hf);
        h8[j] = __bfloat16_as_ushort(hb);
        l8[j] = __bfloat16_as_ushort(lb);
      }
      *(uint4*)&g_woThi[n*256 + kc*8] = *(uint4*)h8;
      *(uint4*)&g_woTlo[n*256 + kc*8] = *(uint4*)l8;
    }
  }
}

// ================= K_MID: conv (0..399) + P GEMM (400..1231) =================
__global__ void k_mid(const float* __restrict__ Lw){
  __shared__ float sbuf[4096];
  int bi = blockIdx.x, tid = threadIdx.x;

  if (bi < 400){
    float* xs = sbuf;
    int b = bi/25, l0 = (bi%25)*8;
    for (int i=tid; i<10*Dn; i+=256){
      int r = i>>8, dp = i&255, col = l0-1+r;
      xs[r*Dn+dp] = (col>=0 && col<Ln) ? g_phonT[((size_t)b*Ln+col)*Dn+dp] : 0.f;
    }
    __syncthreads();
    int warp = tid>>5, lane = tid&31;
    int l = l0 + warp;
    int plen = g_plen[b];
    for (int idx=0; idx<16; idx++){
      int which = idx>>3, o = idx&7;
      const float* ce = g_Ceff + ((which*8+o)*3)*Dn;
      float acc = 0.f;
      for (int i=lane; i<3*Dn; i+=32){
        int k = i>>8, dp = i&255;
        acc = fmaf(ce[k*Dn+dp], xs[((l-l0)+k)*Dn+dp], acc);
      }
      #pragma unroll
      for (int off=16; off; off>>=1) acc += __shfl_xor_sync(0xffffffffu, acc, off);
      if (lane==0){
        int var = (l==0)?0:((l==Ln-1)?2:1);
        float h = silu_f(acc + g_beff[(which*8+o)*3+var]);
        h = (l < plen) ? h : 0.f;
        float* dst = which ? g_hc : g_hw;
        dst[((size_t)b*Ln+l)*8 + o] = h;
      }
    }
  } else {
    float* A = sbuf;
    int idx = bi-400;
    int c = idx%13, q = (idx/13)&3, b = idx/52;
    int l0 = c*16, nl = min(16, Ln - l0);
    for (int i=tid; i<16*Dn; i+=256){
      int li = i>>8, dp = i&255;
      A[dp*16+li] = (li < nl) ? g_phonT[((size_t)b*Ln + l0+li)*Dn + dp] : 0.f;
    }
    __syncthreads();
    ull acc[8];
    #pragma unroll
    for (int j=0;j<8;j++) acc[j]=pack2(0.f,0.f);
    const float* LwQ = Lw + (size_t)q*Dn*Dn;
    for (int dd=0; dd<Dn; dd++){
      float lw = LwQ[dd*Dn + tid];
      ull lw2 = pack2(lw, lw);
      const ulonglong2* ap = (const ulonglong2*)(A + dd*16);
      #pragma unroll
      for (int j=0;j<4;j++){
        ulonglong2 av = ap[j];
        acc[2*j]   = fma2(av.x, lw2, acc[2*j]);
        acc[2*j+1] = fma2(av.y, lw2, acc[2*j+1]);
      }
    }
    #pragma unroll
    for (int j=0;j<8;j++){
      float a,b2; unpack2(acc[j], a, b2);
      int i0 = 2*j, i1 = 2*j+1;
      if (i0 < nl) g_P[(((size_t)b*Ln + l0+i0)*Dn + tid)*4 + q] = a;
      if (i1 < nl) g_P[(((size_t)b*Ln + l0+i1)*Dn + tid)*4 + q] = b2;
    }
  }
}

// ================= K_MAIN: phases 1-3, y -> bf16 hi/lo =================
// dyn smem (floats): w_s 0..12800 | sk 12800..13000 | bc 13000..13400 | wc 13400..13528 | prm 13528..13594
#define SMEM_BYTES 54376

__global__ __launch_bounds__(256,3) void k_main(
  const float* __restrict__ dur,
  const float* __restrict__ Mw, const float* __restrict__ mbw,
  const float* __restrict__ Mc, const float* __restrict__ mbc,
  const float* __restrict__ lbw, const float* __restrict__ Lcm, const float* __restrict__ lbc,
  float* __restrict__ out)
{
  extern __shared__ float sm[];
  float* w_s  = sm;
  float* sk_s = sm + 12800;
  float* bc_s = sm + 13000;
  float* wc_s = sm + 13400;
  float* prm  = sm + 13528;

  int b = blockIdx.y;
  int t0 = blockIdx.x * TT;
  int tid = threadIdx.x;
  int plen = g_plen[b], flen = g_flen[b];
  bool active = (t0 < flen);

  if (active){
    if (tid < 40)      prm[tid] = Mw[tid];
    else if (tid < 44) prm[tid] = mbw[tid-40];
    else if (tid < 64) prm[tid] = Mc[tid-44];
    else if (tid < 66) prm[tid] = mbc[tid-64];
    __syncthreads();

    // ---- phase 1 ----
    if (tid < Ln){
      int l = tid;
      float dv = dur[b*Ln + l];
      float sk = g_sk[b*Ln + l];
      sk_s[l] = sk;
      const float* hwp = g_hw + ((size_t)b*Ln+l)*8;
      const float* hcp = g_hc + ((size_t)b*Ln+l)*8;
      float bw[4], bc[2];
      #pragma unroll
      for (int q=0;q<4;q++){
        float a = prm[40+q] + dv*prm[4+q];
        #pragma unroll
        for (int j=0;j<8;j++) a = fmaf(hwp[j], prm[(2+j)*4+q], a);
        bw[q]=a;
      }
      #pragma unroll
      for (int p=0;p<2;p++){
        float a = prm[64+p] + dv*prm[46+p];
        #pragma unroll
        for (int j=0;j<8;j++) a = fmaf(hcp[j], prm[44+(2+j)*2+p], a);
        bc[p]=a;
      }
      bc_s[2*l]   = bc[0];
      bc_s[2*l+1] = bc[1];
      bool lv = l < plen;
      float4* wl = (float4*)(w_s + l*64);
      #pragma unroll
      for (int t=0;t<TT;t++){
        int tt = t0+t;
        float4 av = {0.f,0.f,0.f,0.f};
        if (lv && tt < flen){
          float S = (float)(tt+1) - sk;
          av.x = silu_f(fmaf(S, prm[0], bw[0]));
          av.y = silu_f(fmaf(S, prm[1], bw[1]));
          av.z = silu_f(fmaf(S, prm[2], bw[2]));
          av.w = silu_f(fmaf(S, prm[3], bw[3]));
        }
        wl[t] = av;
      }
    }
    __syncthreads();

    // ---- phase 2 ----
    {
      int wp = tid>>5, lane = tid&31;
      float mc0 = prm[44], mc1 = prm[45];
      const size_t qs = (size_t)Tn*Ln;
      for (int t=wp; t<TT; t+=8){
        int tt = t0+t;
        if (tt >= Tn) continue;
        size_t wb = OFF_W + ((size_t)(b*4)*Tn + tt)*Ln;
        if (tt >= flen){
          for (int l=lane; l<Ln; l+=32){
            out[wb+l]=0.f; out[wb+qs+l]=0.f; out[wb+2*qs+l]=0.f; out[wb+3*qs+l]=0.f;
          }
          if (lane<8) wc_s[t*8+lane]=0.f;
          continue;
        }
        float4 wv[7];
        float m0=-3e38f,m1=-3e38f,m2=-3e38f,m3=-3e38f;
        #pragma unroll
        for (int i=0;i<7;i++){
          int l = lane + 32*i;
          if (l < plen){
            wv[i] = *(const float4*)(w_s + l*64 + t*4);
            m0=fmaxf(m0,wv[i].x); m1=fmaxf(m1,wv[i].y); m2=fmaxf(m2,wv[i].z); m3=fmaxf(m3,wv[i].w);
          }
        }
        #pragma unroll
        for (int off=16;off;off>>=1){
          m0=fmaxf(m0,__shfl_xor_sync(0xffffffffu,m0,off));
          m1=fmaxf(m1,__shfl_xor_sync(0xffffffffu,m1,off));
          m2=fmaxf(m2,__shfl_xor_sync(0xffffffffu,m2,off));
          m3=fmaxf(m3,__shfl_xor_sync(0xffffffffu,m3,off));
        }
        float s0=0.f,s1=0.f,s2=0.f,s3=0.f;
        #pragma unroll
        for (int i=0;i<7;i++){
          int l = lane + 32*i;
          if (l < plen){
            wv[i].x=__expf(wv[i].x-m0); wv[i].y=__expf(wv[i].y-m1);
            wv[i].z=__expf(wv[i].z-m2); wv[i].w=__expf(wv[i].w-m3);
            s0+=wv[i].x; s1+=wv[i].y; s2+=wv[i].z; s3+=wv[i].w;
          }
        }
        #pragma unroll
        for (int off=16;off;off>>=1){
          s0+=__shfl_xor_sync(0xffffffffu,s0,off);
          s1+=__shfl_xor_sync(0xffffffffu,s1,off);
          s2+=__shfl_xor_sync(0xffffffffu,s2,off);
          s3+=__shfl_xor_sync(0xffffffffu,s3,off);
        }
        float i0=__fdividef(1.f,s0), i1=__fdividef(1.f,s1), i2=__fdividef(1.f,s2), i3=__fdividef(1.f,s3);
        float Sb = (float)(tt+1);
        float r0=0.f,r1=0.f,r2=0.f,r3=0.f,r4=0.f,r5=0.f,r6=0.f,r7=0.f;
        #pragma unroll
        for (int i=0;i<7;i++){
          int l = lane + 32*i;
          if (l < plen){
            float4 v; v.x=wv[i].x*i0; v.y=wv[i].y*i1; v.z=wv[i].z*i2; v.w=wv[i].w*i3;
            *(float4*)(w_s + l*64 + t*4) = v;
            out[wb+l]=v.x; out[wb+qs+l]=v.y; out[wb+2*qs+l]=v.z; out[wb+3*qs+l]=v.w;
            float S = Sb - sk_s[l];
            float cx = silu_f(fmaf(S, mc0, bc_s[2*l]));
            float cy = silu_f(fmaf(S, mc1, bc_s[2*l+1]));
            r0=fmaf(v.x,cx,r0); r1=fmaf(v.x,cy,r1);
            r2=fmaf(v.y,cx,r2); r3=fmaf(v.y,cy,r3);
            r4=fmaf(v.z,cx,r4); r5=fmaf(v.z,cy,r5);
            r6=fmaf(v.w,cx,r6); r7=fmaf(v.w,cy,r7);
          } else if (l < Ln){
            out[wb+l]=0.f; out[wb+qs+l]=0.f; out[wb+2*qs+l]=0.f; out[wb+3*qs+l]=0.f;
          }
        }
        #pragma unroll
        for (int off=16;off;off>>=1){
          r0+=__shfl_xor_sync(0xffffffffu,r0,off); r1+=__shfl_xor_sync(0xffffffffu,r1,off);
          r2+=__shfl_xor_sync(0xffffffffu,r2,off); r3+=__shfl_xor_sync(0xffffffffu,r3,off);
          r4+=__shfl_xor_sync(0xffffffffu,r4,off); r5+=__shfl_xor_sync(0xffffffffu,r5,off);
          r6+=__shfl_xor_sync(0xffffffffu,r6,off); r7+=__shfl_xor_sync(0xffffffffu,r7,off);
        }
        if (lane==0){
          wc_s[t*8+0]=r0; wc_s[t*8+1]=r1; wc_s[t*8+2]=r2; wc_s[t*8+3]=r3;
          wc_s[t*8+4]=r4; wc_s[t*8+5]=r5; wc_s[t*8+6]=r6; wc_s[t*8+7]=r7;
        }
      }
    }
    __syncthreads();

    // ---- phase 3: y -> bf16 hi/lo to gmem ----
    {
      int wp = tid>>5, lane = tid&31;
      int th = (wp & 1) * 8;
      int d0 = ((((wp>>1)<<5) + lane) << 1);
      float2 lb2;
      lb2.x = lbw[d0] + lbc[d0];
      lb2.y = lbw[d0+1] + lbc[d0+1];
      float2 lc2[8];
      #pragma unroll
      for (int j=0;j<8;j++) lc2[j] = *(const float2*)(Lcm + j*Dn + d0);
      ull yA0[8], yA1[8];
      #pragma unroll
      for (int i=0;i<8;i++){
        int tt = t0 + th + i;
        float v0=0.f, v1=0.f;
        if (tt < flen){
          v0 = lb2.x; v1 = lb2.y;
          #pragma unroll
          for (int j=0;j<8;j++){
            float wc = wc_s[(th+i)*8+j];
            v0 = fmaf(wc, lc2[j].x, v0);
            v1 = fmaf(wc, lc2[j].y, v1);
          }
        }
        yA0[i] = pack2(v0, 0.f);
        yA1[i] = pack2(v1, 0.f);
      }
      const ulonglong2* Pb = ((const ulonglong2*)g_P) + (size_t)b*Ln*Dn;
      ulonglong2 z2; z2.x=0ull; z2.y=0ull;
      ulonglong2 pA0 = Pb[d0], pB0 = Pb[d0+1];
      ulonglong2 pA1 = (plen>1)? Pb[Dn+d0] : z2;
      ulonglong2 pB1 = (plen>1)? Pb[Dn+d0+1] : z2;
      for (int l=0;l<plen;l++){
        ulonglong2 nA=z2, nB=z2;
        if (l+2 < plen){
          nA = Pb[(size_t)(l+2)*Dn + d0];
          nB = Pb[(size_t)(l+2)*Dn + d0+1];
        }
        const ulonglong2* wl = (const ulonglong2*)(w_s + l*64 + th*4);
        #pragma unroll
        for (int i=0;i<8;i++){
          ulonglong2 wv = wl[i];
          yA0[i] = fma2(wv.y, pA0.y, fma2(wv.x, pA0.x, yA0[i]));
          yA1[i] = fma2(wv.y, pB0.y, fma2(wv.x, pB0.x, yA1[i]));
        }
        pA0=pA1; pB0=pB1; pA1=nA; pB1=nB;
      }
      #pragma unroll
      for (int i=0;i<8;i++){
        int tt = t0 + th + i;
        if (tt < Tn){
          float a,b2;
          unpack2(yA0[i], a, b2); float v0 = a + b2;
          unpack2(yA1[i], a, b2); float v1 = a + b2;
          __nv_bfloat16 h0 = __float2bfloat16(v0);
          __nv_bfloat16 h1 = __float2bfloat16(v1);
          __nv_bfloat16 l0b = __float2bfloat16(v0 - __bfloat162float(h0));
          __nv_bfloat16 l1b = __float2bfloat16(v1 - __bfloat162float(h1));
          size_t row = (size_t)b*Tn + tt;
          ushort2 hh; hh.x = __bfloat16_as_ushort(h0); hh.y = __bfloat16_as_ushort(h1);
          ushort2 ll; ll.x = __bfloat16_as_ushort(l0b); ll.y = __bfloat16_as_ushort(l1b);
          *(ushort2*)&g_yhi[row*Dn + d0] = hh;
          *(ushort2*)&g_ylo[row*Dn + d0] = ll;
        }
      }
    }
  } else {
    // inactive: zero w planes + zero y rows
    int wp = tid>>5, lane = tid&31;
    const size_t qs = (size_t)Tn*Ln;
    for (int t=wp; t<TT; t+=8){
      int tt = t0+t;
      if (tt >= Tn) continue;
      size_t wb = OFF_W + ((size_t)(b*4)*Tn + tt)*Ln;
      for (int l=lane; l<Ln; l+=32){
        out[wb+l]=0.f; out[wb+qs+l]=0.f; out[wb+2*qs+l]=0.f; out[wb+3*qs+l]=0.f;
      }
    }
    uint4 z; z.x=0u; z.y=0u; z.z=0u; z.w=0u;
    for (int i=tid; i<TT*32; i+=256){
      int t = i>>5, j = i&31;
      int tt = t0+t;
      if (tt < Tn){
        size_t row = (size_t)b*Tn + tt;
        ((uint4*)(g_yhi + row*Dn))[j] = z;
        ((uint4*)(g_ylo + row*Dn))[j] = z;
      }
    }
  }
}

// ================= K_OUT: out = y @ Wo + bo  (mma.sync bf16, hi/lo x3) =================
// smem bytes: A_hi [128][256]bf16 0..65536 | A_lo ..131072 | B_hi [64][256] ..163840 | B_lo ..196608
#define KO_ALO 65536
#define KO_BHI 131072
#define KO_BLO 163840
#define KO_SMEM 196608

__global__ __launch_bounds__(256,1) void k_out(const float* __restrict__ bo,
                                               float* __restrict__ out){
  extern __shared__ float smf[];
  char* smc = (char*)smf;
  uint32_t sb = smem_u32(smc);
  int tid = threadIdx.x, wid = tid>>5, lane = tid&31;
  int mtile = blockIdx.x, ntile = blockIdx.y;

  // stage A (128 rows x 32 chunks of 16B), per-row xor swizzle chunk^=(row&7)
  {
    const uint4* srcH = (const uint4*)(g_yhi + (size_t)(mtile*128)*Dn);
    const uint4* srcL = (const uint4*)(g_ylo + (size_t)(mtile*128)*Dn);
    #pragma unroll
    for (int i=0;i<16;i++){
      int lin = i*256 + tid;
      int row = lin>>5, ch = lin&31;
      uint32_t off = (uint32_t)(row*512 + ((ch ^ (row&7))<<4));
      *(uint4*)(smc + off) = srcH[lin];
      *(uint4*)(smc + KO_ALO + off) = srcL[lin];
    }
  }
  // stage B (64 rows x 32 chunks)
  {
    const uint4* srcH = (const uint4*)(g_woThi + (size_t)(ntile*64)*256);
    const uint4* srcL = (const uint4*)(g_woTlo + (size_t)(ntile*64)*256);
    #pragma unroll
    for (int i=0;i<8;i++){
      int lin = i*256 + tid;
      int row = lin>>5, ch = lin&31;
      uint32_t off = (uint32_t)(row*512 + ((ch ^ (row&7))<<4));
      *(uint4*)(smc + KO_BHI + off) = srcH[lin];
      *(uint4*)(smc + KO_BLO + off) = srcL[lin];
    }
  }
  __syncthreads();

  float acc[8][4];
  #pragma unroll
  for (int nt=0;nt<8;nt++){ acc[nt][0]=0.f; acc[nt][1]=0.f; acc[nt][2]=0.f; acc[nt][3]=0.f; }

  int m0 = wid*16;
  // A ldmatrix lane mapping: row = m0 + (lane&15), kchunk += (lane>>4)
  int arow = m0 + (lane&15);
  int aks  = lane>>4;             // 0/1
  uint32_t aRowOff = (uint32_t)(arow*512);
  int arx = arow & 7;
  // B ldmatrix x4 (2 n-tiles): nrow = (lane>>4)*8 + (lane&7), kchunk += (lane>>3)&1
  int nrow = ((lane>>4)<<3) + (lane&7);
  int bks  = (lane>>3)&1;
  uint32_t bRowOff = (uint32_t)(nrow*512);
  int nrx = nrow & 7;

  for (int kk=0;kk<16;kk++){
    int kc = kk*2;
    uint32_t aH[4], aL[4];
    uint32_t aoff = aRowOff + (uint32_t)((((kc+aks) ^ arx))<<4);
    ldsm4(aH[0],aH[1],aH[2],aH[3], sb + aoff);
    ldsm4(aL[0],aL[1],aL[2],aL[3], sb + KO_ALO + aoff);
    uint32_t boff = bRowOff + (uint32_t)((((kc+bks) ^ nrx))<<4);
    #pragma unroll
    for (int bt=0;bt<4;bt++){
      uint32_t addr = (uint32_t)(bt*16*512) + boff;
      uint32_t bh0,bh1,bh2,bh3, bl0,bl1,bl2,bl3;
      ldsm4(bh0,bh1,bh2,bh3, sb + KO_BHI + addr);
      ldsm4(bl0,bl1,bl2,bl3, sb + KO_BLO + addr);
      mma16816(acc[2*bt],   aH, bh0, bh1);
      mma16816(acc[2*bt],   aL, bh0, bh1);
      mma16816(acc[2*bt],   aH, bl0, bl1);
      mma16816(acc[2*bt+1], aH, bh2, bh3);
      mma16816(acc[2*bt+1], aL, bh2, bh3);
      mma16816(acc[2*bt+1], aH, bl2, bl3);
    }
  }

  // epilogue: D + bo -> out (mean/log_std planes, column-major [d][t])
  {
    int gRow = lane>>2, tig = lane&3;
    size_t plane = (ntile < 4) ? OFF_MEAN : OFF_LOG;
    int colbase = ntile*64 - ((ntile>=4)?256:0);
    const float* bop = bo + ntile*64;
    #pragma unroll
    for (int nt=0;nt<8;nt++){
      int c0 = nt*8 + 2*tig;
      float b0v = bop[c0], b1v = bop[c0+1];
      #pragma unroll
      for (int half=0;half<2;half++){
        int m_g = mtile*128 + m0 + gRow + half*8;
        int b = m_g / Tn;
        int t = m_g - b*Tn;
        size_t base = plane + ((size_t)(b*Dn + colbase + c0))*Tn + t;
        out[base]      = acc[nt][half*2+0] + b0v;
        out[base + Tn] = acc[nt][half*2+1] + b1v;
      }
    }
  }
}

// ---------------- launcher ----------------
extern "C" void kernel_launch(void* const* d_in, const int* in_sizes, int n_in,
                              void* d_out, int out_size){
  (void)in_sizes; (void)n_in; (void)out_size;
  const float* dur = (const float*)d_in[0];
  const float* phon= (const float*)d_in[1];
  const float* Wpw = (const float*)d_in[3];
  const float* bpw = (const float*)d_in[4];
  const float* Cw  = (const float*)d_in[5];
  const float* cbw = (const float*)d_in[6];
  const float* Mw  = (const float*)d_in[7];
  const float* mbw = (const float*)d_in[8];
  const float* Lw  = (const float*)d_in[9];
  const float* lbw = (const float*)d_in[10];
  const float* Wpc = (const float*)d_in[11];
  const float* bpc = (const float*)d_in[12];
  const float* Cc  = (const float*)d_in[13];
  const float* cbc = (const float*)d_in[14];
  const float* Mc  = (const float*)d_in[15];
  const float* mbc = (const float*)d_in[16];
  const float* Lcm = (const float*)d_in[17];
  const float* lbc = (const float*)d_in[18];
  const float* Wo  = (const float*)d_in[19];
  const float* bo  = (const float*)d_in[20];
  float* out = (float*)d_out;

  cudaFuncSetAttribute((const void*)k_main, cudaFuncAttributeMaxDynamicSharedMemorySize,
                       SMEM_BYTES);
  cudaFuncSetAttribute((const void*)k_out, cudaFuncAttributeMaxDynamicSharedMemorySize,
                       KO_SMEM);

  k_pre<<<964,256>>>(dur, phon, Cw, Wpw, Cc, Wpc, bpw, cbw, bpc, cbc, Wo, out);
  k_mid<<<1232,256>>>(Lw);
  k_main<<<dim3(NB,Bn),256,SMEM_BYTES>>>(dur,Mw,mbw,Mc,mbc,lbw,Lcm,lbc,out);
  k_out<<<dim3(125,8),256,KO_SMEM>>>(bo,out);
}

// round 10
// speedup vs baseline: 1.7690x; 1.0725x over previous
#include <cuda_runtime.h>
#include <cuda_bf16.h>
#include <cstdint>
#include <math.h>

typedef unsigned long long ull;

#define Bn 16
#define Dn 256
#define Ln 200
#define Tn 1000
#define TT 16
#define NB 63            // ceil(1000/16)
#define KW 832           // padded K for combine GEMM (800 w + 8 wc + 1 bias + 23 pad)

#define OFF_MEAN ((size_t)0)
#define OFF_LOG  ((size_t)4096000)
#define OFF_FM   ((size_t)8192000)
#define OFF_FL   ((size_t)8208000)
#define OFF_W    ((size_t)8208016)

// ---------------- device scratch ----------------
__device__ float g_sk[Bn*Ln];
__device__ int   g_plen[Bn];
__device__ int   g_flen[Bn];
__device__ float g_phonT[(size_t)Bn*Ln*Dn];          // [b][l][d]
__device__ float g_hw[(size_t)Bn*Ln*8];
__device__ float g_hc[(size_t)Bn*Ln*8];
__device__ float g_Ceff[2*8*3*Dn];
__device__ float g_beff[2*8*3];
__device__ unsigned short g_wbf_hi[(size_t)Bn*1024*KW];  // W' [b][t(1024)][k]
__device__ unsigned short g_wbf_lo[(size_t)Bn*1024*KW];
__device__ unsigned short g_pbf_hi[(size_t)Bn*Dn*KW];    // P'T [b][d][k]
__device__ unsigned short g_pbf_lo[(size_t)Bn*Dn*KW];
__device__ unsigned short g_yhi[(size_t)Bn*Tn*Dn];   // bf16 hi of y, [m=b*1000+t][d]
__device__ unsigned short g_ylo[(size_t)Bn*Tn*Dn];   // bf16 lo
__device__ unsigned short g_woThi[512*256];          // bf16 WoT [n][k]
__device__ unsigned short g_woTlo[512*256];

__device__ __forceinline__ float silu_f(float x){ return __fdividef(x, 1.f + __expf(-x)); }

__device__ __forceinline__ ull pack2(float a, float b){
  ull r; asm("mov.b64 %0,{%1,%2};" : "=l"(r) : "f"(a), "f"(b)); return r;
}
__device__ __forceinline__ ull fma2(ull a, ull b, ull c){
  ull d; asm("fma.rn.f32x2 %0,%1,%2,%3;" : "=l"(d) : "l"(a), "l"(b), "l"(c)); return d;
}
__device__ __forceinline__ void unpack2(ull v, float& a, float& b){
  asm("mov.b64 {%0,%1},%2;" : "=f"(a), "=f"(b) : "l"(v));
}
__device__ __forceinline__ uint32_t smem_u32(const void* p){
  uint32_t a;
  asm("{ .reg .u64 t; cvta.to.shared.u64 t, %1; cvt.u32.u64 %0, t; }" : "=r"(a) : "l"(p));
  return a;
}
__device__ __forceinline__ void bf_split(float v, unsigned short& h, unsigned short& l){
  __nv_bfloat16 hb = __float2bfloat16(v);
  h = __bfloat16_as_ushort(hb);
  l = __bfloat16_as_ushort(__float2bfloat16(v - __bfloat162float(hb)));
}

// ---------------- mma.sync helpers ----------------
__device__ __forceinline__ void ldsm4(uint32_t& r0, uint32_t& r1, uint32_t& r2, uint32_t& r3,
                                      uint32_t addr){
  asm volatile("ldmatrix.sync.aligned.m8n8.x4.shared.b16 {%0,%1,%2,%3}, [%4];"
    : "=r"(r0), "=r"(r1), "=r"(r2), "=r"(r3) : "r"(addr));
}
__device__ __forceinline__ void mma16816(float* d, const uint32_t* a, uint32_t b0, uint32_t b1){
  asm volatile("mma.sync.aligned.m16n8k16.row.col.f32.bf16.bf16.f32 "
    "{%0,%1,%2,%3},{%4,%5,%6,%7},{%8,%9},{%0,%1,%2,%3};"
    : "+f"(d[0]), "+f"(d[1]), "+f"(d[2]), "+f"(d[3])
    : "r"(a[0]), "r"(a[1]), "r"(a[2]), "r"(a[3]), "r"(b0), "r"(b1));
}

// ================= K_PRE =================
// 0..895 transpose | 896..943 ceff | 944..945 beff | 946..961 setup | 962..963 WoT | 964..979 P'-extra
__global__ void k_pre(const float* __restrict__ dur, const float* __restrict__ phon,
                      const float* __restrict__ Cw, const float* __restrict__ Wpw,
                      const float* __restrict__ Cc, const float* __restrict__ Wpc,
                      const float* __restrict__ bpw, const float* __restrict__ cbw,
                      const float* __restrict__ bpc, const float* __restrict__ cbc,
                      const float* __restrict__ Wo,
                      const float* __restrict__ Lcm, const float* __restrict__ lbw,
                      const float* __restrict__ lbc,
                      float* __restrict__ out){
  __shared__ float tile[32][33];
  __shared__ float cs[Dn];
  __shared__ int sfl;
  int bi = blockIdx.x, tid = threadIdx.x;

  if (bi < 896){
    int l0 = (bi%7)*32, d0 = ((bi/7)%8)*32, b = bi/56;
    int tx = tid&31, ty = tid>>5;
    #pragma unroll
    for (int r=0;r<4;r++){
      int dy = d0+ty+8*r, lx = l0+tx;
      tile[ty+8*r][tx] = (lx<Ln) ? phon[((size_t)b*Dn+dy)*Ln+lx] : 0.f;
    }
    __syncthreads();
    #pragma unroll
    for (int r=0;r<4;r++){
      int ly = l0+ty+8*r, dx = d0+tx;
      if (ly<Ln) g_phonT[((size_t)b*Ln+ly)*Dn+dx] = tile[tx][ty+8*r];
    }
  } else if (bi < 944){
    int idx = bi-896;
    int o = idx&7, k = (idx>>3)%3, which = idx/24;
    const float* C = which? Cc : Cw;
    const float* W = which? Wpc : Wpw;
    cs[tid] = C[(o*Dn+tid)*3+k];
    __syncthreads();
    float acc=0.f;
    #pragma unroll 8
    for (int d=0; d<Dn; d++)
      acc = fmaf(cs[d], W[d*Dn+tid], acc);
    g_Ceff[((which*8+o)*3+k)*Dn + tid] = acc;
  } else if (bi < 946){
    int which = bi-944;
    const float* C = which? Cc: Cw; const float* bp = which? bpc : bpw; const float* cb = which? cbc : cbw;
    int wp = tid>>5, lane = tid&31;
    for (int pr=wp; pr<24; pr+=8){
      int o = pr/3, var = pr%3;
      int k0 = (var==0)?1:0, k1 = (var==2)?1:2;
      float acc = 0.f;
      #pragma unroll
      for (int i=0;i<8;i++){
        int d = lane + 32*i;
        float bv = bp[d];
        for (int k=k0;k<=k1;k++) acc = fmaf(C[(o*Dn+d)*3+k], bv, acc);
      }
      #pragma unroll
      for (int off=16;off;off>>=1) acc += __shfl_xor_sync(0xffffffffu, acc, off);
      if (lane==0) g_beff[(which*8+o)*3+var] = acc + cb[o];
    }
  } else if (bi < 962){
    int b = bi-946;
    float* s = &tile[0][0];
    if (tid < Ln) s[tid] = dur[b*Ln+tid];
    __syncthreads();
    if (tid == 0){
      float acc = 0.f; int plen = 0;
      for (int l=0;l<Ln;l++){ g_sk[b*Ln+l]=acc; float d=s[l]; acc+=d; if (d>0.f) plen=l+1; }
      g_plen[b]=plen;
      int fl = (int)rintf(acc); fl = fl<0?0:(fl>Tn?Tn:fl);
      g_flen[b]=fl; sfl=fl;
      out[OFF_FL + b] = (float)fl;
    }
    __syncthreads();
    int fl = sfl;
    for (int t=tid;t<Tn;t+=256) out[OFF_FM + (size_t)b*Tn + t] = (t<fl)?1.f:0.f;
  } else if (bi < 964){
    // WoT hi/lo split
    int n = (bi-962)*256 + tid;
    for (int kc=0;kc<32;kc++){
      __align__(16) unsigned short h8[8];
      __align__(16) unsigned short l8[8];
      #pragma unroll
      for (int j=0;j<8;j++){
        float w = Wo[(size_t)(kc*8+j)*512 + n];
        bf_split(w, h8[j], l8[j]);
      }
      *(uint4*)&g_woThi[n*256 + kc*8] = *(uint4*)h8;
      *(uint4*)&g_woTlo[n*256 + kc*8] = *(uint4*)l8;
    }
  } else {
    // P' extra rows: k=800..807 = Lc, k=808 = lbw+lbc, 809..831 = 0
    int b = bi-964;
    size_t base = ((size_t)b*Dn + tid)*KW;
    #pragma unroll
    for (int i=0;i<8;i++){
      unsigned short h,l; bf_split(Lcm[i*Dn+tid], h, l);
      g_pbf_hi[base+800+i]=h; g_pbf_lo[base+800+i]=l;
    }
    {
      unsigned short h,l; bf_split(lbw[tid]+lbc[tid], h, l);
      g_pbf_hi[base+808]=h; g_pbf_lo[base+808]=l;
    }
    for (int k=809;k<KW;k++){ g_pbf_hi[base+k]=0; g_pbf_lo[base+k]=0; }
  }
}

// ================= K_MID: conv (0..399) + P' GEMM (400..1231) =================
__global__ void k_mid(const float* __restrict__ Lw){
  __shared__ float sbuf[4096];
  int bi = blockIdx.x, tid = threadIdx.x;

  if (bi < 400){
    float* xs = sbuf;
    int b = bi/25, l0 = (bi%25)*8;
    for (int i=tid; i<10*Dn; i+=256){
      int r = i>>8, dp = i&255, col = l0-1+r;
      xs[r*Dn+dp] = (col>=0 && col<Ln) ? g_phonT[((size_t)b*Ln+col)*Dn+dp] : 0.f;
    }
    __syncthreads();
    int warp = tid>>5, lane = tid&31;
    int l = l0 + warp;
    int plen = g_plen[b];
    for (int idx=0; idx<16; idx++){
      int which = idx>>3, o = idx&7;
      const float* ce = g_Ceff + ((which*8+o)*3)*Dn;
      float acc = 0.f;
      for (int i=lane; i<3*Dn; i+=32){
        int k = i>>8, dp = i&255;
        acc = fmaf(ce[k*Dn+dp], xs[((l-l0)+k)*Dn+dp], acc);
      }
      #pragma unroll
      for (int off=16; off; off>>=1) acc += __shfl_xor_sync(0xffffffffu, acc, off);
      if (lane==0){
        int var = (l==0)?0:((l==Ln-1)?2:1);
        float h = silu_f(acc + g_beff[(which*8+o)*3+var]);
        h = (l < plen) ? h : 0.f;
        float* dst = which ? g_hc : g_hw;
        dst[((size_t)b*Ln+l)*8 + o] = h;
      }
    }
  } else {
    float* A = sbuf;
    int idx = bi-400;
    int c = idx%13, q = (idx/13)&3, b = idx/52;
    int l0 = c*16, nl = min(16, Ln - l0);
    for (int i=tid; i<16*Dn; i+=256){
      int li = i>>8, dp = i&255;
      A[dp*16+li] = (li < nl) ? g_phonT[((size_t)b*Ln + l0+li)*Dn + dp] : 0.f;
    }
    __syncthreads();
    ull acc[8];
    #pragma unroll
    for (int j=0;j<8;j++) acc[j]=pack2(0.f,0.f);
    const float* LwQ = Lw + (size_t)q*Dn*Dn;
    for (int dd=0; dd<Dn; dd++){
      float lw = LwQ[dd*Dn + tid];
      ull lw2 = pack2(lw, lw);
      const ulonglong2* ap = (const ulonglong2*)(A + dd*16);
      #pragma unroll
      for (int j=0;j<4;j++){
        ulonglong2 av = ap[j];
        acc[2*j]   = fma2(av.x, lw2, acc[2*j]);
        acc[2*j+1] = fma2(av.y, lw2, acc[2*j+1]);
      }
    }
    // write P'T bf16 hi/lo: [b][d=tid][k=(l0+i)*4+q]
    size_t base = ((size_t)b*Dn + tid)*KW;
    #pragma unroll
    for (int j=0;j<8;j++){
      float a,b2; unpack2(acc[j], a, b2);
      int i0 = 2*j, i1 = 2*j+1;
      if (i0 < nl){
        unsigned short h,l; bf_split(a,h,l);
        size_t k = base + (size_t)(l0+i0)*4 + q;
        g_pbf_hi[k]=h; g_pbf_lo[k]=l;
      }
      if (i1 < nl){
        unsigned short h,l; bf_split(b2,h,l);
        size_t k = base + (size_t)(l0+i1)*4 + q;
        g_pbf_hi[k]=h; g_pbf_lo[k]=l;
      }
    }
  }
}

// ================= K_MAIN: phases 1-2 + W' export =================
// dyn smem (floats): w_s 0..12800 | sk 12800..13000 | bc 13000..13400 | wc 13400..13528 | prm 13528..13594
#define SMEM_BYTES 54376

__global__ __launch_bounds__(256,3) void k_main(
  const float* __restrict__ dur,
  const float* __restrict__ Mw, const float* __restrict__ mbw,
  const float* __restrict__ Mc, const float* __restrict__ mbc,
  float* __restrict__ out)
{
  extern __shared__ float sm[];
  float* w_s  = sm;
  float* sk_s = sm + 12800;
  float* bc_s = sm + 13000;
  float* wc_s = sm + 13400;
  float* prm  = sm + 13528;

  int b = blockIdx.y;
  int t0 = blockIdx.x * TT;
  int tid = threadIdx.x;
  int plen = g_plen[b], flen = g_flen[b];
  bool active = (t0 < flen);

  if (active){
    if (tid < 40)      prm[tid] = Mw[tid];
    else if (tid < 44) prm[tid] = mbw[tid-40];
    else if (tid < 64) prm[tid] = Mc[tid-44];
    else if (tid < 66) prm[tid] = mbc[tid-64];
    __syncthreads();

    // ---- phase 1 ----
    if (tid < Ln){
      int l = tid;
      float dv = dur[b*Ln + l];
      float sk = g_sk[b*Ln + l];
      sk_s[l] = sk;
      const float* hwp = g_hw + ((size_t)b*Ln+l)*8;
      const float* hcp = g_hc + ((size_t)b*Ln+l)*8;
      float bw[4], bc[2];
      #pragma unroll
      for (int q=0;q<4;q++){
        float a = prm[40+q] + dv*prm[4+q];
        #pragma unroll
        for (int j=0;j<8;j++) a = fmaf(hwp[j], prm[(2+j)*4+q], a);
        bw[q]=a;
      }
      #pragma unroll
      for (int p=0;p<2;p++){
        float a = prm[64+p] + dv*prm[46+p];
        #pragma unroll
        for (int j=0;j<8;j++) a = fmaf(hcp[j], prm[44+(2+j)*2+p], a);
        bc[p]=a;
      }
      bc_s[2*l]   = bc[0];
      bc_s[2*l+1] = bc[1];
      bool lv = l < plen;
      float4* wl = (float4*)(w_s + l*64);
      #pragma unroll
      for (int t=0;t<TT;t++){
        int tt = t0+t;
        float4 av = {0.f,0.f,0.f,0.f};
        if (lv && tt < flen){
          float S = (float)(tt+1) - sk;
          av.x = silu_f(fmaf(S, prm[0], bw[0]));
          av.y = silu_f(fmaf(S, prm[1], bw[1]));
          av.z = silu_f(fmaf(S, prm[2], bw[2]));
          av.w = silu_f(fmaf(S, prm[3], bw[3]));
        }
        wl[t] = av;
      }
    }
    __syncthreads();

    // ---- phase 2: softmax + f32 w out + wc reduce ----
    {
      int wp = tid>>5, lane = tid&31;
      float mc0 = prm[44], mc1 = prm[45];
      const size_t qs = (size_t)Tn*Ln;
      for (int t=wp; t<TT; t+=8){
        int tt = t0+t;
        if (tt >= Tn) continue;
        size_t wb = OFF_W + ((size_t)(b*4)*Tn + tt)*Ln;
        if (tt >= flen){
          for (int l=lane; l<Ln; l+=32){
            out[wb+l]=0.f; out[wb+qs+l]=0.f; out[wb+2*qs+l]=0.f; out[wb+3*qs+l]=0.f;
          }
          if (lane<8) wc_s[t*8+lane]=0.f;
          continue;
        }
        float4 wv[7];
        float m0=-3e38f,m1=-3e38f,m2=-3e38f,m3=-3e38f;
        #pragma unroll
        for (int i=0;i<7;i++){
          int l = lane + 32*i;
          if (l < plen){
            wv[i] = *(const float4*)(w_s + l*64 + t*4);
            m0=fmaxf(m0,wv[i].x); m1=fmaxf(m1,wv[i].y); m2=fmaxf(m2,wv[i].z); m3=fmaxf(m3,wv[i].w);
          }
        }
        #pragma unroll
        for (int off=16;off;off>>=1){
          m0=fmaxf(m0,__shfl_xor_sync(0xffffffffu,m0,off));
          m1=fmaxf(m1,__shfl_xor_sync(0xffffffffu,m1,off));
          m2=fmaxf(m2,__shfl_xor_sync(0xffffffffu,m2,off));
          m3=fmaxf(m3,__shfl_xor_sync(0xffffffffu,m3,off));
        }
        float s0=0.f,s1=0.f,s2=0.f,s3=0.f;
        #pragma unroll
        for (int i=0;i<7;i++){
          int l = lane + 32*i;
          if (l < plen){
            wv[i].x=__expf(wv[i].x-m0); wv[i].y=__expf(wv[i].y-m1);
            wv[i].z=__expf(wv[i].z-m2); wv[i].w=__expf(wv[i].w-m3);
            s0+=wv[i].x; s1+=wv[i].y; s2+=wv[i].z; s3+=wv[i].w;
          }
        }
        #pragma unroll
        for (int off=16;off;off>>=1){
          s0+=__shfl_xor_sync(0xffffffffu,s0,off);
          s1+=__shfl_xor_sync(0xffffffffu,s1,off);
          s2+=__shfl_xor_sync(0xffffffffu,s2,off);
          s3+=__shfl_xor_sync(0xffffffffu,s3,off);
        }
        float i0=__fdividef(1.f,s0), i1=__fdividef(1.f,s1), i2=__fdividef(1.f,s2), i3=__fdividef(1.f,s3);
        float Sb = (float)(tt+1);
        float r0=0.f,r1=0.f,r2=0.f,r3=0.f,r4=0.f,r5=0.f,r6=0.f,r7=0.f;
        #pragma unroll
        for (int i=0;i<7;i++){
          int l = lane + 32*i;
          if (l < plen){
            float4 v; v.x=wv[i].x*i0; v.y=wv[i].y*i1; v.z=wv[i].z*i2; v.w=wv[i].w*i3;
            *(float4*)(w_s + l*64 + t*4) = v;
            out[wb+l]=v.x; out[wb+qs+l]=v.y; out[wb+2*qs+l]=v.z; out[wb+3*qs+l]=v.w;
            float S = Sb - sk_s[l];
            float cx = silu_f(fmaf(S, mc0, bc_s[2*l]));
            float cy = silu_f(fmaf(S, mc1, bc_s[2*l+1]));
            r0=fmaf(v.x,cx,r0); r1=fmaf(v.x,cy,r1);
            r2=fmaf(v.y,cx,r2); r3=fmaf(v.y,cy,r3);
            r4=fmaf(v.z,cx,r4); r5=fmaf(v.z,cy,r5);
            r6=fmaf(v.w,cx,r6); r7=fmaf(v.w,cy,r7);
          } else if (l < Ln){
            out[wb+l]=0.f; out[wb+qs+l]=0.f; out[wb+2*qs+l]=0.f; out[wb+3*qs+l]=0.f;
          }
        }
        #pragma unroll
        for (int off=16;off;off>>=1){
          r0+=__shfl_xor_sync(0xffffffffu,r0,off); r1+=__shfl_xor_sync(0xffffffffu,r1,off);
          r2+=__shfl_xor_sync(0xffffffffu,r2,off); r3+=__shfl_xor_sync(0xffffffffu,r3,off);
          r4+=__shfl_xor_sync(0xffffffffu,r4,off); r5+=__shfl_xor_sync(0xffffffffu,r5,off);
          r6+=__shfl_xor_sync(0xffffffffu,r6,off); r7+=__shfl_xor_sync(0xffffffffu,r7,off);
        }
        if (lane==0){
          wc_s[t*8+0]=r0; wc_s[t*8+1]=r1; wc_s[t*8+2]=r2; wc_s[t*8+3]=r3;
          wc_s[t*8+4]=r4; wc_s[t*8+5]=r5; wc_s[t*8+6]=r6; wc_s[t*8+7]=r7;
        }
      }
    }
    __syncthreads();

    // ---- phase 2.5: export W' rows as bf16 hi/lo (coalesced over k) ----
    for (int t=0;t<TT;t++){
      int tt = t0+t;
      if (tt >= Tn) break;
      bool live = tt < flen;
      size_t rw = ((size_t)(b*1024)+tt)*KW;
      for (int k=tid;k<KW;k+=256){
        float v;
        if (k < 800)      v = w_s[(k>>2)*64 + t*4 + (k&3)];
        else if (k < 808) v = wc_s[t*8 + (k-800)];
        else if (k == 808) v = live ? 1.f : 0.f;
        else              v = 0.f;
        unsigned short h,l; bf_split(v,h,l);
        g_wbf_hi[rw+k]=h; g_wbf_lo[rw+k]=l;
      }
    }
  } else {
    // inactive: zero w planes + zero W' rows
    int wp = tid>>5, lane = tid&31;
    const size_t qs = (size_t)Tn*Ln;
    for (int t=wp; t<TT; t+=8){
      int tt = t0+t;
      if (tt >= Tn) continue;
      size_t wb = OFF_W + ((size_t)(b*4)*Tn + tt)*Ln;
      for (int l=lane; l<Ln; l+=32){
        out[wb+l]=0.f; out[wb+qs+l]=0.f; out[wb+2*qs+l]=0.f; out[wb+3*qs+l]=0.f;
      }
    }
    for (int t=0;t<TT;t++){
      int tt = t0+t;
      if (tt >= Tn) break;
      size_t rw = ((size_t)(b*1024)+tt)*KW;
      for (int k=tid;k<KW;k+=256){ g_wbf_hi[rw+k]=0; g_wbf_lo[rw+k]=0; }
    }
  }
}

// ================= K_COMB: Y = W' @ P'  (mma.sync bf16 hi/lo x3) -> g_yhi/g_ylo =================
// smem: A_hi 16KB | A_lo 16KB | B_hi 16KB | B_lo 16KB  (128 rows x 128B, ch^(row&7) swizzle)
#define KC_ALO 16384
#define KC_BHI 32768
#define KC_BLO 49152
#define KC_SMEM 65536

__global__ __launch_bounds__(256,2) void k_comb(){
  extern __shared__ float smf[];
  char* smc = (char*)smf;
  uint32_t sb = smem_u32(smc);
  int tid = threadIdx.x, wid = tid>>5, lane = tid&31;
  int mtile = blockIdx.x, ntile = blockIdx.y, b = blockIdx.z;

  float acc[2][8][4];
  #pragma unroll
  for (int mt=0;mt<2;mt++)
    #pragma unroll
    for (int ng=0;ng<8;ng++){ acc[mt][ng][0]=0.f; acc[mt][ng][1]=0.f; acc[mt][ng][2]=0.f; acc[mt][ng][3]=0.f; }

  int m0 = (wid&3)*32, n0 = (wid>>2)*64;

  const uint4* gwh = (const uint4*)(g_wbf_hi + ((size_t)(b*1024) + (size_t)mtile*128)*KW);
  const uint4* gwl = (const uint4*)(g_wbf_lo + ((size_t)(b*1024) + (size_t)mtile*128)*KW);
  const uint4* gph = (const uint4*)(g_pbf_hi + ((size_t)(b*Dn) + (size_t)ntile*128)*KW);
  const uint4* gpl = (const uint4*)(g_pbf_lo + ((size_t)(b*Dn) + (size_t)ntile*128)*KW);
  const int rs = KW/8;   // row stride in uint4 = 104

  for (int c=0;c<13;c++){
    if (c) __syncthreads();
    #pragma unroll
    for (int i=0;i<4;i++){
      int lin = i*256 + tid;
      int row = lin>>3, ch = lin&7;
      uint32_t off = (uint32_t)(row*128 + ((ch ^ (row&7))<<4));
      size_t g = (size_t)row*rs + c*8 + ch;
      *(uint4*)(smc + off) = gwh[g];
      *(uint4*)(smc + KC_ALO + off) = gwl[g];
      *(uint4*)(smc + KC_BHI + off) = gph[g];
      *(uint4*)(smc + KC_BLO + off) = gpl[g];
    }
    __syncthreads();
    #pragma unroll
    for (int kk=0;kk<4;kk++){
      uint32_t aH[2][4], aL[2][4];
      #pragma unroll
      for (int mt=0;mt<2;mt++){
        int arow = m0 + mt*16 + (lane&15);
        uint32_t aoff = (uint32_t)(arow*128 + (((kk*2 + (lane>>4)) ^ (arow&7))<<4));
        ldsm4(aH[mt][0],aH[mt][1],aH[mt][2],aH[mt][3], sb + aoff);
        ldsm4(aL[mt][0],aL[mt][1],aL[mt][2],aL[mt][3], sb + KC_ALO + aoff);
      }
      #pragma unroll
      for (int ng=0;ng<4;ng++){
        int nrow = n0 + ng*16 + ((lane>>4)<<3) + (lane&7);
        uint32_t boff = (uint32_t)(nrow*128 + (((kk*2 + ((lane>>3)&1)) ^ (nrow&7))<<4));
        uint32_t bh0,bh1,bh2,bh3, bl0,bl1,bl2,bl3;
        ldsm4(bh0,bh1,bh2,bh3, sb + KC_BHI + boff);
        ldsm4(bl0,bl1,bl2,bl3, sb + KC_BLO + boff);
        #pragma unroll
        for (int mt=0;mt<2;mt++){
          mma16816(acc[mt][2*ng],   aH[mt], bh0, bh1);
          mma16816(acc[mt][2*ng],   aL[mt], bh0, bh1);
          mma16816(acc[mt][2*ng],   aH[mt], bl0, bl1);
          mma16816(acc[mt][2*ng+1], aH[mt], bh2, bh3);
          mma16816(acc[mt][2*ng+1], aL[mt], bh2, bh3);
          mma16816(acc[mt][2*ng+1], aH[mt], bl2, bl3);
        }
      }
    }
  }

  // epilogue: split f32 -> bf16 hi/lo, store to g_yhi/g_ylo [b*1000+t][d]
  #pragma unroll
  for (int mt=0;mt<2;mt++){
    #pragma unroll
    for (int ng=0;ng<8;ng++){
      int d = ntile*128 + n0 + ng*8 + (lane&3)*2;
      #pragma unroll
      for (int half=0;half<2;half++){
        int t = mtile*128 + m0 + mt*16 + (lane>>2) + half*8;
        if (t < Tn){
          size_t row = (size_t)b*Tn + t;
          unsigned short h0,l0,h1,l1;
          bf_split(acc[mt][ng][half*2+0], h0, l0);
          bf_split(acc[mt][ng][half*2+1], h1, l1);
          ushort2 hh; hh.x=h0; hh.y=h1;
          ushort2 ll; ll.x=l0; ll.y=l1;
          *(ushort2*)&g_yhi[row*Dn + d] = hh;
          *(ushort2*)&g_ylo[row*Dn + d] = ll;
        }
      }
    }
  }
}

// ================= K_OUT: out = y @ Wo + bo  (mma.sync bf16, hi/lo x3) =================
#define KO_ALO 65536
#define KO_BHI 131072
#define KO_BLO 163840
#define KO_SMEM 196608

__global__ __launch_bounds__(256,1) void k_out(const float* __restrict__ bo,
                                               float* __restrict__ out){
  extern __shared__ float smf[];
  char* smc = (char*)smf;
  uint32_t sb = smem_u32(smc);
  int tid = threadIdx.x, wid = tid>>5, lane = tid&31;
  int mtile = blockIdx.x, ntile = blockIdx.y;

  {
    const uint4* srcH = (const uint4*)(g_yhi + (size_t)(mtile*128)*Dn);
    const uint4* srcL = (const uint4*)(g_ylo + (size_t)(mtile*128)*Dn);
    #pragma unroll
    for (int i=0;i<16;i++){
      int lin = i*256 + tid;
      int row = lin>>5, ch = lin&31;
      uint32_t off = (uint32_t)(row*512 + ((ch ^ (row&7))<<4));
      *(uint4*)(smc + off) = srcH[lin];
      *(uint4*)(smc + KO_ALO + off) = srcL[lin];
    }
  }
  {
    const uint4* srcH = (const uint4*)(g_woThi + (size_t)(ntile*64)*256);
    const uint4* srcL = (const uint4*)(g_woTlo + (size_t)(ntile*64)*256);
    #pragma unroll
    for (int i=0;i<8;i++){
      int lin = i*256 + tid;
      int row = lin>>5, ch = lin&31;
      uint32_t off = (uint32_t)(row*512 + ((ch ^ (row&7))<<4));
      *(uint4*)(smc + KO_BHI + off) = srcH[lin];
      *(uint4*)(smc + KO_BLO + off) = srcL[lin];
    }
  }
  __syncthreads();

  float acc[8][4];
  #pragma unroll
  for (int nt=0;nt<8;nt++){ acc[nt][0]=0.f; acc[nt][1]=0.f; acc[nt][2]=0.f; acc[nt][3]=0.f; }

  int m0 = wid*16;
  int arow = m0 + (lane&15);
  int aks  = lane>>4;
  uint32_t aRowOff = (uint32_t)(arow*512);
  int arx = arow & 7;
  int nrow = ((lane>>4)<<3) + (lane&7);
  int bks  = (lane>>3)&1;
  uint32_t bRowOff = (uint32_t)(nrow*512);
  int nrx = nrow & 7;

  for (int kk=0;kk<16;kk++){
    int kc = kk*2;
    uint32_t aH[4], aL[4];
    uint32_t aoff = aRowOff + (uint32_t)((((kc+aks) ^ arx))<<4);
    ldsm4(aH[0],aH[1],aH[2],aH[3], sb + aoff);
    ldsm4(aL[0],aL[1],aL[2],aL[3], sb + KO_ALO + aoff);
    uint32_t boff = bRowOff + (uint32_t)((((kc+bks) ^ nrx))<<4);
    #pragma unroll
    for (int bt=0;bt<4;bt++){
      uint32_t addr = (uint32_t)(bt*16*512) + boff;
      uint32_t bh0,bh1,bh2,bh3, bl0,bl1,bl2,bl3;
      ldsm4(bh0,bh1,bh2,bh3, sb + KO_BHI + addr);
      ldsm4(bl0,bl1,bl2,bl3, sb + KO_BLO + addr);
      mma16816(acc[2*bt],   aH, bh0, bh1);
      mma16816(acc[2*bt],   aL, bh0, bh1);
      mma16816(acc[2*bt],   aH, bl0, bl1);
      mma16816(acc[2*bt+1], aH, bh2, bh3);
      mma16816(acc[2*bt+1], aL, bh2, bh3);
      mma16816(acc[2*bt+1], aH, bl2, bl3);
    }
  }

  {
    int gRow = lane>>2, tig = lane&3;
    size_t plane = (ntile < 4) ? OFF_MEAN : OFF_LOG;
    int colbase = ntile*64 - ((ntile>=4)?256:0);
    const float* bop = bo + ntile*64;
    #pragma unroll
    for (int nt=0;nt<8;nt++){
      int c0 = nt*8 + 2*tig;
      float b0v = bop[c0], b1v = bop[c0+1];
      #pragma unroll
      for (int half=0;half<2;half++){
        int m_g = mtile*128 + m0 + gRow + half*8;
        int b = m_g / Tn;
        int t = m_g - b*Tn;
        size_t base = plane + ((size_t)(b*Dn + colbase + c0))*Tn + t;
        out[base]      = acc[nt][half*2+0] + b0v;
        out[base + Tn] = acc[nt][half*2+1] + b1v;
      }
    }
  }
}

// ---------------- launcher ----------------
extern "C" void kernel_launch(void* const* d_in, const int* in_sizes, int n_in,
                              void* d_out, int out_size){
  (void)in_sizes; (void)n_in; (void)out_size;
  const float* dur = (const float*)d_in[0];
  const float* phon= (const float*)d_in[1];
  const float* Wpw = (const float*)d_in[3];
  const float* bpw = (const float*)d_in[4];
  const float* Cw  = (const float*)d_in[5];
  const float* cbw = (const float*)d_in[6];
  const float* Mw  = (const float*)d_in[7];
  const float* mbw = (const float*)d_in[8];
  const float* Lw  = (const float*)d_in[9];
  const float* lbw = (const float*)d_in[10];
  const float* Wpc = (const float*)d_in[11];
  const float* bpc = (const float*)d_in[12];
  const float* Cc  = (const float*)d_in[13];
  const float* cbc = (const float*)d_in[14];
  const float* Mc  = (const float*)d_in[15];
  const float* mbc = (const float*)d_in[16];
  const float* Lcm = (const float*)d_in[17];
  const float* lbc = (const float*)d_in[18];
  const float* Wo  = (const float*)d_in[19];
  const float* bo  = (const float*)d_in[20];
  float* out = (float*)d_out;

  cudaFuncSetAttribute((const void*)k_main, cudaFuncAttributeMaxDynamicSharedMemorySize,
                       SMEM_BYTES);
  cudaFuncSetAttribute((const void*)k_comb, cudaFuncAttributeMaxDynamicSharedMemorySize,
                       KC_SMEM);
  cudaFuncSetAttribute((const void*)k_out, cudaFuncAttributeMaxDynamicSharedMemorySize,
                       KO_SMEM);

  k_pre<<<980,256>>>(dur, phon, Cw, Wpw, Cc, Wpc, bpw, cbw, bpc, cbc, Wo, Lcm, lbw, lbc, out);
  k_mid<<<1232,256>>>(Lw);
  k_main<<<dim3(NB,Bn),256,SMEM_BYTES>>>(dur,Mw,mbw,Mc,mbc,out);
  k_comb<<<dim3(8,2,Bn),256,KC_SMEM>>>();
  k_out<<<dim3(125,8),256,KO_SMEM>>>(bo,out);
}

// round 11
// speedup vs baseline: 2.0115x; 1.1371x over previous
#include <cuda_runtime.h>
#include <cuda_bf16.h>
#include <cstdint>
#include <math.h>

typedef unsigned long long ull;

#define Bn 16
#define Dn 256
#define Ln 200
#define Tn 1000
#define TT 16
#define NB 63            // ceil(1000/16)
#define KW 832           // padded K: [q*200+l] (800) | wc (8) | bias (1) | pad (23)

#define OFF_MEAN ((size_t)0)
#define OFF_LOG  ((size_t)4096000)
#define OFF_FM   ((size_t)8192000)
#define OFF_FL   ((size_t)8208000)
#define OFF_W    ((size_t)8208016)

// ---------------- device scratch ----------------
__device__ float g_sk[Bn*Ln];
__device__ int   g_plen[Bn];
__device__ int   g_flen[Bn];
__device__ float g_phonT[(size_t)Bn*Ln*Dn];          // [b][l][d]
__device__ float g_hw[(size_t)Bn*Ln*8];
__device__ float g_hc[(size_t)Bn*Ln*8];
__device__ float g_Ceff[2*8*3*Dn];
__device__ float g_beff[2*8*3];
__device__ unsigned short g_wbf_hi[(size_t)Bn*1024*KW];  // W' [b][t(1024)][k]
__device__ unsigned short g_wbf_lo[(size_t)Bn*1024*KW];
__device__ unsigned short g_pbf_hi[(size_t)Bn*Dn*KW];    // P'T [b][d][k]
__device__ unsigned short g_pbf_lo[(size_t)Bn*Dn*KW];
__device__ unsigned short g_yhi[(size_t)Bn*Tn*Dn];   // bf16 hi of y, [m=b*1000+t][d]
__device__ unsigned short g_ylo[(size_t)Bn*Tn*Dn];   // bf16 lo
__device__ unsigned short g_woThi[512*256];          // bf16 WoT [n][k]
__device__ unsigned short g_woTlo[512*256];

__device__ __forceinline__ float silu_f(float x){ return __fdividef(x, 1.f + __expf(-x)); }

__device__ __forceinline__ ull pack2(float a, float b){
  ull r; asm("mov.b64 %0,{%1,%2};" : "=l"(r) : "f"(a), "f"(b)); return r;
}
__device__ __forceinline__ ull fma2(ull a, ull b, ull c){
  ull d; asm("fma.rn.f32x2 %0,%1,%2,%3;" : "=l"(d) : "l"(a), "l"(b), "l"(c)); return d;
}
__device__ __forceinline__ void unpack2(ull v, float& a, float& b){
  asm("mov.b64 {%0,%1},%2;" : "=f"(a), "=f"(b) : "l"(v));
}
__device__ __forceinline__ uint32_t smem_u32(const void* p){
  uint32_t a;
  asm("{ .reg .u64 t; cvta.to.shared.u64 t, %1; cvt.u32.u64 %0, t; }" : "=r"(a) : "l"(p));
  return a;
}
__device__ __forceinline__ void bf_split(float v, unsigned short& h, unsigned short& l){
  __nv_bfloat16 hb = __float2bfloat16(v);
  h = __bfloat16_as_ushort(hb);
  l = __bfloat16_as_ushort(__float2bfloat16(v - __bfloat162float(hb)));
}

// ---------------- mma.sync helpers ----------------
__device__ __forceinline__ void ldsm4(uint32_t& r0, uint32_t& r1, uint32_t& r2, uint32_t& r3,
                                      uint32_t addr){
  asm volatile("ldmatrix.sync.aligned.m8n8.x4.shared.b16 {%0,%1,%2,%3}, [%4];"
    : "=r"(r0), "=r"(r1), "=r"(r2), "=r"(r3) : "r"(addr));
}
__device__ __forceinline__ void mma16816(float* d, const uint32_t* a, uint32_t b0, uint32_t b1){
  asm volatile("mma.sync.aligned.m16n8k16.row.col.f32.bf16.bf16.f32 "
    "{%0,%1,%2,%3},{%4,%5,%6,%7},{%8,%9},{%0,%1,%2,%3};"
    : "+f"(d[0]), "+f"(d[1]), "+f"(d[2]), "+f"(d[3])
    : "r"(a[0]), "r"(a[1]), "r"(a[2]), "r"(a[3]), "r"(b0), "r"(b1));
}

// ================= K_PRE =================
// 0..895 transpose | 896..943 ceff | 944..945 beff | 946..961 setup | 962..963 WoT | 964..979 P'-extra
__global__ void k_pre(const float* __restrict__ dur, const float* __restrict__ phon,
                      const float* __restrict__ Cw, const float* __restrict__ Wpw,
                      const float* __restrict__ Cc, const float* __restrict__ Wpc,
                      const float* __restrict__ bpw, const float* __restrict__ cbw,
                      const float* __restrict__ bpc, const float* __restrict__ cbc,
                      const float* __restrict__ Wo,
                      const float* __restrict__ Lcm, const float* __restrict__ lbw,
                      const float* __restrict__ lbc,
                      float* __restrict__ out){
  __shared__ float tile[32][33];
  __shared__ float cs[Dn];
  __shared__ int sfl;
  int bi = blockIdx.x, tid = threadIdx.x;

  if (bi < 896){
    int l0 = (bi%7)*32, d0 = ((bi/7)%8)*32, b = bi/56;
    int tx = tid&31, ty = tid>>5;
    #pragma unroll
    for (int r=0;r<4;r++){
      int dy = d0+ty+8*r, lx = l0+tx;
      tile[ty+8*r][tx] = (lx<Ln) ? phon[((size_t)b*Dn+dy)*Ln+lx] : 0.f;
    }
    __syncthreads();
    #pragma unroll
    for (int r=0;r<4;r++){
      int ly = l0+ty+8*r, dx = d0+tx;
      if (ly<Ln) g_phonT[((size_t)b*Ln+ly)*Dn+dx] = tile[tx][ty+8*r];
    }
  } else if (bi < 944){
    int idx = bi-896;
    int o = idx&7, k = (idx>>3)%3, which = idx/24;
    const float* C = which? Cc : Cw;
    const float* W = which? Wpc : Wpw;
    cs[tid] = C[(o*Dn+tid)*3+k];
    __syncthreads();
    float acc=0.f;
    #pragma unroll 8
    for (int d=0; d<Dn; d++)
      acc = fmaf(cs[d], W[d*Dn+tid], acc);
    g_Ceff[((which*8+o)*3+k)*Dn + tid] = acc;
  } else if (bi < 946){
    int which = bi-944;
    const float* C = which? Cc: Cw; const float* bp = which? bpc : bpw; const float* cb = which? cbc : cbw;
    int wp = tid>>5, lane = tid&31;
    for (int pr=wp; pr<24; pr+=8){
      int o = pr/3, var = pr%3;
      int k0 = (var==0)?1:0, k1 = (var==2)?1:2;
      float acc = 0.f;
      #pragma unroll
      for (int i=0;i<8;i++){
        int d = lane + 32*i;
        float bv = bp[d];
        for (int k=k0;k<=k1;k++) acc = fmaf(C[(o*Dn+d)*3+k], bv, acc);
      }
      #pragma unroll
      for (int off=16;off;off>>=1) acc += __shfl_xor_sync(0xffffffffu, acc, off);
      if (lane==0) g_beff[(which*8+o)*3+var] = acc + cb[o];
    }
  } else if (bi < 962){
    int b = bi-946;
    float* s = &tile[0][0];
    if (tid < Ln) s[tid] = dur[b*Ln+tid];
    __syncthreads();
    if (tid == 0){
      float acc = 0.f; int plen = 0;
      for (int l=0;l<Ln;l++){ g_sk[b*Ln+l]=acc; float d=s[l]; acc+=d; if (d>0.f) plen=l+1; }
      g_plen[b]=plen;
      int fl = (int)rintf(acc); fl = fl<0?0:(fl>Tn?Tn:fl);
      g_flen[b]=fl; sfl=fl;
      out[OFF_FL + b] = (float)fl;
    }
    __syncthreads();
    int fl = sfl;
    for (int t=tid;t<Tn;t+=256) out[OFF_FM + (size_t)b*Tn + t] = (t<fl)?1.f:0.f;
  } else if (bi < 964){
    // WoT hi/lo split
    int n = (bi-962)*256 + tid;
    for (int kc=0;kc<32;kc++){
      __align__(16) unsigned short h8[8];
      __align__(16) unsigned short l8[8];
      #pragma unroll
      for (int j=0;j<8;j++){
        float w = Wo[(size_t)(kc*8+j)*512 + n];
        bf_split(w, h8[j], l8[j]);
      }
      *(uint4*)&g_woThi[n*256 + kc*8] = *(uint4*)h8;
      *(uint4*)&g_woTlo[n*256 + kc*8] = *(uint4*)l8;
    }
  } else {
    // P' extra rows: k=800..807 = Lc, k=808 = lbw+lbc, 809..831 = 0
    int b = bi-964;
    size_t base = ((size_t)b*Dn + tid)*KW;
    #pragma unroll
    for (int i=0;i<8;i++){
      unsigned short h,l; bf_split(Lcm[i*Dn+tid], h, l);
      g_pbf_hi[base+800+i]=h; g_pbf_lo[base+800+i]=l;
    }
    {
      unsigned short h,l; bf_split(lbw[tid]+lbc[tid], h, l);
      g_pbf_hi[base+808]=h; g_pbf_lo[base+808]=l;
    }
    for (int k=809;k<KW;k++){ g_pbf_hi[base+k]=0; g_pbf_lo[base+k]=0; }
  }
}

// ================= K_MID: conv (0..399) + P' GEMM (400..1231) =================
__global__ void k_mid(const float* __restrict__ Lw){
  __shared__ float sbuf[4096];
  int bi = blockIdx.x, tid = threadIdx.x;

  if (bi < 400){
    float* xs = sbuf;
    int b = bi/25, l0 = (bi%25)*8;
    for (int i=tid; i<10*Dn; i+=256){
      int r = i>>8, dp = i&255, col = l0-1+r;
      xs[r*Dn+dp] = (col>=0 && col<Ln) ? g_phonT[((size_t)b*Ln+col)*Dn+dp] : 0.f;
    }
    __syncthreads();
    int warp = tid>>5, lane = tid&31;
    int l = l0 + warp;
    int plen = g_plen[b];
    for (int idx=0; idx<16; idx++){
      int which = idx>>3, o = idx&7;
      const float* ce = g_Ceff + ((which*8+o)*3)*Dn;
      float acc = 0.f;
      for (int i=lane; i<3*Dn; i+=32){
        int k = i>>8, dp = i&255;
        acc = fmaf(ce[k*Dn+dp], xs[((l-l0)+k)*Dn+dp], acc);
      }
      #pragma unroll
      for (int off=16; off; off>>=1) acc += __shfl_xor_sync(0xffffffffu, acc, off);
      if (lane==0){
        int var = (l==0)?0:((l==Ln-1)?2:1);
        float h = silu_f(acc + g_beff[(which*8+o)*3+var]);
        h = (l < plen) ? h : 0.f;
        float* dst = which ? g_hc : g_hw;
        dst[((size_t)b*Ln+l)*8 + o] = h;
      }
    }
  } else {
    float* A = sbuf;
    int idx = bi-400;
    int c = idx%13, q = (idx/13)&3, b = idx/52;
    int l0 = c*16, nl = min(16, Ln - l0);
    for (int i=tid; i<16*Dn; i+=256){
      int li = i>>8, dp = i&255;
      A[dp*16+li] = (li < nl) ? g_phonT[((size_t)b*Ln + l0+li)*Dn + dp] : 0.f;
    }
    __syncthreads();
    ull acc[8];
    #pragma unroll
    for (int j=0;j<8;j++) acc[j]=pack2(0.f,0.f);
    const float* LwQ = Lw + (size_t)q*Dn*Dn;
    for (int dd=0; dd<Dn; dd++){
      float lw = LwQ[dd*Dn + tid];
      ull lw2 = pack2(lw, lw);
      const ulonglong2* ap = (const ulonglong2*)(A + dd*16);
      #pragma unroll
      for (int j=0;j<4;j++){
        ulonglong2 av = ap[j];
        acc[2*j]   = fma2(av.x, lw2, acc[2*j]);
        acc[2*j+1] = fma2(av.y, lw2, acc[2*j+1]);
      }
    }
    // write P'T bf16 hi/lo: [b][d=tid][k = q*200 + (l0+i)]  (vectorized 16B stores)
    __align__(16) unsigned short h16[16];
    __align__(16) unsigned short l16[16];
    #pragma unroll
    for (int j=0;j<8;j++){
      float a,b2; unpack2(acc[j], a, b2);
      bf_split(a,  h16[2*j],   l16[2*j]);
      bf_split(b2, h16[2*j+1], l16[2*j+1]);
    }
    size_t base = ((size_t)b*Dn + tid)*KW + (size_t)q*200 + l0;
    *(uint4*)&g_pbf_hi[base] = ((uint4*)h16)[0];
    *(uint4*)&g_pbf_lo[base] = ((uint4*)l16)[0];
    if (nl == 16){
      *(uint4*)&g_pbf_hi[base+8] = ((uint4*)h16)[1];
      *(uint4*)&g_pbf_lo[base+8] = ((uint4*)l16)[1];
    }
  }
}

// ================= K_MAIN: phases 1-2 + W' export =================
// dyn smem (floats): w_s 0..12800 | sk 12800..13000 | bc 13000..13400 | wc 13400..13528 | prm 13528..13594
#define SMEM_BYTES 54376

__global__ __launch_bounds__(256,3) void k_main(
  const float* __restrict__ dur,
  const float* __restrict__ Mw, const float* __restrict__ mbw,
  const float* __restrict__ Mc, const float* __restrict__ mbc,
  float* __restrict__ out)
{
  extern __shared__ float sm[];
  float* w_s  = sm;
  float* sk_s = sm + 12800;
  float* bc_s = sm + 13000;
  float* wc_s = sm + 13400;
  float* prm  = sm + 13528;

  int b = blockIdx.y;
  int t0 = blockIdx.x * TT;
  int tid = threadIdx.x;
  int plen = g_plen[b], flen = g_flen[b];
  bool active = (t0 < flen);

  if (active){
    if (tid < 40)      prm[tid] = Mw[tid];
    else if (tid < 44) prm[tid] = mbw[tid-40];
    else if (tid < 64) prm[tid] = Mc[tid-44];
    else if (tid < 66) prm[tid] = mbc[tid-64];
    __syncthreads();

    // ---- phase 1 ----
    if (tid < Ln){
      int l = tid;
      float dv = dur[b*Ln + l];
      float sk = g_sk[b*Ln + l];
      sk_s[l] = sk;
      const float* hwp = g_hw + ((size_t)b*Ln+l)*8;
      const float* hcp = g_hc + ((size_t)b*Ln+l)*8;
      float bw[4], bc[2];
      #pragma unroll
      for (int q=0;q<4;q++){
        float a = prm[40+q] + dv*prm[4+q];
        #pragma unroll
        for (int j=0;j<8;j++) a = fmaf(hwp[j], prm[(2+j)*4+q], a);
        bw[q]=a;
      }
      #pragma unroll
      for (int p=0;p<2;p++){
        float a = prm[64+p] + dv*prm[46+p];
        #pragma unroll
        for (int j=0;j<8;j++) a = fmaf(hcp[j], prm[44+(2+j)*2+p], a);
        bc[p]=a;
      }
      bc_s[2*l]   = bc[0];
      bc_s[2*l+1] = bc[1];
      bool lv = l < plen;
      float4* wl = (float4*)(w_s + l*64);
      #pragma unroll
      for (int t=0;t<TT;t++){
        int tt = t0+t;
        float4 av = {0.f,0.f,0.f,0.f};
        if (lv && tt < flen){
          float S = (float)(tt+1) - sk;
          av.x = silu_f(fmaf(S, prm[0], bw[0]));
          av.y = silu_f(fmaf(S, prm[1], bw[1]));
          av.z = silu_f(fmaf(S, prm[2], bw[2]));
          av.w = silu_f(fmaf(S, prm[3], bw[3]));
        }
        wl[t] = av;
      }
    }
    __syncthreads();

    // ---- phase 2: softmax + f32 w out + wc reduce ----
    {
      int wp = tid>>5, lane = tid&31;
      float mc0 = prm[44], mc1 = prm[45];
      const size_t qs = (size_t)Tn*Ln;
      for (int t=wp; t<TT; t+=8){
        int tt = t0+t;
        if (tt >= Tn) continue;
        size_t wb = OFF_W + ((size_t)(b*4)*Tn + tt)*Ln;
        if (tt >= flen){
          for (int l=lane; l<Ln; l+=32){
            out[wb+l]=0.f; out[wb+qs+l]=0.f; out[wb+2*qs+l]=0.f; out[wb+3*qs+l]=0.f;
          }
          if (lane<8) wc_s[t*8+lane]=0.f;
          continue;
        }
        float4 wv[7];
        float m0=-3e38f,m1=-3e38f,m2=-3e38f,m3=-3e38f;
        #pragma unroll
        for (int i=0;i<7;i++){
          int l = lane + 32*i;
          if (l < plen){
            wv[i] = *(const float4*)(w_s + l*64 + t*4);
            m0=fmaxf(m0,wv[i].x); m1=fmaxf(m1,wv[i].y); m2=fmaxf(m2,wv[i].z); m3=fmaxf(m3,wv[i].w);
          }
        }
        #pragma unroll
        for (int off=16;off;off>>=1){
          m0=fmaxf(m0,__shfl_xor_sync(0xffffffffu,m0,off));
          m1=fmaxf(m1,__shfl_xor_sync(0xffffffffu,m1,off));
          m2=fmaxf(m2,__shfl_xor_sync(0xffffffffu,m2,off));
          m3=fmaxf(m3,__shfl_xor_sync(0xffffffffu,m3,off));
        }
        float s0=0.f,s1=0.f,s2=0.f,s3=0.f;
        #pragma unroll
        for (int i=0;i<7;i++){
          int l = lane + 32*i;
          if (l < plen){
            wv[i].x=__expf(wv[i].x-m0); wv[i].y=__expf(wv[i].y-m1);
            wv[i].z=__expf(wv[i].z-m2); wv[i].w=__expf(wv[i].w-m3);
            s0+=wv[i].x; s1+=wv[i].y; s2+=wv[i].z; s3+=wv[i].w;
          }
        }
        #pragma unroll
        for (int off=16;off;off>>=1){
          s0+=__shfl_xor_sync(0xffffffffu,s0,off);
          s1+=__shfl_xor_sync(0xffffffffu,s1,off);
          s2+=__shfl_xor_sync(0xffffffffu,s2,off);
          s3+=__shfl_xor_sync(0xffffffffu,s3,off);
        }
        float i0=__fdividef(1.f,s0), i1=__fdividef(1.f,s1), i2=__fdividef(1.f,s2), i3=__fdividef(1.f,s3);
        float Sb = (float)(tt+1);
        float r0=0.f,r1=0.f,r2=0.f,r3=0.f,r4=0.f,r5=0.f,r6=0.f,r7=0.f;
        #pragma unroll
        for (int i=0;i<7;i++){
          int l = lane + 32*i;
          if (l < plen){
            float4 v; v.x=wv[i].x*i0; v.y=wv[i].y*i1; v.z=wv[i].z*i2; v.w=wv[i].w*i3;
            *(float4*)(w_s + l*64 + t*4) = v;
            out[wb+l]=v.x; out[wb+qs+l]=v.y; out[wb+2*qs+l]=v.z; out[wb+3*qs+l]=v.w;
            float S = Sb - sk_s[l];
            float cx = silu_f(fmaf(S, mc0, bc_s[2*l]));
            float cy = silu_f(fmaf(S, mc1, bc_s[2*l+1]));
            r0=fmaf(v.x,cx,r0); r1=fmaf(v.x,cy,r1);
            r2=fmaf(v.y,cx,r2); r3=fmaf(v.y,cy,r3);
            r4=fmaf(v.z,cx,r4); r5=fmaf(v.z,cy,r5);
            r6=fmaf(v.w,cx,r6); r7=fmaf(v.w,cy,r7);
          } else if (l < Ln){
            out[wb+l]=0.f; out[wb+qs+l]=0.f; out[wb+2*qs+l]=0.f; out[wb+3*qs+l]=0.f;
          }
        }
        #pragma unroll
        for (int off=16;off;off>>=1){
          r0+=__shfl_xor_sync(0xffffffffu,r0,off); r1+=__shfl_xor_sync(0xffffffffu,r1,off);
          r2+=__shfl_xor_sync(0xffffffffu,r2,off); r3+=__shfl_xor_sync(0xffffffffu,r3,off);
          r4+=__shfl_xor_sync(0xffffffffu,r4,off); r5+=__shfl_xor_sync(0xffffffffu,r5,off);
          r6+=__shfl_xor_sync(0xffffffffu,r6,off); r7+=__shfl_xor_sync(0xffffffffu,r7,off);
        }
        if (lane==0){
          wc_s[t*8+0]=r0; wc_s[t*8+1]=r1; wc_s[t*8+2]=r2; wc_s[t*8+3]=r3;
          wc_s[t*8+4]=r4; wc_s[t*8+5]=r5; wc_s[t*8+6]=r6; wc_s[t*8+7]=r7;
        }
      }
    }
    __syncthreads();

    // ---- phase 2.5: export W' rows, k = q*200+l (lane-coalesced) ----
    for (int t=0;t<TT;t++){
      int tt = t0+t;
      if (tt >= Tn) break;
      size_t rw = ((size_t)(b*1024)+tt)*KW;
      if (tid < Ln){
        float4 v = *(const float4*)(w_s + tid*64 + t*4);
        unsigned short h,l;
        bf_split(v.x,h,l); g_wbf_hi[rw+tid]=h;     g_wbf_lo[rw+tid]=l;
        bf_split(v.y,h,l); g_wbf_hi[rw+200+tid]=h; g_wbf_lo[rw+200+tid]=l;
        bf_split(v.z,h,l); g_wbf_hi[rw+400+tid]=h; g_wbf_lo[rw+400+tid]=l;
        bf_split(v.w,h,l); g_wbf_hi[rw+600+tid]=h; g_wbf_lo[rw+600+tid]=l;
      } else if (tid < 202){
        int base = (tid-200)*4;
        #pragma unroll
        for (int j=0;j<4;j++){
          unsigned short h,l; bf_split(wc_s[t*8+base+j],h,l);
          g_wbf_hi[rw+800+base+j]=h; g_wbf_lo[rw+800+base+j]=l;
        }
      } else if (tid == 202){
        bool live = tt < flen;
        unsigned short h,l; bf_split(live?1.f:0.f,h,l);
        g_wbf_hi[rw+808]=h; g_wbf_lo[rw+808]=l;
        for (int k=809;k<812;k++){ g_wbf_hi[rw+k]=0; g_wbf_lo[rw+k]=0; }
      } else if (tid < 208){
        int k0 = 812 + (tid-203)*4;
        #pragma unroll
        for (int j=0;j<4;j++){ g_wbf_hi[rw+k0+j]=0; g_wbf_lo[rw+k0+j]=0; }
      }
    }
  } else {
    // inactive: zero w planes + zero W' rows
    int wp = tid>>5, lane = tid&31;
    const size_t qs = (size_t)Tn*Ln;
    for (int t=wp; t<TT; t+=8){
      int tt = t0+t;
      if (tt >= Tn) continue;
      size_t wb = OFF_W + ((size_t)(b*4)*Tn + tt)*Ln;
      for (int l=lane; l<Ln; l+=32){
        out[wb+l]=0.f; out[wb+qs+l]=0.f; out[wb+2*qs+l]=0.f; out[wb+3*qs+l]=0.f;
      }
    }
    for (int t=0;t<TT;t++){
      int tt = t0+t;
      if (tt >= Tn) break;
      size_t rw = ((size_t)(b*1024)+tt)*KW;
      for (int k=tid;k<KW;k+=256){ g_wbf_hi[rw+k]=0; g_wbf_lo[rw+k]=0; }
    }
  }
}

// ================= K_COMB: Y = W' @ P'  (mma.sync bf16 hi/lo x3) -> g_yhi/g_ylo =================
#define KC_ALO 16384
#define KC_BHI 32768
#define KC_BLO 49152
#define KC_SMEM 65536

__global__ __launch_bounds__(256,2) void k_comb(){
  extern __shared__ float smf[];
  char* smc = (char*)smf;
  uint32_t sb = smem_u32(smc);
  int tid = threadIdx.x, wid = tid>>5, lane = tid&31;
  int mtile = blockIdx.x, ntile = blockIdx.y, b = blockIdx.z;

  // dead fast path: whole m-tile past flen -> Y = 0
  if (mtile*128 >= g_flen[b]){
    uint4 z; z.x=0u; z.y=0u; z.z=0u; z.w=0u;
    #pragma unroll
    for (int i=0;i<8;i++){
      int lin = i*256 + tid;
      int r = lin>>4, ch = lin&15;
      int t = mtile*128 + r;
      if (t < Tn){
        size_t row = (size_t)b*Tn + t;
        ((uint4*)(g_yhi + row*Dn + ntile*128))[ch] = z;
        ((uint4*)(g_ylo + row*Dn + ntile*128))[ch] = z;
      }
    }
    return;
  }

  float acc[2][8][4];
  #pragma unroll
  for (int mt=0;mt<2;mt++)
    #pragma unroll
    for (int ng=0;ng<8;ng++){ acc[mt][ng][0]=0.f; acc[mt][ng][1]=0.f; acc[mt][ng][2]=0.f; acc[mt][ng][3]=0.f; }

  int m0 = (wid&3)*32, n0 = (wid>>2)*64;

  const uint4* gwh = (const uint4*)(g_wbf_hi + ((size_t)(b*1024) + (size_t)mtile*128)*KW);
  const uint4* gwl = (const uint4*)(g_wbf_lo + ((size_t)(b*1024) + (size_t)mtile*128)*KW);
  const uint4* gph = (const uint4*)(g_pbf_hi + ((size_t)(b*Dn) + (size_t)ntile*128)*KW);
  const uint4* gpl = (const uint4*)(g_pbf_lo + ((size_t)(b*Dn) + (size_t)ntile*128)*KW);
  const int rs = KW/8;   // 104

  for (int c=0;c<13;c++){
    if (c) __syncthreads();
    #pragma unroll
    for (int i=0;i<4;i++){
      int lin = i*256 + tid;
      int row = lin>>3, ch = lin&7;
      uint32_t off = (uint32_t)(row*128 + ((ch ^ (row&7))<<4));
      size_t g = (size_t)row*rs + c*8 + ch;
      *(uint4*)(smc + off) = gwh[g];
      *(uint4*)(smc + KC_ALO + off) = gwl[g];
      *(uint4*)(smc + KC_BHI + off) = gph[g];
      *(uint4*)(smc + KC_BLO + off) = gpl[g];
    }
    __syncthreads();
    #pragma unroll
    for (int kk=0;kk<4;kk++){
      uint32_t aH[2][4], aL[2][4];
      #pragma unroll
      for (int mt=0;mt<2;mt++){
        int arow = m0 + mt*16 + (lane&15);
        uint32_t aoff = (uint32_t)(arow*128 + (((kk*2 + (lane>>4)) ^ (arow&7))<<4));
        ldsm4(aH[mt][0],aH[mt][1],aH[mt][2],aH[mt][3], sb + aoff);
        ldsm4(aL[mt][0],aL[mt][1],aL[mt][2],aL[mt][3], sb + KC_ALO + aoff);
      }
      #pragma unroll
      for (int ng=0;ng<4;ng++){
        int nrow = n0 + ng*16 + ((lane>>4)<<3) + (lane&7);
        uint32_t boff = (uint32_t)(nrow*128 + (((kk*2 + ((lane>>3)&1)) ^ (nrow&7))<<4));
        uint32_t bh0,bh1,bh2,bh3, bl0,bl1,bl2,bl3;
        ldsm4(bh0,bh1,bh2,bh3, sb + KC_BHI + boff);
        ldsm4(bl0,bl1,bl2,bl3, sb + KC_BLO + boff);
        #pragma unroll
        for (int mt=0;mt<2;mt++){
          mma16816(acc[mt][2*ng],   aH[mt], bh0, bh1);
          mma16816(acc[mt][2*ng],   aL[mt], bh0, bh1);
          mma16816(acc[mt][2*ng],   aH[mt], bl0, bl1);
          mma16816(acc[mt][2*ng+1], aH[mt], bh2, bh3);
          mma16816(acc[mt][2*ng+1], aL[mt], bh2, bh3);
          mma16816(acc[mt][2*ng+1], aH[mt], bl2, bl3);
        }
      }
    }
  }

  // epilogue: split f32 -> bf16 hi/lo, store to g_yhi/g_ylo
  #pragma unroll
  for (int mt=0;mt<2;mt++){
    #pragma unroll
    for (int ng=0;ng<8;ng++){
      int d = ntile*128 + n0 + ng*8 + (lane&3)*2;
      #pragma unroll
      for (int half=0;half<2;half++){
        int t = mtile*128 + m0 + mt*16 + (lane>>2) + half*8;
        if (t < Tn){
          size_t row = (size_t)b*Tn + t;
          unsigned short h0,l0,h1,l1;
          bf_split(acc[mt][ng][half*2+0], h0, l0);
          bf_split(acc[mt][ng][half*2+1], h1, l1);
          ushort2 hh; hh.x=h0; hh.y=h1;
          ushort2 ll; ll.x=l0; ll.y=l1;
          *(ushort2*)&g_yhi[row*Dn + d] = hh;
          *(ushort2*)&g_ylo[row*Dn + d] = ll;
        }
      }
    }
  }
}

// ================= K_OUT: out = y @ Wo + bo  (mma.sync, K-chunked, m32n32 warps) =================
// smem: A_hi 32KB | A_lo 32KB | B_hi 16KB | B_lo 16KB  = 96KB; rows 256B, swizzle ch^(row&7)
#define KO_ALO 32768
#define KO_BHI 65536
#define KO_BLO 81920
#define KO_SMEM 98304

__global__ __launch_bounds__(256,2) void k_out(const float* __restrict__ bo,
                                               float* __restrict__ out){
  extern __shared__ float smf[];
  char* smc = (char*)smf;
  uint32_t sb = smem_u32(smc);
  int tid = threadIdx.x, wid = tid>>5, lane = tid&31;
  int mtile = blockIdx.x, ntile = blockIdx.y;

  // dead fast path
  {
    int mstart = mtile*128;
    int b0 = mstart/Tn, b1 = (mstart+127)/Tn;
    int t_start = mstart - b0*Tn;
    bool dead = (t_start >= g_flen[b0]) && (b1==b0 || g_flen[b1]<=0);
    if (dead){
      int r = tid & 127;
      int m = mtile*128 + r;
      int b = m/Tn, t = m - b*Tn;
      size_t plane = (ntile<4)?OFF_MEAN:OFF_LOG;
      int colbase = ntile*64 - ((ntile>=4)?256:0);
      const float* bop = bo + ntile*64;
      for (int i = tid>>7; i<64; i+=2)
        out[plane + ((size_t)(b*Dn + colbase + i))*Tn + t] = bop[i];
      return;
    }
  }

  float acc[2][4][4];
  #pragma unroll
  for (int mt=0;mt<2;mt++)
    #pragma unroll
    for (int ng=0;ng<4;ng++){ acc[mt][ng][0]=0.f; acc[mt][ng][1]=0.f; acc[mt][ng][2]=0.f; acc[mt][ng][3]=0.f; }

  int m0 = (wid&3)*32, n0 = (wid>>2)*32;

  const uint4* aH_g = (const uint4*)(g_yhi + (size_t)(mtile*128)*Dn);
  const uint4* aL_g = (const uint4*)(g_ylo + (size_t)(mtile*128)*Dn);
  const uint4* bH_g = (const uint4*)(g_woThi + (size_t)(ntile*64)*256);
  const uint4* bL_g = (const uint4*)(g_woTlo + (size_t)(ntile*64)*256);

  for (int c=0;c<2;c++){
    if (c) __syncthreads();
    // stage A chunk (128 rows x 128 k)
    #pragma unroll
    for (int i=0;i<8;i++){
      int lin = i*256 + tid;
      int r = lin>>4, ch = lin&15;
      uint32_t off = (uint32_t)(r*256 + ((ch ^ (r&7))<<4));
      size_t g = (size_t)r*32 + c*16 + ch;
      *(uint4*)(smc + off) = aH_g[g];
      *(uint4*)(smc + KO_ALO + off) = aL_g[g];
    }
    // stage B chunk (64 rows x 128 k)
    #pragma unroll
    for (int i=0;i<4;i++){
      int lin = i*256 + tid;
      int r = lin>>4, ch = lin&15;
      uint32_t off = (uint32_t)(r*256 + ((ch ^ (r&7))<<4));
      size_t g = (size_t)r*32 + c*16 + ch;
      *(uint4*)(smc + KO_BHI + off) = bH_g[g];
      *(uint4*)(smc + KO_BLO + off) = bL_g[g];
    }
    __syncthreads();
    #pragma unroll
    for (int kk=0;kk<8;kk++){
      uint32_t aH[2][4], aL[2][4];
      #pragma unroll
      for (int mt=0;mt<2;mt++){
        int arow = m0 + mt*16 + (lane&15);
        uint32_t aoff = (uint32_t)(arow*256 + (((kk*2 + (lane>>4)) ^ (arow&7))<<4));
        ldsm4(aH[mt][0],aH[mt][1],aH[mt][2],aH[mt][3], sb + aoff);
        ldsm4(aL[mt][0],aL[mt][1],aL[mt][2],aL[mt][3], sb + KO_ALO + aoff);
      }
      #pragma unroll
      for (int g2=0;g2<2;g2++){
        int nrow = n0 + g2*16 + ((lane>>4)<<3) + (lane&7);
        uint32_t boff = (uint32_t)(nrow*256 + (((kk*2 + ((lane>>3)&1)) ^ (nrow&7))<<4));
        uint32_t bh0,bh1,bh2,bh3, bl0,bl1,bl2,bl3;
        ldsm4(bh0,bh1,bh2,bh3, sb + KO_BHI + boff);
        ldsm4(bl0,bl1,bl2,bl3, sb + KO_BLO + boff);
        #pragma unroll
        for (int mt=0;mt<2;mt++){
          mma16816(acc[mt][g2*2],   aH[mt], bh0, bh1);
          mma16816(acc[mt][g2*2],   aL[mt], bh0, bh1);
          mma16816(acc[mt][g2*2],   aH[mt], bl0, bl1);
          mma16816(acc[mt][g2*2+1], aH[mt], bh2, bh3);
          mma16816(acc[mt][g2*2+1], aL[mt], bh2, bh3);
          mma16816(acc[mt][g2*2+1], aH[mt], bl2, bl3);
        }
      }
    }
  }

  // epilogue
  {
    size_t plane = (ntile < 4) ? OFF_MEAN : OFF_LOG;
    int colbase = ntile*64 - ((ntile>=4)?256:0);
    const float* bop = bo + ntile*64;
    #pragma unroll
    for (int mt=0;mt<2;mt++){
      #pragma unroll
      for (int ng=0;ng<4;ng++){
        int cin = n0 + ng*8 + 2*(lane&3);
        float b0v = bop[cin], b1v = bop[cin+1];
        #pragma unroll
        for (int half=0;half<2;half++){
          int m_g = mtile*128 + m0 + mt*16 + (lane>>2) + half*8;
          int b = m_g / Tn;
          int t = m_g - b*Tn;
          size_t base = plane + ((size_t)(b*Dn + colbase + cin))*Tn + t;
          out[base]      = acc[mt][ng][half*2+0] + b0v;
          out[base + Tn] = acc[mt][ng][half*2+1] + b1v;
        }
      }
    }
  }
}

// ---------------- launcher ----------------
extern "C" void kernel_launch(void* const* d_in, const int* in_sizes, int n_in,
                              void* d_out, int out_size){
  (void)in_sizes; (void)n_in; (void)out_size;
  const float* dur = (const float*)d_in[0];
  const float* phon= (const float*)d_in[1];
  const float* Wpw = (const float*)d_in[3];
  const float* bpw = (const float*)d_in[4];
  const float* Cw  = (const float*)d_in[5];
  const float* cbw = (const float*)d_in[6];
  const float* Mw  = (const float*)d_in[7];
  const float* mbw = (const float*)d_in[8];
  const float* Lw  = (const float*)d_in[9];
  const float* lbw = (const float*)d_in[10];
  const float* Wpc = (const float*)d_in[11];
  const float* bpc = (const float*)d_in[12];
  const float* Cc  = (const float*)d_in[13];
  const float* cbc = (const float*)d_in[14];
  const float* Mc  = (const float*)d_in[15];
  const float* mbc = (const float*)d_in[16];
  const float* Lcm = (const float*)d_in[17];
  const float* lbc = (const float*)d_in[18];
  const float* Wo  = (const float*)d_in[19];
  const float* bo  = (const float*)d_in[20];
  float* out = (float*)d_out;

  cudaFuncSetAttribute((const void*)k_main, cudaFuncAttributeMaxDynamicSharedMemorySize,
                       SMEM_BYTES);
  cudaFuncSetAttribute((const void*)k_comb, cudaFuncAttributeMaxDynamicSharedMemorySize,
                       KC_SMEM);
  cudaFuncSetAttribute((const void*)k_out, cudaFuncAttributeMaxDynamicSharedMemorySize,
                       KO_SMEM);

  k_pre<<<980,256>>>(dur, phon, Cw, Wpw, Cc, Wpc, bpw, cbw, bpc, cbc, Wo, Lcm, lbw, lbc, out);
  k_mid<<<1232,256>>>(Lw);
  k_main<<<dim3(NB,Bn),256,SMEM_BYTES>>>(dur,Mw,mbw,Mc,mbc,out);
  k_comb<<<dim3(8,2,Bn),256,KC_SMEM>>>();
  k_out<<<dim3(125,8),256,KO_SMEM>>>(bo,out);
}

// round 12
// speedup vs baseline: 2.0650x; 1.0266x over previous
#include <cuda_runtime.h>
#include <cuda_bf16.h>
#include <cstdint>
#include <math.h>

typedef unsigned long long ull;

#define Bn 16
#define Dn 256
#define Ln 200
#define Tn 1000
#define TT 16
#define NB 63            // ceil(1000/16)
#define KW 832           // padded K: [q*200+l] (800) | wc (8) | bias (1) | pad (23)

#define OFF_MEAN ((size_t)0)
#define OFF_LOG  ((size_t)4096000)
#define OFF_FM   ((size_t)8192000)
#define OFF_FL   ((size_t)8208000)
#define OFF_W    ((size_t)8208016)

// ---------------- device scratch ----------------
__device__ float g_sk[Bn*Ln];
__device__ int   g_plen[Bn];
__device__ int   g_flen[Bn];
__device__ float g_phonT[(size_t)Bn*Ln*Dn];          // [b][l][d]
__device__ float g_hw[(size_t)Bn*Ln*8];
__device__ float g_hc[(size_t)Bn*Ln*8];
__device__ float g_Ceff[2*8*3*Dn];
__device__ float g_beff[2*8*3];
__device__ unsigned short g_wbf_hi[(size_t)Bn*1024*KW];  // W' [b][t(1024)][k]
__device__ unsigned short g_wbf_lo[(size_t)Bn*1024*KW];
__device__ unsigned short g_pbf_hi[(size_t)Bn*Dn*KW];    // P'T [b][d][k]
__device__ unsigned short g_pbf_lo[(size_t)Bn*Dn*KW];
__device__ unsigned short g_yhi[(size_t)Bn*Tn*Dn];   // bf16 hi of y, [m=b*1000+t][d]
__device__ unsigned short g_ylo[(size_t)Bn*Tn*Dn];   // bf16 lo
__device__ unsigned short g_woThi[512*256];          // bf16 WoT [n][k]
__device__ unsigned short g_woTlo[512*256];

__device__ __forceinline__ float silu_f(float x){ return __fdividef(x, 1.f + __expf(-x)); }

__device__ __forceinline__ ull pack2(float a, float b){
  ull r; asm("mov.b64 %0,{%1,%2};" : "=l"(r) : "f"(a), "f"(b)); return r;
}
__device__ __forceinline__ ull fma2(ull a, ull b, ull c){
  ull d; asm("fma.rn.f32x2 %0,%1,%2,%3;" : "=l"(d) : "l"(a), "l"(b), "l"(c)); return d;
}
__device__ __forceinline__ void unpack2(ull v, float& a, float& b){
  asm("mov.b64 {%0,%1},%2;" : "=f"(a), "=f"(b) : "l"(v));
}
__device__ __forceinline__ uint32_t smem_u32(const void* p){
  uint32_t a;
  asm("{ .reg .u64 t; cvta.to.shared.u64 t, %1; cvt.u32.u64 %0, t; }" : "=r"(a) : "l"(p));
  return a;
}
__device__ __forceinline__ void bf_split(float v, unsigned short& h, unsigned short& l){
  __nv_bfloat16 hb = __float2bfloat16(v);
  h = __bfloat16_as_ushort(hb);
  l = __bfloat16_as_ushort(__float2bfloat16(v - __bfloat162float(hb)));
}

// ---------------- mma.sync / cp.async helpers ----------------
__device__ __forceinline__ void ldsm4(uint32_t& r0, uint32_t& r1, uint32_t& r2, uint32_t& r3,
                                      uint32_t addr){
  asm volatile("ldmatrix.sync.aligned.m8n8.x4.shared.b16 {%0,%1,%2,%3}, [%4];"
    : "=r"(r0), "=r"(r1), "=r"(r2), "=r"(r3) : "r"(addr));
}
__device__ __forceinline__ void mma16816(float* d, const uint32_t* a, uint32_t b0, uint32_t b1){
  asm volatile("mma.sync.aligned.m16n8k16.row.col.f32.bf16.bf16.f32 "
    "{%0,%1,%2,%3},{%4,%5,%6,%7},{%8,%9},{%0,%1,%2,%3};"
    : "+f"(d[0]), "+f"(d[1]), "+f"(d[2]), "+f"(d[3])
    : "r"(a[0]), "r"(a[1]), "r"(a[2]), "r"(a[3]), "r"(b0), "r"(b1));
}
#define CP16(dst,src) asm volatile("cp.async.cg.shared.global [%0],[%1],16;" :: "r"(dst), "l"(src) : "memory")
#define CP_COMMIT()   asm volatile("cp.async.commit_group;" ::: "memory")
#define CP_WAIT1()    asm volatile("cp.async.wait_group 1;" ::: "memory")
#define CP_WAIT0()    asm volatile("cp.async.wait_group 0;" ::: "memory")

// ================= K_PRE =================
// 0..895 transpose | 896..943 ceff | 944..945 beff | 946..961 setup | 962..963 WoT | 964..979 P'-extra
__global__ void k_pre(const float* __restrict__ dur, const float* __restrict__ phon,
                      const float* __restrict__ Cw, const float* __restrict__ Wpw,
                      const float* __restrict__ Cc, const float* __restrict__ Wpc,
                      const float* __restrict__ bpw, const float* __restrict__ cbw,
                      const float* __restrict__ bpc, const float* __restrict__ cbc,
                      const float* __restrict__ Wo,
                      const float* __restrict__ Lcm, const float* __restrict__ lbw,
                      const float* __restrict__ lbc,
                      float* __restrict__ out){
  __shared__ float tile[32][33];
  __shared__ float cs[Dn];
  __shared__ int sfl;
  int bi = blockIdx.x, tid = threadIdx.x;

  if (bi < 896){
    int l0 = (bi%7)*32, d0 = ((bi/7)%8)*32, b = bi/56;
    int tx = tid&31, ty = tid>>5;
    #pragma unroll
    for (int r=0;r<4;r++){
      int dy = d0+ty+8*r, lx = l0+tx;
      tile[ty+8*r][tx] = (lx<Ln) ? phon[((size_t)b*Dn+dy)*Ln+lx] : 0.f;
    }
    __syncthreads();
    #pragma unroll
    for (int r=0;r<4;r++){
      int ly = l0+ty+8*r, dx = d0+tx;
      if (ly<Ln) g_phonT[((size_t)b*Ln+ly)*Dn+dx] = tile[tx][ty+8*r];
    }
  } else if (bi < 944){
    int idx = bi-896;
    int o = idx&7, k = (idx>>3)%3, which = idx/24;
    const float* C = which? Cc : Cw;
    const float* W = which? Wpc : Wpw;
    cs[tid] = C[(o*Dn+tid)*3+k];
    __syncthreads();
    float acc=0.f;
    #pragma unroll 8
    for (int d=0; d<Dn; d++)
      acc = fmaf(cs[d], W[d*Dn+tid], acc);
    g_Ceff[((which*8+o)*3+k)*Dn + tid] = acc;
  } else if (bi < 946){
    int which = bi-944;
    const float* C = which? Cc: Cw; const float* bp = which? bpc : bpw; const float* cb = which? cbc : cbw;
    int wp = tid>>5, lane = tid&31;
    for (int pr=wp; pr<24; pr+=8){
      int o = pr/3, var = pr%3;
      int k0 = (var==0)?1:0, k1 = (var==2)?1:2;
      float acc = 0.f;
      #pragma unroll
      for (int i=0;i<8;i++){
        int d = lane + 32*i;
        float bv = bp[d];
        for (int k=k0;k<=k1;k++) acc = fmaf(C[(o*Dn+d)*3+k], bv, acc);
      }
      #pragma unroll
      for (int off=16;off;off>>=1) acc += __shfl_xor_sync(0xffffffffu, acc, off);
      if (lane==0) g_beff[(which*8+o)*3+var] = acc + cb[o];
    }
  } else if (bi < 962){
    int b = bi-946;
    float* s = &tile[0][0];
    if (tid < Ln) s[tid] = dur[b*Ln+tid];
    __syncthreads();
    if (tid == 0){
      float acc = 0.f; int plen = 0;
      for (int l=0;l<Ln;l++){ g_sk[b*Ln+l]=acc; float d=s[l]; acc+=d; if (d>0.f) plen=l+1; }
      g_plen[b]=plen;
      int fl = (int)rintf(acc); fl = fl<0?0:(fl>Tn?Tn:fl);
      g_flen[b]=fl; sfl=fl;
      out[OFF_FL + b] = (float)fl;
    }
    __syncthreads();
    int fl = sfl;
    for (int t=tid;t<Tn;t+=256) out[OFF_FM + (size_t)b*Tn + t] = (t<fl)?1.f:0.f;
  } else if (bi < 964){
    // WoT hi/lo split
    int n = (bi-962)*256 + tid;
    for (int kc=0;kc<32;kc++){
      __align__(16) unsigned short h8[8];
      __align__(16) unsigned short l8[8];
      #pragma unroll
      for (int j=0;j<8;j++){
        float w = Wo[(size_t)(kc*8+j)*512 + n];
        bf_split(w, h8[j], l8[j]);
      }
      *(uint4*)&g_woThi[n*256 + kc*8] = *(uint4*)h8;
      *(uint4*)&g_woTlo[n*256 + kc*8] = *(uint4*)l8;
    }
  } else {
    // P' extra rows: k=800..807 = Lc, k=808 = lbw+lbc, 809..831 = 0
    int b = bi-964;
    size_t base = ((size_t)b*Dn + tid)*KW;
    #pragma unroll
    for (int i=0;i<8;i++){
      unsigned short h,l; bf_split(Lcm[i*Dn+tid], h, l);
      g_pbf_hi[base+800+i]=h; g_pbf_lo[base+800+i]=l;
    }
    {
      unsigned short h,l; bf_split(lbw[tid]+lbc[tid], h, l);
      g_pbf_hi[base+808]=h; g_pbf_lo[base+808]=l;
    }
    for (int k=809;k<KW;k++){ g_pbf_hi[base+k]=0; g_pbf_lo[base+k]=0; }
  }
}

// ================= K_MID: conv (0..399) + P' GEMM (400..1231) =================
__global__ void k_mid(const float* __restrict__ Lw){
  __shared__ float sbuf[4096];
  int bi = blockIdx.x, tid = threadIdx.x;

  if (bi < 400){
    float* xs = sbuf;
    int b = bi/25, l0 = (bi%25)*8;
    for (int i=tid; i<10*Dn; i+=256){
      int r = i>>8, dp = i&255, col = l0-1+r;
      xs[r*Dn+dp] = (col>=0 && col<Ln) ? g_phonT[((size_t)b*Ln+col)*Dn+dp] : 0.f;
    }
    __syncthreads();
    int warp = tid>>5, lane = tid&31;
    int l = l0 + warp;
    int plen = g_plen[b];
    for (int idx=0; idx<16; idx++){
      int which = idx>>3, o = idx&7;
      const float* ce = g_Ceff + ((which*8+o)*3)*Dn;
      float acc = 0.f;
      for (int i=lane; i<3*Dn; i+=32){
        int k = i>>8, dp = i&255;
        acc = fmaf(ce[k*Dn+dp], xs[((l-l0)+k)*Dn+dp], acc);
      }
      #pragma unroll
      for (int off=16; off; off>>=1) acc += __shfl_xor_sync(0xffffffffu, acc, off);
      if (lane==0){
        int var = (l==0)?0:((l==Ln-1)?2:1);
        float h = silu_f(acc + g_beff[(which*8+o)*3+var]);
        h = (l < plen) ? h : 0.f;
        float* dst = which ? g_hc : g_hw;
        dst[((size_t)b*Ln+l)*8 + o] = h;
      }
    }
  } else {
    float* A = sbuf;
    int idx = bi-400;
    int c = idx%13, q = (idx/13)&3, b = idx/52;
    int l0 = c*16, nl = min(16, Ln - l0);
    for (int i=tid; i<16*Dn; i+=256){
      int li = i>>8, dp = i&255;
      A[dp*16+li] = (li < nl) ? g_phonT[((size_t)b*Ln + l0+li)*Dn + dp] : 0.f;
    }
    __syncthreads();
    ull acc[8];
    #pragma unroll
    for (int j=0;j<8;j++) acc[j]=pack2(0.f,0.f);
    const float* LwQ = Lw + (size_t)q*Dn*Dn;
    for (int dd=0; dd<Dn; dd++){
      float lw = LwQ[dd*Dn + tid];
      ull lw2 = pack2(lw, lw);
      const ulonglong2* ap = (const ulonglong2*)(A + dd*16);
      #pragma unroll
      for (int j=0;j<4;j++){
        ulonglong2 av = ap[j];
        acc[2*j]   = fma2(av.x, lw2, acc[2*j]);
        acc[2*j+1] = fma2(av.y, lw2, acc[2*j+1]);
      }
    }
    // write P'T bf16 hi/lo: [b][d=tid][k = q*200 + (l0+i)]  (vectorized 16B stores)
    __align__(16) unsigned short h16[16];
    __align__(16) unsigned short l16[16];
    #pragma unroll
    for (int j=0;j<8;j++){
      float a,b2; unpack2(acc[j], a, b2);
      bf_split(a,  h16[2*j],   l16[2*j]);
      bf_split(b2, h16[2*j+1], l16[2*j+1]);
    }
    size_t base = ((size_t)b*Dn + tid)*KW + (size_t)q*200 + l0;
    *(uint4*)&g_pbf_hi[base] = ((uint4*)h16)[0];
    *(uint4*)&g_pbf_lo[base] = ((uint4*)l16)[0];
    if (nl == 16){
      *(uint4*)&g_pbf_hi[base+8] = ((uint4*)h16)[1];
      *(uint4*)&g_pbf_lo[base+8] = ((uint4*)l16)[1];
    }
  }
}

// ================= K_MAIN: phases 1-2 + W' export =================
// dyn smem (floats): w_s 0..12800 | sk 12800..13000 | bc 13000..13400 | wc 13400..13528 | prm 13528..13594
#define SMEM_BYTES 54376

__global__ __launch_bounds__(256,3) void k_main(
  const float* __restrict__ dur,
  const float* __restrict__ Mw, const float* __restrict__ mbw,
  const float* __restrict__ Mc, const float* __restrict__ mbc,
  float* __restrict__ out)
{
  extern __shared__ float sm[];
  float* w_s  = sm;
  float* sk_s = sm + 12800;
  float* bc_s = sm + 13000;
  float* wc_s = sm + 13400;
  float* prm  = sm + 13528;

  int b = blockIdx.y;
  int t0 = blockIdx.x * TT;
  int tid = threadIdx.x;
  int plen = g_plen[b], flen = g_flen[b];
  bool active = (t0 < flen);

  if (active){
    if (tid < 40)      prm[tid] = Mw[tid];
    else if (tid < 44) prm[tid] = mbw[tid-40];
    else if (tid < 64) prm[tid] = Mc[tid-44];
    else if (tid < 66) prm[tid] = mbc[tid-64];
    __syncthreads();

    // ---- phase 1 ----
    if (tid < Ln){
      int l = tid;
      float dv = dur[b*Ln + l];
      float sk = g_sk[b*Ln + l];
      sk_s[l] = sk;
      const float* hwp = g_hw + ((size_t)b*Ln+l)*8;
      const float* hcp = g_hc + ((size_t)b*Ln+l)*8;
      float bw[4], bc[2];
      #pragma unroll
      for (int q=0;q<4;q++){
        float a = prm[40+q] + dv*prm[4+q];
        #pragma unroll
        for (int j=0;j<8;j++) a = fmaf(hwp[j], prm[(2+j)*4+q], a);
        bw[q]=a;
      }
      #pragma unroll
      for (int p=0;p<2;p++){
        float a = prm[64+p] + dv*prm[46+p];
        #pragma unroll
        for (int j=0;j<8;j++) a = fmaf(hcp[j], prm[44+(2+j)*2+p], a);
        bc[p]=a;
      }
      bc_s[2*l]   = bc[0];
      bc_s[2*l+1] = bc[1];
      bool lv = l < plen;
      float4* wl = (float4*)(w_s + l*64);
      #pragma unroll
      for (int t=0;t<TT;t++){
        int tt = t0+t;
        float4 av = {0.f,0.f,0.f,0.f};
        if (lv && tt < flen){
          float S = (float)(tt+1) - sk;
          av.x = silu_f(fmaf(S, prm[0], bw[0]));
          av.y = silu_f(fmaf(S, prm[1], bw[1]));
          av.z = silu_f(fmaf(S, prm[2], bw[2]));
          av.w = silu_f(fmaf(S, prm[3], bw[3]));
        }
        wl[t] = av;
      }
    }
    __syncthreads();

    // ---- phase 2: softmax + f32 w out + wc reduce ----
    {
      int wp = tid>>5, lane = tid&31;
      float mc0 = prm[44], mc1 = prm[45];
      const size_t qs = (size_t)Tn*Ln;
      for (int t=wp; t<TT; t+=8){
        int tt = t0+t;
        if (tt >= Tn) continue;
        size_t wb = OFF_W + ((size_t)(b*4)*Tn + tt)*Ln;
        if (tt >= flen){
          for (int l=lane; l<Ln; l+=32){
            out[wb+l]=0.f; out[wb+qs+l]=0.f; out[wb+2*qs+l]=0.f; out[wb+3*qs+l]=0.f;
          }
          if (lane<8) wc_s[t*8+lane]=0.f;
          continue;
        }
        float4 wv[7];
        float m0=-3e38f,m1=-3e38f,m2=-3e38f,m3=-3e38f;
        #pragma unroll
        for (int i=0;i<7;i++){
          int l = lane + 32*i;
          if (l < plen){
            wv[i] = *(const float4*)(w_s + l*64 + t*4);
            m0=fmaxf(m0,wv[i].x); m1=fmaxf(m1,wv[i].y); m2=fmaxf(m2,wv[i].z); m3=fmaxf(m3,wv[i].w);
          }
        }
        #pragma unroll
        for (int off=16;off;off>>=1){
          m0=fmaxf(m0,__shfl_xor_sync(0xffffffffu,m0,off));
          m1=fmaxf(m1,__shfl_xor_sync(0xffffffffu,m1,off));
          m2=fmaxf(m2,__shfl_xor_sync(0xffffffffu,m2,off));
          m3=fmaxf(m3,__shfl_xor_sync(0xffffffffu,m3,off));
        }
        float s0=0.f,s1=0.f,s2=0.f,s3=0.f;
        #pragma unroll
        for (int i=0;i<7;i++){
          int l = lane + 32*i;
          if (l < plen){
            wv[i].x=__expf(wv[i].x-m0); wv[i].y=__expf(wv[i].y-m1);
            wv[i].z=__expf(wv[i].z-m2); wv[i].w=__expf(wv[i].w-m3);
            s0+=wv[i].x; s1+=wv[i].y; s2+=wv[i].z; s3+=wv[i].w;
          }
        }
        #pragma unroll
        for (int off=16;off;off>>=1){
          s0+=__shfl_xor_sync(0xffffffffu,s0,off);
          s1+=__shfl_xor_sync(0xffffffffu,s1,off);
          s2+=__shfl_xor_sync(0xffffffffu,s2,off);
          s3+=__shfl_xor_sync(0xffffffffu,s3,off);
        }
        float i0=__fdividef(1.f,s0), i1=__fdividef(1.f,s1), i2=__fdividef(1.f,s2), i3=__fdividef(1.f,s3);
        float Sb = (float)(tt+1);
        float r0=0.f,r1=0.f,r2=0.f,r3=0.f,r4=0.f,r5=0.f,r6=0.f,r7=0.f;
        #pragma unroll
        for (int i=0;i<7;i++){
          int l = lane + 32*i;
          if (l < plen){
            float4 v; v.x=wv[i].x*i0; v.y=wv[i].y*i1; v.z=wv[i].z*i2; v.w=wv[i].w*i3;
            *(float4*)(w_s + l*64 + t*4) = v;
            out[wb+l]=v.x; out[wb+qs+l]=v.y; out[wb+2*qs+l]=v.z; out[wb+3*qs+l]=v.w;
            float S = Sb - sk_s[l];
            float cx = silu_f(fmaf(S, mc0, bc_s[2*l]));
            float cy = silu_f(fmaf(S, mc1, bc_s[2*l+1]));
            r0=fmaf(v.x,cx,r0); r1=fmaf(v.x,cy,r1);
            r2=fmaf(v.y,cx,r2); r3=fmaf(v.y,cy,r3);
            r4=fmaf(v.z,cx,r4); r5=fmaf(v.z,cy,r5);
            r6=fmaf(v.w,cx,r6); r7=fmaf(v.w,cy,r7);
          } else if (l < Ln){
            out[wb+l]=0.f; out[wb+qs+l]=0.f; out[wb+2*qs+l]=0.f; out[wb+3*qs+l]=0.f;
          }
        }
        #pragma unroll
        for (int off=16;off;off>>=1){
          r0+=__shfl_xor_sync(0xffffffffu,r0,off); r1+=__shfl_xor_sync(0xffffffffu,r1,off);
          r2+=__shfl_xor_sync(0xffffffffu,r2,off); r3+=__shfl_xor_sync(0xffffffffu,r3,off);
          r4+=__shfl_xor_sync(0xffffffffu,r4,off); r5+=__shfl_xor_sync(0xffffffffu,r5,off);
          r6+=__shfl_xor_sync(0xffffffffu,r6,off); r7+=__shfl_xor_sync(0xffffffffu,r7,off);
        }
        if (lane==0){
          wc_s[t*8+0]=r0; wc_s[t*8+1]=r1; wc_s[t*8+2]=r2; wc_s[t*8+3]=r3;
          wc_s[t*8+4]=r4; wc_s[t*8+5]=r5; wc_s[t*8+6]=r6; wc_s[t*8+7]=r7;
        }
      }
    }
    __syncthreads();

    // ---- phase 2.5: export W' rows, k = q*200+l (lane-coalesced) ----
    for (int t=0;t<TT;t++){
      int tt = t0+t;
      if (tt >= Tn) break;
      size_t rw = ((size_t)(b*1024)+tt)*KW;
      if (tid < Ln){
        float4 v = *(const float4*)(w_s + tid*64 + t*4);
        unsigned short h,l;
        bf_split(v.x,h,l); g_wbf_hi[rw+tid]=h;     g_wbf_lo[rw+tid]=l;
        bf_split(v.y,h,l); g_wbf_hi[rw+200+tid]=h; g_wbf_lo[rw+200+tid]=l;
        bf_split(v.z,h,l); g_wbf_hi[rw+400+tid]=h; g_wbf_lo[rw+400+tid]=l;
        bf_split(v.w,h,l); g_wbf_hi[rw+600+tid]=h; g_wbf_lo[rw+600+tid]=l;
      } else if (tid < 202){
        int base = (tid-200)*4;
        #pragma unroll
        for (int j=0;j<4;j++){
          unsigned short h,l; bf_split(wc_s[t*8+base+j],h,l);
          g_wbf_hi[rw+800+base+j]=h; g_wbf_lo[rw+800+base+j]=l;
        }
      } else if (tid == 202){
        bool live = tt < flen;
        unsigned short h,l; bf_split(live?1.f:0.f,h,l);
        g_wbf_hi[rw+808]=h; g_wbf_lo[rw+808]=l;
        for (int k=809;k<812;k++){ g_wbf_hi[rw+k]=0; g_wbf_lo[rw+k]=0; }
      } else if (tid < 208){
        int k0 = 812 + (tid-203)*4;
        #pragma unroll
        for (int j=0;j<4;j++){ g_wbf_hi[rw+k0+j]=0; g_wbf_lo[rw+k0+j]=0; }
      }
    }
  } else {
    // inactive: zero w planes + zero W' rows
    int wp = tid>>5, lane = tid&31;
    const size_t qs = (size_t)Tn*Ln;
    for (int t=wp; t<TT; t+=8){
      int tt = t0+t;
      if (tt >= Tn) continue;
      size_t wb = OFF_W + ((size_t)(b*4)*Tn + tt)*Ln;
      for (int l=lane; l<Ln; l+=32){
        out[wb+l]=0.f; out[wb+qs+l]=0.f; out[wb+2*qs+l]=0.f; out[wb+3*qs+l]=0.f;
      }
    }
    for (int t=0;t<TT;t++){
      int tt = t0+t;
      if (tt >= Tn) break;
      size_t rw = ((size_t)(b*1024)+tt)*KW;
      for (int k=tid;k<KW;k+=256){ g_wbf_hi[rw+k]=0; g_wbf_lo[rw+k]=0; }
    }
  }
}

// ================= K_COMB: Y = W' @ P'  (cp.async double-buffered, hi/lo x3) =================
// stage (64 k): A_hi 16K | A_lo 16K | B_hi 16K | B_lo 16K = 64KB; x2 stages = 128KB
#define KC_ST 65536
#define KC_SMEM 131072

__global__ __launch_bounds__(256,1) void k_comb(){
  extern __shared__ float smf[];
  char* smc = (char*)smf;
  uint32_t sb = smem_u32(smc);
  int tid = threadIdx.x, wid = tid>>5, lane = tid&31;
  int mtile = blockIdx.x, ntile = blockIdx.y, b = blockIdx.z;

  // dead fast path: whole m-tile past flen -> Y = 0
  if (mtile*128 >= g_flen[b]){
    uint4 z; z.x=0u; z.y=0u; z.z=0u; z.w=0u;
    #pragma unroll
    for (int i=0;i<8;i++){
      int lin = i*256 + tid;
      int r = lin>>4, ch = lin&15;
      int t = mtile*128 + r;
      if (t < Tn){
        size_t row = (size_t)b*Tn + t;
        ((uint4*)(g_yhi + row*Dn + ntile*128))[ch] = z;
        ((uint4*)(g_ylo + row*Dn + ntile*128))[ch] = z;
      }
    }
    return;
  }

  float acc[2][8][4];
  #pragma unroll
  for (int mt=0;mt<2;mt++)
    #pragma unroll
    for (int ng=0;ng<8;ng++){ acc[mt][ng][0]=0.f; acc[mt][ng][1]=0.f; acc[mt][ng][2]=0.f; acc[mt][ng][3]=0.f; }

  int m0 = (wid&3)*32, n0 = (wid>>2)*64;

  const uint4* gwh = (const uint4*)(g_wbf_hi + ((size_t)(b*1024) + (size_t)mtile*128)*KW);
  const uint4* gwl = (const uint4*)(g_wbf_lo + ((size_t)(b*1024) + (size_t)mtile*128)*KW);
  const uint4* gph = (const uint4*)(g_pbf_hi + ((size_t)(b*Dn) + (size_t)ntile*128)*KW);
  const uint4* gpl = (const uint4*)(g_pbf_lo + ((size_t)(b*Dn) + (size_t)ntile*128)*KW);
  const int rs = KW/8;   // 104

  int srow = tid>>3, sch = tid&7;
  uint32_t soff = (uint32_t)(srow*128 + ((sch ^ (srow&7))<<4));

  // issue stage c into buffer s
  #define KC_ISSUE(c, s) do{                                              \
    uint32_t base_ = sb + (uint32_t)(s)*KC_ST;                            \
    _Pragma("unroll")                                                     \
    for (int i_=0;i_<4;i_++){                                             \
      uint32_t off_ = soff + (uint32_t)(i_*32*128);                       \
      size_t g_ = (size_t)(srow + i_*32)*rs + (c)*8 + sch;                \
      CP16(base_ + off_,          gwh + g_);                              \
      CP16(base_ + 16384 + off_,  gwl + g_);                              \
      CP16(base_ + 32768 + off_,  gph + g_);                              \
      CP16(base_ + 49152 + off_,  gpl + g_);                              \
    }                                                                     \
    CP_COMMIT();                                                          \
  }while(0)

  KC_ISSUE(0, 0);
  for (int c=0;c<13;c++){
    int s = c & 1;
    if (c+1 < 13){ KC_ISSUE(c+1, s^1); CP_WAIT1(); }
    else         { CP_WAIT0(); }
    __syncthreads();
    uint32_t stb = sb + (uint32_t)s*KC_ST;
    #pragma unroll
    for (int kk=0;kk<4;kk++){
      uint32_t aH[2][4], aL[2][4];
      #pragma unroll
      for (int mt=0;mt<2;mt++){
        int arow = m0 + mt*16 + (lane&15);
        uint32_t aoff = (uint32_t)(arow*128 + (((kk*2 + (lane>>4)) ^ (arow&7))<<4));
        ldsm4(aH[mt][0],aH[mt][1],aH[mt][2],aH[mt][3], stb + aoff);
        ldsm4(aL[mt][0],aL[mt][1],aL[mt][2],aL[mt][3], stb + 16384 + aoff);
      }
      #pragma unroll
      for (int ng=0;ng<4;ng++){
        int nrow = n0 + ng*16 + ((lane>>4)<<3) + (lane&7);
        uint32_t boff = (uint32_t)(nrow*128 + (((kk*2 + ((lane>>3)&1)) ^ (nrow&7))<<4));
        uint32_t bh0,bh1,bh2,bh3, bl0,bl1,bl2,bl3;
        ldsm4(bh0,bh1,bh2,bh3, stb + 32768 + boff);
        ldsm4(bl0,bl1,bl2,bl3, stb + 49152 + boff);
        #pragma unroll
        for (int mt=0;mt<2;mt++){
          mma16816(acc[mt][2*ng],   aH[mt], bh0, bh1);
          mma16816(acc[mt][2*ng],   aL[mt], bh0, bh1);
          mma16816(acc[mt][2*ng],   aH[mt], bl0, bl1);
          mma16816(acc[mt][2*ng+1], aH[mt], bh2, bh3);
          mma16816(acc[mt][2*ng+1], aL[mt], bh2, bh3);
          mma16816(acc[mt][2*ng+1], aH[mt], bl2, bl3);
        }
      }
    }
    __syncthreads();
  }

  // epilogue: split f32 -> bf16 hi/lo, store to g_yhi/g_ylo
  #pragma unroll
  for (int mt=0;mt<2;mt++){
    #pragma unroll
    for (int ng=0;ng<8;ng++){
      int d = ntile*128 + n0 + ng*8 + (lane&3)*2;
      #pragma unroll
      for (int half=0;half<2;half++){
        int t = mtile*128 + m0 + mt*16 + (lane>>2) + half*8;
        if (t < Tn){
          size_t row = (size_t)b*Tn + t;
          unsigned short h0,l0,h1,l1;
          bf_split(acc[mt][ng][half*2+0], h0, l0);
          bf_split(acc[mt][ng][half*2+1], h1, l1);
          ushort2 hh; hh.x=h0; hh.y=h1;
          ushort2 ll; ll.x=l0; ll.y=l1;
          *(ushort2*)&g_yhi[row*Dn + d] = hh;
          *(ushort2*)&g_ylo[row*Dn + d] = ll;
        }
      }
    }
  }
}

// ================= K_OUT: out = y @ Wo + bo  (cp.async double-buffered, 4 chunks) =================
// stage (64 k): A_hi 16K | A_lo 16K | B_hi 8K | B_lo 8K = 48KB; x2 = 96KB
#define KO_ST 49152
#define KO_SMEM 98304

__global__ __launch_bounds__(256,2) void k_out(const float* __restrict__ bo,
                                               float* __restrict__ out){
  extern __shared__ float smf[];
  char* smc = (char*)smf;
  uint32_t sb = smem_u32(smc);
  int tid = threadIdx.x, wid = tid>>5, lane = tid&31;
  int mtile = blockIdx.x, ntile = blockIdx.y;

  // dead fast path
  {
    int mstart = mtile*128;
    int b0 = mstart/Tn, b1 = (mstart+127)/Tn;
    int t_start = mstart - b0*Tn;
    bool dead = (t_start >= g_flen[b0]) && (b1==b0 || g_flen[b1]<=0);
    if (dead){
      int r = tid & 127;
      int m = mtile*128 + r;
      int b = m/Tn, t = m - b*Tn;
      size_t plane = (ntile<4)?OFF_MEAN:OFF_LOG;
      int colbase = ntile*64 - ((ntile>=4)?256:0);
      const float* bop = bo + ntile*64;
      for (int i = tid>>7; i<64; i+=2)
        out[plane + ((size_t)(b*Dn + colbase + i))*Tn + t] = bop[i];
      return;
    }
  }

  float acc[2][4][4];
  #pragma unroll
  for (int mt=0;mt<2;mt++)
    #pragma unroll
    for (int ng=0;ng<4;ng++){ acc[mt][ng][0]=0.f; acc[mt][ng][1]=0.f; acc[mt][ng][2]=0.f; acc[mt][ng][3]=0.f; }

  int m0 = (wid&3)*32, n0 = (wid>>2)*32;

  const uint4* aH_g = (const uint4*)(g_yhi + (size_t)(mtile*128)*Dn);
  const uint4* aL_g = (const uint4*)(g_ylo + (size_t)(mtile*128)*Dn);
  const uint4* bH_g = (const uint4*)(g_woThi + (size_t)(ntile*64)*256);
  const uint4* bL_g = (const uint4*)(g_woTlo + (size_t)(ntile*64)*256);

  int srow = tid>>3, sch = tid&7;
  uint32_t soff = (uint32_t)(srow*128 + ((sch ^ (srow&7))<<4));

  #define KO_ISSUE(c, s) do{                                              \
    uint32_t base_ = sb + (uint32_t)(s)*KO_ST;                            \
    _Pragma("unroll")                                                     \
    for (int i_=0;i_<4;i_++){                                             \
      uint32_t off_ = soff + (uint32_t)(i_*32*128);                       \
      size_t g_ = (size_t)(srow + i_*32)*32 + (c)*8 + sch;                \
      CP16(base_ + off_,         aH_g + g_);                              \
      CP16(base_ + 16384 + off_, aL_g + g_);                              \
    }                                                                     \
    _Pragma("unroll")                                                     \
    for (int i_=0;i_<2;i_++){                                             \
      uint32_t off_ = soff + (uint32_t)(i_*32*128);                       \
      size_t g_ = (size_t)(srow + i_*32)*32 + (c)*8 + sch;                \
      CP16(base_ + 32768 + off_, bH_g + g_);                              \
      CP16(base_ + 40960 + off_, bL_g + g_);                              \
    }                                                                     \
    CP_COMMIT();                                                          \
  }while(0)

  KO_ISSUE(0, 0);
  for (int c=0;c<4;c++){
    int s = c & 1;
    if (c+1 < 4){ KO_ISSUE(c+1, s^1); CP_WAIT1(); }
    else        { CP_WAIT0(); }
    __syncthreads();
    uint32_t stb = sb + (uint32_t)s*KO_ST;
    #pragma unroll
    for (int kk=0;kk<4;kk++){
      uint32_t aH[2][4], aL[2][4];
      #pragma unroll
      for (int mt=0;mt<2;mt++){
        int arow = m0 + mt*16 + (lane&15);
        uint32_t aoff = (uint32_t)(arow*128 + (((kk*2 + (lane>>4)) ^ (arow&7))<<4));
        ldsm4(aH[mt][0],aH[mt][1],aH[mt][2],aH[mt][3], stb + aoff);
        ldsm4(aL[mt][0],aL[mt][1],aL[mt][2],aL[mt][3], stb + 16384 + aoff);
      }
      #pragma unroll
      for (int g2=0;g2<2;g2++){
        int nrow = n0 + g2*16 + ((lane>>4)<<3) + (lane&7);
        uint32_t boff = (uint32_t)(nrow*128 + (((kk*2 + ((lane>>3)&1)) ^ (nrow&7))<<4));
        uint32_t bh0,bh1,bh2,bh3, bl0,bl1,bl2,bl3;
        ldsm4(bh0,bh1,bh2,bh3, stb + 32768 + boff);
        ldsm4(bl0,bl1,bl2,bl3, stb + 40960 + boff);
        #pragma unroll
        for (int mt=0;mt<2;mt++){
          mma16816(acc[mt][g2*2],   aH[mt], bh0, bh1);
          mma16816(acc[mt][g2*2],   aL[mt], bh0, bh1);
          mma16816(acc[mt][g2*2],   aH[mt], bl0, bl1);
          mma16816(acc[mt][g2*2+1], aH[mt], bh2, bh3);
          mma16816(acc[mt][g2*2+1], aL[mt], bh2, bh3);
          mma16816(acc[mt][g2*2+1], aH[mt], bl2, bl3);
        }
      }
    }
    __syncthreads();
  }

  // epilogue
  {
    size_t plane = (ntile < 4) ? OFF_MEAN : OFF_LOG;
    int colbase = ntile*64 - ((ntile>=4)?256:0);
    const float* bop = bo + ntile*64;
    #pragma unroll
    for (int mt=0;mt<2;mt++){
      #pragma unroll
      for (int ng=0;ng<4;ng++){
        int cin = n0 + ng*8 + 2*(lane&3);
        float b0v = bop[cin], b1v = bop[cin+1];
        #pragma unroll
        for (int half=0;half<2;half++){
          int m_g = mtile*128 + m0 + mt*16 + (lane>>2) + half*8;
          int b = m_g / Tn;
          int t = m_g - b*Tn;
          size_t base = plane + ((size_t)(b*Dn + colbase + cin))*Tn + t;
          out[base]      = acc[mt][ng][half*2+0] + b0v;
          out[base + Tn] = acc[mt][ng][half*2+1] + b1v;
        }
      }
    }
  }
}

// ---------------- launcher ----------------
extern "C" void kernel_launch(void* const* d_in, const int* in_sizes, int n_in,
                              void* d_out, int out_size){
  (void)in_sizes; (void)n_in; (void)out_size;
  const float* dur = (const float*)d_in[0];
  const float* phon= (const float*)d_in[1];
  const float* Wpw = (const float*)d_in[3];
  const float* bpw = (const float*)d_in[4];
  const float* Cw  = (const float*)d_in[5];
  const float* cbw = (const float*)d_in[6];
  const float* Mw  = (const float*)d_in[7];
  const float* mbw = (const float*)d_in[8];
  const float* Lw  = (const float*)d_in[9];
  const float* lbw = (const float*)d_in[10];
  const float* Wpc = (const float*)d_in[11];
  const float* bpc = (const float*)d_in[12];
  const float* Cc  = (const float*)d_in[13];
  const float* cbc = (const float*)d_in[14];
  const float* Mc  = (const float*)d_in[15];
  const float* mbc = (const float*)d_in[16];
  const float* Lcm = (const float*)d_in[17];
  const float* lbc = (const float*)d_in[18];
  const float* Wo  = (const float*)d_in[19];
  const float* bo  = (const float*)d_in[20];
  float* out = (float*)d_out;

  cudaFuncSetAttribute((const void*)k_main, cudaFuncAttributeMaxDynamicSharedMemorySize,
                       SMEM_BYTES);
  cudaFuncSetAttribute((const void*)k_comb, cudaFuncAttributeMaxDynamicSharedMemorySize,
                       KC_SMEM);
  cudaFuncSetAttribute((const void*)k_out, cudaFuncAttributeMaxDynamicSharedMemorySize,
                       KO_SMEM);

  k_pre<<<980,256>>>(dur, phon, Cw, Wpw, Cc, Wpc, bpw, cbw, bpc, cbc, Wo, Lcm, lbw, lbc, out);
  k_mid<<<1232,256>>>(Lw);
  k_main<<<dim3(NB,Bn),256,SMEM_BYTES>>>(dur,Mw,mbw,Mc,mbc,out);
  k_comb<<<dim3(8,2,Bn),256,KC_SMEM>>>();
  k_out<<<dim3(125,8),256,KO_SMEM>>>(bo,out);
}

// round 13
// speedup vs baseline: 2.2155x; 1.0729x over previous
#include <cuda_runtime.h>
#include <cuda_bf16.h>
#include <cstdint>
#include <math.h>

typedef unsigned long long ull;

#define Bn 16
#define Dn 256
#define Ln 200
#define Tn 1000
#define TT 16
#define NB 63            // ceil(1000/16)
#define KW 832           // padded K: [q*200+l] (800) | wc (8) | bias (1) | pad (23)

#define OFF_MEAN ((size_t)0)
#define OFF_LOG  ((size_t)4096000)
#define OFF_FM   ((size_t)8192000)
#define OFF_FL   ((size_t)8208000)
#define OFF_W    ((size_t)8208016)

// ---------------- device scratch ----------------
__device__ float g_sk[Bn*Ln];
__device__ int   g_plen[Bn];
__device__ int   g_flen[Bn];
__device__ float g_phonT[(size_t)Bn*Ln*Dn];          // [b][l][d]
__device__ float g_hw[(size_t)Bn*Ln*8];
__device__ float g_hc[(size_t)Bn*Ln*8];
__device__ float g_Ceff[2*8*3*Dn];
__device__ float g_beff[2*8*3];
__device__ unsigned short g_wbf_hi[(size_t)Bn*1024*KW];  // W' [b][t(1024)][k]
__device__ unsigned short g_wbf_lo[(size_t)Bn*1024*KW];
__device__ unsigned short g_pbf_hi[(size_t)Bn*Dn*KW];    // P'T [b][d][k]
__device__ unsigned short g_pbf_lo[(size_t)Bn*Dn*KW];
__device__ unsigned short g_yhi[(size_t)Bn*Tn*Dn];   // bf16 hi of y, [m=b*1000+t][d]
__device__ unsigned short g_ylo[(size_t)Bn*Tn*Dn];   // bf16 lo
__device__ unsigned short g_woThi[512*256];          // bf16 WoT [n][k]
__device__ unsigned short g_woTlo[512*256];

__device__ __forceinline__ float silu_f(float x){ return __fdividef(x, 1.f + __expf(-x)); }

__device__ __forceinline__ ull pack2(float a, float b){
  ull r; asm("mov.b64 %0,{%1,%2};" : "=l"(r) : "f"(a), "f"(b)); return r;
}
__device__ __forceinline__ ull fma2(ull a, ull b, ull c){
  ull d; asm("fma.rn.f32x2 %0,%1,%2,%3;" : "=l"(d) : "l"(a), "l"(b), "l"(c)); return d;
}
__device__ __forceinline__ void unpack2(ull v, float& a, float& b){
  asm("mov.b64 {%0,%1},%2;" : "=f"(a), "=f"(b) : "l"(v));
}
__device__ __forceinline__ uint32_t smem_u32(const void* p){
  uint32_t a;
  asm("{ .reg .u64 t; cvta.to.shared.u64 t, %1; cvt.u32.u64 %0, t; }" : "=r"(a) : "l"(p));
  return a;
}
__device__ __forceinline__ void bf_split(float v, unsigned short& h, unsigned short& l){
  __nv_bfloat16 hb = __float2bfloat16(v);
  h = __bfloat16_as_ushort(hb);
  l = __bfloat16_as_ushort(__float2bfloat16(v - __bfloat162float(hb)));
}

// ---------------- mma.sync / cp.async helpers ----------------
__device__ __forceinline__ void ldsm4(uint32_t& r0, uint32_t& r1, uint32_t& r2, uint32_t& r3,
                                      uint32_t addr){
  asm volatile("ldmatrix.sync.aligned.m8n8.x4.shared.b16 {%0,%1,%2,%3}, [%4];"
    : "=r"(r0), "=r"(r1), "=r"(r2), "=r"(r3) : "r"(addr));
}
__device__ __forceinline__ void mma16816(float* d, const uint32_t* a, uint32_t b0, uint32_t b1){
  asm volatile("mma.sync.aligned.m16n8k16.row.col.f32.bf16.bf16.f32 "
    "{%0,%1,%2,%3},{%4,%5,%6,%7},{%8,%9},{%0,%1,%2,%3};"
    : "+f"(d[0]), "+f"(d[1]), "+f"(d[2]), "+f"(d[3])
    : "r"(a[0]), "r"(a[1]), "r"(a[2]), "r"(a[3]), "r"(b0), "r"(b1));
}
#define CP16(dst,src) asm volatile("cp.async.cg.shared.global [%0],[%1],16;" :: "r"(dst), "l"(src) : "memory")
#define CP_COMMIT()   asm volatile("cp.async.commit_group;" ::: "memory")
#define CP_WAIT1()    asm volatile("cp.async.wait_group 1;" ::: "memory")
#define CP_WAIT0()    asm volatile("cp.async.wait_group 0;" ::: "memory")

// ================= K_PRE =================
// 0..895 transpose | 896..943 ceff | 944..945 beff | 946..961 setup | 962..963 WoT | 964..979 P'-extra
__global__ void k_pre(const float* __restrict__ dur, const float* __restrict__ phon,
                      const float* __restrict__ Cw, const float* __restrict__ Wpw,
                      const float* __restrict__ Cc, const float* __restrict__ Wpc,
                      const float* __restrict__ bpw, const float* __restrict__ cbw,
                      const float* __restrict__ bpc, const float* __restrict__ cbc,
                      const float* __restrict__ Wo,
                      const float* __restrict__ Lcm, const float* __restrict__ lbw,
                      const float* __restrict__ lbc,
                      float* __restrict__ out){
  __shared__ float tile[32][33];
  __shared__ float cs[Dn];
  __shared__ int sfl;
  int bi = blockIdx.x, tid = threadIdx.x;

  if (bi < 896){
    int l0 = (bi%7)*32, d0 = ((bi/7)%8)*32, b = bi/56;
    int tx = tid&31, ty = tid>>5;
    #pragma unroll
    for (int r=0;r<4;r++){
      int dy = d0+ty+8*r, lx = l0+tx;
      tile[ty+8*r][tx] = (lx<Ln) ? phon[((size_t)b*Dn+dy)*Ln+lx] : 0.f;
    }
    __syncthreads();
    #pragma unroll
    for (int r=0;r<4;r++){
      int ly = l0+ty+8*r, dx = d0+tx;
      if (ly<Ln) g_phonT[((size_t)b*Ln+ly)*Dn+dx] = tile[tx][ty+8*r];
    }
  } else if (bi < 944){
    int idx = bi-896;
    int o = idx&7, k = (idx>>3)%3, which = idx/24;
    const float* C = which? Cc : Cw;
    const float* W = which? Wpc : Wpw;
    cs[tid] = C[(o*Dn+tid)*3+k];
    __syncthreads();
    float acc=0.f;
    #pragma unroll 8
    for (int d=0; d<Dn; d++)
      acc = fmaf(cs[d], W[d*Dn+tid], acc);
    g_Ceff[((which*8+o)*3+k)*Dn + tid] = acc;
  } else if (bi < 946){
    int which = bi-944;
    const float* C = which? Cc: Cw; const float* bp = which? bpc : bpw; const float* cb = which? cbc : cbw;
    int wp = tid>>5, lane = tid&31;
    for (int pr=wp; pr<24; pr+=8){
      int o = pr/3, var = pr%3;
      int k0 = (var==0)?1:0, k1 = (var==2)?1:2;
      float acc = 0.f;
      #pragma unroll
      for (int i=0;i<8;i++){
        int d = lane + 32*i;
        float bv = bp[d];
        for (int k=k0;k<=k1;k++) acc = fmaf(C[(o*Dn+d)*3+k], bv, acc);
      }
      #pragma unroll
      for (int off=16;off;off>>=1) acc += __shfl_xor_sync(0xffffffffu, acc, off);
      if (lane==0) g_beff[(which*8+o)*3+var] = acc + cb[o];
    }
  } else if (bi < 962){
    int b = bi-946;
    float* s = &tile[0][0];
    if (tid < Ln) s[tid] = dur[b*Ln+tid];
    __syncthreads();
    if (tid == 0){
      float acc = 0.f; int plen = 0;
      for (int l=0;l<Ln;l++){ g_sk[b*Ln+l]=acc; float d=s[l]; acc+=d; if (d>0.f) plen=l+1; }
      g_plen[b]=plen;
      int fl = (int)rintf(acc); fl = fl<0?0:(fl>Tn?Tn:fl);
      g_flen[b]=fl; sfl=fl;
      out[OFF_FL + b] = (float)fl;
    }
    __syncthreads();
    int fl = sfl;
    for (int t=tid;t<Tn;t+=256) out[OFF_FM + (size_t)b*Tn + t] = (t<fl)?1.f:0.f;
  } else if (bi < 964){
    // WoT hi/lo split
    int n = (bi-962)*256 + tid;
    for (int kc=0;kc<32;kc++){
      __align__(16) unsigned short h8[8];
      __align__(16) unsigned short l8[8];
      #pragma unroll
      for (int j=0;j<8;j++){
        float w = Wo[(size_t)(kc*8+j)*512 + n];
        bf_split(w, h8[j], l8[j]);
      }
      *(uint4*)&g_woThi[n*256 + kc*8] = *(uint4*)h8;
      *(uint4*)&g_woTlo[n*256 + kc*8] = *(uint4*)l8;
    }
  } else {
    // P' extra rows: k=800..807 = Lc, k=808 = lbw+lbc, 809..831 = 0
    int b = bi-964;
    size_t base = ((size_t)b*Dn + tid)*KW;
    #pragma unroll
    for (int i=0;i<8;i++){
      unsigned short h,l; bf_split(Lcm[i*Dn+tid], h, l);
      g_pbf_hi[base+800+i]=h; g_pbf_lo[base+800+i]=l;
    }
    {
      unsigned short h,l; bf_split(lbw[tid]+lbc[tid], h, l);
      g_pbf_hi[base+808]=h; g_pbf_lo[base+808]=l;
    }
    for (int k=809;k<KW;k++){ g_pbf_hi[base+k]=0; g_pbf_lo[base+k]=0; }
  }
}

// ================= K_MID: conv (0..399) + P' GEMM (400..1231) =================
__global__ void k_mid(const float* __restrict__ Lw){
  __shared__ float sbuf[4096];
  int bi = blockIdx.x, tid = threadIdx.x;

  if (bi < 400){
    float* xs = sbuf;
    int b = bi/25, l0 = (bi%25)*8;
    for (int i=tid; i<10*Dn; i+=256){
      int r = i>>8, dp = i&255, col = l0-1+r;
      xs[r*Dn+dp] = (col>=0 && col<Ln) ? g_phonT[((size_t)b*Ln+col)*Dn+dp] : 0.f;
    }
    __syncthreads();
    int warp = tid>>5, lane = tid&31;
    int l = l0 + warp;
    int plen = g_plen[b];
    for (int idx=0; idx<16; idx++){
      int which = idx>>3, o = idx&7;
      const float* ce = g_Ceff + ((which*8+o)*3)*Dn;
      float acc = 0.f;
      for (int i=lane; i<3*Dn; i+=32){
        int k = i>>8, dp = i&255;
        acc = fmaf(ce[k*Dn+dp], xs[((l-l0)+k)*Dn+dp], acc);
      }
      #pragma unroll
      for (int off=16; off; off>>=1) acc += __shfl_xor_sync(0xffffffffu, acc, off);
      if (lane==0){
        int var = (l==0)?0:((l==Ln-1)?2:1);
        float h = silu_f(acc + g_beff[(which*8+o)*3+var]);
        h = (l < plen) ? h : 0.f;
        float* dst = which ? g_hc : g_hw;
        dst[((size_t)b*Ln+l)*8 + o] = h;
      }
    }
  } else {
    float* A = sbuf;
    int idx = bi-400;
    int c = idx%13, q = (idx/13)&3, b = idx/52;
    int l0 = c*16, nl = min(16, Ln - l0);
    for (int i=tid; i<16*Dn; i+=256){
      int li = i>>8, dp = i&255;
      A[dp*16+li] = (li < nl) ? g_phonT[((size_t)b*Ln + l0+li)*Dn + dp] : 0.f;
    }
    __syncthreads();
    ull acc[8];
    #pragma unroll
    for (int j=0;j<8;j++) acc[j]=pack2(0.f,0.f);
    const float* LwQ = Lw + (size_t)q*Dn*Dn;
    for (int dd=0; dd<Dn; dd++){
      float lw = LwQ[dd*Dn + tid];
      ull lw2 = pack2(lw, lw);
      const ulonglong2* ap = (const ulonglong2*)(A + dd*16);
      #pragma unroll
      for (int j=0;j<4;j++){
        ulonglong2 av = ap[j];
        acc[2*j]   = fma2(av.x, lw2, acc[2*j]);
        acc[2*j+1] = fma2(av.y, lw2, acc[2*j+1]);
      }
    }
    // write P'T bf16 hi/lo: [b][d=tid][k = q*200 + (l0+i)]  (vectorized 16B stores)
    __align__(16) unsigned short h16[16];
    __align__(16) unsigned short l16[16];
    #pragma unroll
    for (int j=0;j<8;j++){
      float a,b2; unpack2(acc[j], a, b2);
      bf_split(a,  h16[2*j],   l16[2*j]);
      bf_split(b2, h16[2*j+1], l16[2*j+1]);
    }
    size_t base = ((size_t)b*Dn + tid)*KW + (size_t)q*200 + l0;
    *(uint4*)&g_pbf_hi[base] = ((uint4*)h16)[0];
    *(uint4*)&g_pbf_lo[base] = ((uint4*)l16)[0];
    if (nl == 16){
      *(uint4*)&g_pbf_hi[base+8] = ((uint4*)h16)[1];
      *(uint4*)&g_pbf_lo[base+8] = ((uint4*)l16)[1];
    }
  }
}

// ================= K_MAIN: phases 1-2 + W' export =================
// dyn smem (floats): w_s 0..12800 | sk 12800..13000 | bc 13000..13400 | wc 13400..13528 | prm 13528..13594
#define SMEM_BYTES 54376

__global__ __launch_bounds__(256,3) void k_main(
  const float* __restrict__ dur,
  const float* __restrict__ Mw, const float* __restrict__ mbw,
  const float* __restrict__ Mc, const float* __restrict__ mbc,
  float* __restrict__ out)
{
  extern __shared__ float sm[];
  float* w_s  = sm;
  float* sk_s = sm + 12800;
  float* bc_s = sm + 13000;
  float* wc_s = sm + 13400;
  float* prm  = sm + 13528;

  int b = blockIdx.y;
  int t0 = blockIdx.x * TT;
  int tid = threadIdx.x;
  int plen = g_plen[b], flen = g_flen[b];
  bool active = (t0 < flen);

  if (active){
    if (tid < 40)      prm[tid] = Mw[tid];
    else if (tid < 44) prm[tid] = mbw[tid-40];
    else if (tid < 64) prm[tid] = Mc[tid-44];
    else if (tid < 66) prm[tid] = mbc[tid-64];
    __syncthreads();

    // ---- phase 1 ----
    if (tid < Ln){
      int l = tid;
      float dv = dur[b*Ln + l];
      float sk = g_sk[b*Ln + l];
      sk_s[l] = sk;
      const float* hwp = g_hw + ((size_t)b*Ln+l)*8;
      const float* hcp = g_hc + ((size_t)b*Ln+l)*8;
      float bw[4], bc[2];
      #pragma unroll
      for (int q=0;q<4;q++){
        float a = prm[40+q] + dv*prm[4+q];
        #pragma unroll
        for (int j=0;j<8;j++) a = fmaf(hwp[j], prm[(2+j)*4+q], a);
        bw[q]=a;
      }
      #pragma unroll
      for (int p=0;p<2;p++){
        float a = prm[64+p] + dv*prm[46+p];
        #pragma unroll
        for (int j=0;j<8;j++) a = fmaf(hcp[j], prm[44+(2+j)*2+p], a);
        bc[p]=a;
      }
      bc_s[2*l]   = bc[0];
      bc_s[2*l+1] = bc[1];
      bool lv = l < plen;
      float4* wl = (float4*)(w_s + l*64);
      #pragma unroll
      for (int t=0;t<TT;t++){
        int tt = t0+t;
        float4 av = {0.f,0.f,0.f,0.f};
        if (lv && tt < flen){
          float S = (float)(tt+1) - sk;
          av.x = silu_f(fmaf(S, prm[0], bw[0]));
          av.y = silu_f(fmaf(S, prm[1], bw[1]));
          av.z = silu_f(fmaf(S, prm[2], bw[2]));
          av.w = silu_f(fmaf(S, prm[3], bw[3]));
        }
        wl[t] = av;
      }
    }
    __syncthreads();

    // ---- phase 2: softmax + f32 w out + wc reduce ----
    {
      int wp = tid>>5, lane = tid&31;
      float mc0 = prm[44], mc1 = prm[45];
      const size_t qs = (size_t)Tn*Ln;
      for (int t=wp; t<TT; t+=8){
        int tt = t0+t;
        if (tt >= Tn) continue;
        size_t wb = OFF_W + ((size_t)(b*4)*Tn + tt)*Ln;
        if (tt >= flen){
          for (int l=lane; l<Ln; l+=32){
            out[wb+l]=0.f; out[wb+qs+l]=0.f; out[wb+2*qs+l]=0.f; out[wb+3*qs+l]=0.f;
          }
          if (lane<8) wc_s[t*8+lane]=0.f;
          continue;
        }
        float4 wv[7];
        float m0=-3e38f,m1=-3e38f,m2=-3e38f,m3=-3e38f;
        #pragma unroll
        for (int i=0;i<7;i++){
          int l = lane + 32*i;
          if (l < plen){
            wv[i] = *(const float4*)(w_s + l*64 + t*4);
            m0=fmaxf(m0,wv[i].x); m1=fmaxf(m1,wv[i].y); m2=fmaxf(m2,wv[i].z); m3=fmaxf(m3,wv[i].w);
          }
        }
        #pragma unroll
        for (int off=16;off;off>>=1){
          m0=fmaxf(m0,__shfl_xor_sync(0xffffffffu,m0,off));
          m1=fmaxf(m1,__shfl_xor_sync(0xffffffffu,m1,off));
          m2=fmaxf(m2,__shfl_xor_sync(0xffffffffu,m2,off));
          m3=fmaxf(m3,__shfl_xor_sync(0xffffffffu,m3,off));
        }
        float s0=0.f,s1=0.f,s2=0.f,s3=0.f;
        #pragma unroll
        for (int i=0;i<7;i++){
          int l = lane + 32*i;
          if (l < plen){
            wv[i].x=__expf(wv[i].x-m0); wv[i].y=__expf(wv[i].y-m1);
            wv[i].z=__expf(wv[i].z-m2); wv[i].w=__expf(wv[i].w-m3);
            s0+=wv[i].x; s1+=wv[i].y; s2+=wv[i].z; s3+=wv[i].w;
          }
        }
        #pragma unroll
        for (int off=16;off;off>>=1){
          s0+=__shfl_xor_sync(0xffffffffu,s0,off);
          s1+=__shfl_xor_sync(0xffffffffu,s1,off);
          s2+=__shfl_xor_sync(0xffffffffu,s2,off);
          s3+=__shfl_xor_sync(0xffffffffu,s3,off);
        }
        float i0=__fdividef(1.f,s0), i1=__fdividef(1.f,s1), i2=__fdividef(1.f,s2), i3=__fdividef(1.f,s3);
        float Sb = (float)(tt+1);
        float r0=0.f,r1=0.f,r2=0.f,r3=0.f,r4=0.f,r5=0.f,r6=0.f,r7=0.f;
        #pragma unroll
        for (int i=0;i<7;i++){
          int l = lane + 32*i;
          if (l < plen){
            float4 v; v.x=wv[i].x*i0; v.y=wv[i].y*i1; v.z=wv[i].z*i2; v.w=wv[i].w*i3;
            *(float4*)(w_s + l*64 + t*4) = v;
            out[wb+l]=v.x; out[wb+qs+l]=v.y; out[wb+2*qs+l]=v.z; out[wb+3*qs+l]=v.w;
            float S = Sb - sk_s[l];
            float cx = silu_f(fmaf(S, mc0, bc_s[2*l]));
            float cy = silu_f(fmaf(S, mc1, bc_s[2*l+1]));
            r0=fmaf(v.x,cx,r0); r1=fmaf(v.x,cy,r1);
            r2=fmaf(v.y,cx,r2); r3=fmaf(v.y,cy,r3);
            r4=fmaf(v.z,cx,r4); r5=fmaf(v.z,cy,r5);
            r6=fmaf(v.w,cx,r6); r7=fmaf(v.w,cy,r7);
          } else if (l < Ln){
            out[wb+l]=0.f; out[wb+qs+l]=0.f; out[wb+2*qs+l]=0.f; out[wb+3*qs+l]=0.f;
          }
        }
        #pragma unroll
        for (int off=16;off;off>>=1){
          r0+=__shfl_xor_sync(0xffffffffu,r0,off); r1+=__shfl_xor_sync(0xffffffffu,r1,off);
          r2+=__shfl_xor_sync(0xffffffffu,r2,off); r3+=__shfl_xor_sync(0xffffffffu,r3,off);
          r4+=__shfl_xor_sync(0xffffffffu,r4,off); r5+=__shfl_xor_sync(0xffffffffu,r5,off);
          r6+=__shfl_xor_sync(0xffffffffu,r6,off); r7+=__shfl_xor_sync(0xffffffffu,r7,off);
        }
        if (lane==0){
          wc_s[t*8+0]=r0; wc_s[t*8+1]=r1; wc_s[t*8+2]=r2; wc_s[t*8+3]=r3;
          wc_s[t*8+4]=r4; wc_s[t*8+5]=r5; wc_s[t*8+6]=r6; wc_s[t*8+7]=r7;
        }
      }
    }
    __syncthreads();

    // ---- phase 2.5: export W' rows, k = q*200+l (lane-coalesced) ----
    for (int t=0;t<TT;t++){
      int tt = t0+t;
      if (tt >= Tn) break;
      size_t rw = ((size_t)(b*1024)+tt)*KW;
      if (tid < Ln){
        float4 v = *(const float4*)(w_s + tid*64 + t*4);
        unsigned short h,l;
        bf_split(v.x,h,l); g_wbf_hi[rw+tid]=h;     g_wbf_lo[rw+tid]=l;
        bf_split(v.y,h,l); g_wbf_hi[rw+200+tid]=h; g_wbf_lo[rw+200+tid]=l;
        bf_split(v.z,h,l); g_wbf_hi[rw+400+tid]=h; g_wbf_lo[rw+400+tid]=l;
        bf_split(v.w,h,l); g_wbf_hi[rw+600+tid]=h; g_wbf_lo[rw+600+tid]=l;
      } else if (tid < 202){
        int base = (tid-200)*4;
        #pragma unroll
        for (int j=0;j<4;j++){
          unsigned short h,l; bf_split(wc_s[t*8+base+j],h,l);
          g_wbf_hi[rw+800+base+j]=h; g_wbf_lo[rw+800+base+j]=l;
        }
      } else if (tid == 202){
        bool live = tt < flen;
        unsigned short h,l; bf_split(live?1.f:0.f,h,l);
        g_wbf_hi[rw+808]=h; g_wbf_lo[rw+808]=l;
        for (int k=809;k<812;k++){ g_wbf_hi[rw+k]=0; g_wbf_lo[rw+k]=0; }
      } else if (tid < 208){
        int k0 = 812 + (tid-203)*4;
        #pragma unroll
        for (int j=0;j<4;j++){ g_wbf_hi[rw+k0+j]=0; g_wbf_lo[rw+k0+j]=0; }
      }
    }
  } else {
    // inactive: zero w planes + zero W' rows
    int wp = tid>>5, lane = tid&31;
    const size_t qs = (size_t)Tn*Ln;
    for (int t=wp; t<TT; t+=8){
      int tt = t0+t;
      if (tt >= Tn) continue;
      size_t wb = OFF_W + ((size_t)(b*4)*Tn + tt)*Ln;
      for (int l=lane; l<Ln; l+=32){
        out[wb+l]=0.f; out[wb+qs+l]=0.f; out[wb+2*qs+l]=0.f; out[wb+3*qs+l]=0.f;
      }
    }
    for (int t=0;t<TT;t++){
      int tt = t0+t;
      if (tt >= Tn) break;
      size_t rw = ((size_t)(b*1024)+tt)*KW;
      for (int k=tid;k<KW;k+=256){ g_wbf_hi[rw+k]=0; g_wbf_lo[rw+k]=0; }
    }
  }
}

// ================= K_COMB: Y = W' @ P'  (cp.async double-buffered, M128xN64, 2 blk/SM) =================
// stage (64 k): A_hi 16K | A_lo 16K | B_hi 8K | B_lo 8K = 48KB; x2 stages = 96KB
#define KC_ST 49152
#define KC_SMEM 98304

__global__ __launch_bounds__(256,2) void k_comb(){
  extern __shared__ float smf[];
  char* smc = (char*)smf;
  uint32_t sb = smem_u32(smc);
  int tid = threadIdx.x, wid = tid>>5, lane = tid&31;
  int mtile = blockIdx.x, ntile = blockIdx.y, b = blockIdx.z;

  // dead fast path: whole m-tile past flen -> Y = 0
  if (mtile*128 >= g_flen[b]){
    uint4 z; z.x=0u; z.y=0u; z.z=0u; z.w=0u;
    #pragma unroll
    for (int i=0;i<4;i++){
      int lin = i*256 + tid;
      int r = lin>>3, ch = lin&7;
      int t = mtile*128 + r;
      if (t < Tn){
        size_t row = (size_t)b*Tn + t;
        ((uint4*)(g_yhi + row*Dn + ntile*64))[ch] = z;
        ((uint4*)(g_ylo + row*Dn + ntile*64))[ch] = z;
      }
    }
    return;
  }

  float acc[2][4][4];
  #pragma unroll
  for (int mt=0;mt<2;mt++)
    #pragma unroll
    for (int ng=0;ng<4;ng++){ acc[mt][ng][0]=0.f; acc[mt][ng][1]=0.f; acc[mt][ng][2]=0.f; acc[mt][ng][3]=0.f; }

  int m0 = (wid&3)*32, n0 = (wid>>2)*32;

  const uint4* gwh = (const uint4*)(g_wbf_hi + ((size_t)(b*1024) + (size_t)mtile*128)*KW);
  const uint4* gwl = (const uint4*)(g_wbf_lo + ((size_t)(b*1024) + (size_t)mtile*128)*KW);
  const uint4* gph = (const uint4*)(g_pbf_hi + ((size_t)(b*Dn) + (size_t)ntile*64)*KW);
  const uint4* gpl = (const uint4*)(g_pbf_lo + ((size_t)(b*Dn) + (size_t)ntile*64)*KW);
  const int rs = KW/8;   // 104

  int srow = tid>>3, sch = tid&7;
  uint32_t soff = (uint32_t)(srow*128 + ((sch ^ (srow&7))<<4));

  // issue stage c into buffer s: A 128 rows (4 iters), B 64 rows (2 iters)
  #define KC_ISSUE(c, s) do{                                              \
    uint32_t base_ = sb + (uint32_t)(s)*KC_ST;                            \
    _Pragma("unroll")                                                     \
    for (int i_=0;i_<4;i_++){                                             \
      uint32_t off_ = soff + (uint32_t)(i_*32*128);                       \
      size_t g_ = (size_t)(srow + i_*32)*rs + (c)*8 + sch;                \
      CP16(base_ + off_,          gwh + g_);                              \
      CP16(base_ + 16384 + off_,  gwl + g_);                              \
    }                                                                     \
    _Pragma("unroll")                                                     \
    for (int i_=0;i_<2;i_++){                                             \
      uint32_t off_ = soff + (uint32_t)(i_*32*128);                       \
      size_t g_ = (size_t)(srow + i_*32)*rs + (c)*8 + sch;                \
      CP16(base_ + 32768 + off_,  gph + g_);                              \
      CP16(base_ + 40960 + off_,  gpl + g_);                              \
    }                                                                     \
    CP_COMMIT();                                                          \
  }while(0)

  KC_ISSUE(0, 0);
  for (int c=0;c<13;c++){
    int s = c & 1;
    if (c+1 < 13){ KC_ISSUE(c+1, s^1); CP_WAIT1(); }
    else         { CP_WAIT0(); }
    __syncthreads();
    uint32_t stb = sb + (uint32_t)s*KC_ST;
    #pragma unroll
    for (int kk=0;kk<4;kk++){
      uint32_t aH[2][4], aL[2][4];
      #pragma unroll
      for (int mt=0;mt<2;mt++){
        int arow = m0 + mt*16 + (lane&15);
        uint32_t aoff = (uint32_t)(arow*128 + (((kk*2 + (lane>>4)) ^ (arow&7))<<4));
        ldsm4(aH[mt][0],aH[mt][1],aH[mt][2],aH[mt][3], stb + aoff);
        ldsm4(aL[mt][0],aL[mt][1],aL[mt][2],aL[mt][3], stb + 16384 + aoff);
      }
      #pragma unroll
      for (int g2=0;g2<2;g2++){
        int nrow = n0 + g2*16 + ((lane>>4)<<3) + (lane&7);
        uint32_t boff = (uint32_t)(nrow*128 + (((kk*2 + ((lane>>3)&1)) ^ (nrow&7))<<4));
        uint32_t bh0,bh1,bh2,bh3, bl0,bl1,bl2,bl3;
        ldsm4(bh0,bh1,bh2,bh3, stb + 32768 + boff);
        ldsm4(bl0,bl1,bl2,bl3, stb + 40960 + boff);
        #pragma unroll
        for (int mt=0;mt<2;mt++){
          mma16816(acc[mt][g2*2],   aH[mt], bh0, bh1);
          mma16816(acc[mt][g2*2],   aL[mt], bh0, bh1);
          mma16816(acc[mt][g2*2],   aH[mt], bl0, bl1);
          mma16816(acc[mt][g2*2+1], aH[mt], bh2, bh3);
          mma16816(acc[mt][g2*2+1], aL[mt], bh2, bh3);
          mma16816(acc[mt][g2*2+1], aH[mt], bl2, bl3);
        }
      }
    }
    __syncthreads();
  }

  // epilogue: split f32 -> bf16 hi/lo, store to g_yhi/g_ylo
  #pragma unroll
  for (int mt=0;mt<2;mt++){
    #pragma unroll
    for (int ng=0;ng<4;ng++){
      int d = ntile*64 + n0 + ng*8 + (lane&3)*2;
      #pragma unroll
      for (int half=0;half<2;half++){
        int t = mtile*128 + m0 + mt*16 + (lane>>2) + half*8;
        if (t < Tn){
          size_t row = (size_t)b*Tn + t;
          unsigned short h0,l0,h1,l1;
          bf_split(acc[mt][ng][half*2+0], h0, l0);
          bf_split(acc[mt][ng][half*2+1], h1, l1);
          ushort2 hh; hh.x=h0; hh.y=h1;
          ushort2 ll; ll.x=l0; ll.y=l1;
          *(ushort2*)&g_yhi[row*Dn + d] = hh;
          *(ushort2*)&g_ylo[row*Dn + d] = ll;
        }
      }
    }
  }
}

// ================= K_OUT: out = y @ Wo + bo  (cp.async double-buffered, 4 chunks) =================
// stage (64 k): A_hi 16K | A_lo 16K | B_hi 8K | B_lo 8K = 48KB; x2 = 96KB
#define KO_ST 49152
#define KO_SMEM 98304

__global__ __launch_bounds__(256,2) void k_out(const float* __restrict__ bo,
                                               float* __restrict__ out){
  extern __shared__ float smf[];
  char* smc = (char*)smf;
  uint32_t sb = smem_u32(smc);
  int tid = threadIdx.x, wid = tid>>5, lane = tid&31;
  int mtile = blockIdx.x, ntile = blockIdx.y;

  // dead fast path
  {
    int mstart = mtile*128;
    int b0 = mstart/Tn, b1 = (mstart+127)/Tn;
    int t_start = mstart - b0*Tn;
    bool dead = (t_start >= g_flen[b0]) && (b1==b0 || g_flen[b1]<=0);
    if (dead){
      int r = tid & 127;
      int m = mtile*128 + r;
      int b = m/Tn, t = m - b*Tn;
      size_t plane = (ntile<4)?OFF_MEAN:OFF_LOG;
      int colbase = ntile*64 - ((ntile>=4)?256:0);
      const float* bop = bo + ntile*64;
      for (int i = tid>>7; i<64; i+=2)
        out[plane + ((size_t)(b*Dn + colbase + i))*Tn + t] = bop[i];
      return;
    }
  }

  float acc[2][4][4];
  #pragma unroll
  for (int mt=0;mt<2;mt++)
    #pragma unroll
    for (int ng=0;ng<4;ng++){ acc[mt][ng][0]=0.f; acc[mt][ng][1]=0.f; acc[mt][ng][2]=0.f; acc[mt][ng][3]=0.f; }

  int m0 = (wid&3)*32, n0 = (wid>>2)*32;

  const uint4* aH_g = (const uint4*)(g_yhi + (size_t)(mtile*128)*Dn);
  const uint4* aL_g = (const uint4*)(g_ylo + (size_t)(mtile*128)*Dn);
  const uint4* bH_g = (const uint4*)(g_woThi + (size_t)(ntile*64)*256);
  const uint4* bL_g = (const uint4*)(g_woTlo + (size_t)(ntile*64)*256);

  int srow = tid>>3, sch = tid&7;
  uint32_t soff = (uint32_t)(srow*128 + ((sch ^ (srow&7))<<4));

  #define KO_ISSUE(c, s) do{                                              \
    uint32_t base_ = sb + (uint32_t)(s)*KO_ST;                            \
    _Pragma("unroll")                                                     \
    for (int i_=0;i_<4;i_++){                                             \
      uint32_t off_ = soff + (uint32_t)(i_*32*128);                       \
      size_t g_ = (size_t)(srow + i_*32)*32 + (c)*8 + sch;                \
      CP16(base_ + off_,         aH_g + g_);                              \
      CP16(base_ + 16384 + off_, aL_g + g_);                              \
    }                                                                     \
    _Pragma("unroll")                                                     \
    for (int i_=0;i_<2;i_++){                                             \
      uint32_t off_ = soff + (uint32_t)(i_*32*128);                       \
      size_t g_ = (size_t)(srow + i_*32)*32 + (c)*8 + sch;                \
      CP16(base_ + 32768 + off_, bH_g + g_);                              \
      CP16(base_ + 40960 + off_, bL_g + g_);                              \
    }                                                                     \
    CP_COMMIT();                                                          \
  }while(0)

  KO_ISSUE(0, 0);
  for (int c=0;c<4;c++){
    int s = c & 1;
    if (c+1 < 4){ KO_ISSUE(c+1, s^1); CP_WAIT1(); }
    else        { CP_WAIT0(); }
    __syncthreads();
    uint32_t stb = sb + (uint32_t)s*KO_ST;
    #pragma unroll
    for (int kk=0;kk<4;kk++){
      uint32_t aH[2][4], aL[2][4];
      #pragma unroll
      for (int mt=0;mt<2;mt++){
        int arow = m0 + mt*16 + (lane&15);
        uint32_t aoff = (uint32_t)(arow*128 + (((kk*2 + (lane>>4)) ^ (arow&7))<<4));
        ldsm4(aH[mt][0],aH[mt][1],aH[mt][2],aH[mt][3], stb + aoff);
        ldsm4(aL[mt][0],aL[mt][1],aL[mt][2],aL[mt][3], stb + 16384 + aoff);
      }
      #pragma unroll
      for (int g2=0;g2<2;g2++){
        int nrow = n0 + g2*16 + ((lane>>4)<<3) + (lane&7);
        uint32_t boff = (uint32_t)(nrow*128 + (((kk*2 + ((lane>>3)&1)) ^ (nrow&7))<<4));
        uint32_t bh0,bh1,bh2,bh3, bl0,bl1,bl2,bl3;
        ldsm4(bh0,bh1,bh2,bh3, stb + 32768 + boff);
        ldsm4(bl0,bl1,bl2,bl3, stb + 40960 + boff);
        #pragma unroll
        for (int mt=0;mt<2;mt++){
          mma16816(acc[mt][g2*2],   aH[mt], bh0, bh1);
          mma16816(acc[mt][g2*2],   aL[mt], bh0, bh1);
          mma16816(acc[mt][g2*2],   aH[mt], bl0, bl1);
          mma16816(acc[mt][g2*2+1], aH[mt], bh2, bh3);
          mma16816(acc[mt][g2*2+1], aL[mt], bh2, bh3);
          mma16816(acc[mt][g2*2+1], aH[mt], bl2, bl3);
        }
      }
    }
    __syncthreads();
  }

  // epilogue
  {
    size_t plane = (ntile < 4) ? OFF_MEAN : OFF_LOG;
    int colbase = ntile*64 - ((ntile>=4)?256:0);
    const float* bop = bo + ntile*64;
    #pragma unroll
    for (int mt=0;mt<2;mt++){
      #pragma unroll
      for (int ng=0;ng<4;ng++){
        int cin = n0 + ng*8 + 2*(lane&3);
        float b0v = bop[cin], b1v = bop[cin+1];
        #pragma unroll
        for (int half=0;half<2;half++){
          int m_g = mtile*128 + m0 + mt*16 + (lane>>2) + half*8;
          int b = m_g / Tn;
          int t = m_g - b*Tn;
          size_t base = plane + ((size_t)(b*Dn + colbase + cin))*Tn + t;
          out[base]      = acc[mt][ng][half*2+0] + b0v;
          out[base + Tn] = acc[mt][ng][half*2+1] + b1v;
        }
      }
    }
  }
}

// ---------------- launcher ----------------
extern "C" void kernel_launch(void* const* d_in, const int* in_sizes, int n_in,
                              void* d_out, int out_size){
  (void)in_sizes; (void)n_in; (void)out_size;
  const float* dur = (const float*)d_in[0];
  const float* phon= (const float*)d_in[1];
  const float* Wpw = (const float*)d_in[3];
  const float* bpw = (const float*)d_in[4];
  const float* Cw  = (const float*)d_in[5];
  const float* cbw = (const float*)d_in[6];
  const float* Mw  = (const float*)d_in[7];
  const float* mbw = (const float*)d_in[8];
  const float* Lw  = (const float*)d_in[9];
  const float* lbw = (const float*)d_in[10];
  const float* Wpc = (const float*)d_in[11];
  const float* bpc = (const float*)d_in[12];
  const float* Cc  = (const float*)d_in[13];
  const float* cbc = (const float*)d_in[14];
  const float* Mc  = (const float*)d_in[15];
  const float* mbc = (const float*)d_in[16];
  const float* Lcm = (const float*)d_in[17];
  const float* lbc = (const float*)d_in[18];
  const float* Wo  = (const float*)d_in[19];
  const float* bo  = (const float*)d_in[20];
  float* out = (float*)d_out;

  cudaFuncSetAttribute((const void*)k_main, cudaFuncAttributeMaxDynamicSharedMemorySize,
                       SMEM_BYTES);
  cudaFuncSetAttribute((const void*)k_comb, cudaFuncAttributeMaxDynamicSharedMemorySize,
                       KC_SMEM);
  cudaFuncSetAttribute((const void*)k_out, cudaFuncAttributeMaxDynamicSharedMemorySize,
                       KO_SMEM);

  k_pre<<<980,256>>>(dur, phon, Cw, Wpw, Cc, Wpc, bpw, cbw, bpc, cbc, Wo, Lcm, lbw, lbc, out);
  k_mid<<<1232,256>>>(Lw);
  k_main<<<dim3(NB,Bn),256,SMEM_BYTES>>>(dur,Mw,mbw,Mc,mbc,out);
  k_comb<<<dim3(8,4,Bn),256,KC_SMEM>>>();
  k_out<<<dim3(125,8),256,KO_SMEM>>>(bo,out);
}

// round 14
// speedup vs baseline: 2.2847x; 1.0312x over previous
#include <cuda_runtime.h>
#include <cuda_bf16.h>
#include <cstdint>
#include <math.h>

typedef unsigned long long ull;

#define Bn 16
#define Dn 256
#define Ln 200
#define Tn 1000
#define TT 16
#define NB 63            // ceil(1000/16)
#define KW 832           // padded K: [q*200+l] (800) | wc (8) | bias (1) | pad (23)

#define OFF_MEAN ((size_t)0)
#define OFF_LOG  ((size_t)4096000)
#define OFF_FM   ((size_t)8192000)
#define OFF_FL   ((size_t)8208000)
#define OFF_W    ((size_t)8208016)

// ---------------- device scratch ----------------
__device__ float g_sk[Bn*Ln];
__device__ int   g_plen[Bn];
__device__ int   g_flen[Bn];
__device__ float g_phonT[(size_t)Bn*Ln*Dn];          // [b][l][d] f32 (conv)
__device__ unsigned short g_phbf_hi[(size_t)Bn*Ln*Dn];  // bf16 split of phonT
__device__ unsigned short g_phbf_lo[(size_t)Bn*Ln*Dn];
__device__ unsigned short g_lwbf_hi[4*Dn*Dn];        // LwT [q][d][dd] bf16
__device__ unsigned short g_lwbf_lo[4*Dn*Dn];
__device__ float g_hw[(size_t)Bn*Ln*8];
__device__ float g_hc[(size_t)Bn*Ln*8];
__device__ float g_Ceff[2*8*3*Dn];
__device__ float g_beff[2*8*3];
__device__ unsigned short g_wbf_hi[(size_t)Bn*1024*KW];  // W' [b][t(1024)][k]
__device__ unsigned short g_wbf_lo[(size_t)Bn*1024*KW];
__device__ unsigned short g_pbf_hi[(size_t)Bn*Dn*KW];    // P'T [b][d][k]
__device__ unsigned short g_pbf_lo[(size_t)Bn*Dn*KW];
__device__ unsigned short g_yhi[(size_t)Bn*Tn*Dn];   // bf16 hi of y
__device__ unsigned short g_ylo[(size_t)Bn*Tn*Dn];
__device__ unsigned short g_woThi[512*256];          // bf16 WoT [n][k]
__device__ unsigned short g_woTlo[512*256];

__device__ __forceinline__ float silu_f(float x){ return __fdividef(x, 1.f + __expf(-x)); }

__device__ __forceinline__ uint32_t smem_u32(const void* p){
  uint32_t a;
  asm("{ .reg .u64 t; cvta.to.shared.u64 t, %1; cvt.u32.u64 %0, t; }" : "=r"(a) : "l"(p));
  return a;
}
__device__ __forceinline__ void bf_split(float v, unsigned short& h, unsigned short& l){
  __nv_bfloat16 hb = __float2bfloat16(v);
  h = __bfloat16_as_ushort(hb);
  l = __bfloat16_as_ushort(__float2bfloat16(v - __bfloat162float(hb)));
}

// ---------------- mma.sync / cp.async helpers ----------------
__device__ __forceinline__ void ldsm4(uint32_t& r0, uint32_t& r1, uint32_t& r2, uint32_t& r3,
                                      uint32_t addr){
  asm volatile("ldmatrix.sync.aligned.m8n8.x4.shared.b16 {%0,%1,%2,%3}, [%4];"
    : "=r"(r0), "=r"(r1), "=r"(r2), "=r"(r3) : "r"(addr));
}
__device__ __forceinline__ void mma16816(float* d, const uint32_t* a, uint32_t b0, uint32_t b1){
  asm volatile("mma.sync.aligned.m16n8k16.row.col.f32.bf16.bf16.f32 "
    "{%0,%1,%2,%3},{%4,%5,%6,%7},{%8,%9},{%0,%1,%2,%3};"
    : "+f"(d[0]), "+f"(d[1]), "+f"(d[2]), "+f"(d[3])
    : "r"(a[0]), "r"(a[1]), "r"(a[2]), "r"(a[3]), "r"(b0), "r"(b1));
}
#define CP16(dst,src) asm volatile("cp.async.cg.shared.global [%0],[%1],16;" :: "r"(dst), "l"(src) : "memory")
#define CP_COMMIT()   asm volatile("cp.async.commit_group;" ::: "memory")
#define CP_WAIT1()    asm volatile("cp.async.wait_group 1;" ::: "memory")
#define CP_WAIT0()    asm volatile("cp.async.wait_group 0;" ::: "memory")

// ================= K_PRE =================
// 0..895 transpose(+bf16) | 896..943 ceff | 944..945 beff | 946..961 setup |
// 962..963 WoT | 964..979 P'-extra | 980..1235 LwT split-transpose
__global__ void k_pre(const float* __restrict__ dur, const float* __restrict__ phon,
                      const float* __restrict__ Cw, const float* __restrict__ Wpw,
                      const float* __restrict__ Cc, const float* __restrict__ Wpc,
                      const float* __restrict__ bpw, const float* __restrict__ cbw,
                      const float* __restrict__ bpc, const float* __restrict__ cbc,
                      const float* __restrict__ Wo, const float* __restrict__ Lw,
                      const float* __restrict__ Lcm, const float* __restrict__ lbw,
                      const float* __restrict__ lbc,
                      float* __restrict__ out){
  __shared__ float tile[32][33];
  __shared__ float cs[Dn];
  __shared__ int sfl;
  int bi = blockIdx.x, tid = threadIdx.x;

  if (bi < 896){
    int l0 = (bi%7)*32, d0 = ((bi/7)%8)*32, b = bi/56;
    int tx = tid&31, ty = tid>>5;
    #pragma unroll
    for (int r=0;r<4;r++){
      int dy = d0+ty+8*r, lx = l0+tx;
      tile[ty+8*r][tx] = (lx<Ln) ? phon[((size_t)b*Dn+dy)*Ln+lx] : 0.f;
    }
    __syncthreads();
    #pragma unroll
    for (int r=0;r<4;r++){
      int ly = l0+ty+8*r, dx = d0+tx;
      if (ly<Ln){
        float v = tile[tx][ty+8*r];
        size_t idx = ((size_t)b*Ln+ly)*Dn+dx;
        g_phonT[idx] = v;
        unsigned short h,l; bf_split(v,h,l);
        g_phbf_hi[idx]=h; g_phbf_lo[idx]=l;
      }
    }
  } else if (bi < 944){
    int idx = bi-896;
    int o = idx&7, k = (idx>>3)%3, which = idx/24;
    const float* C = which? Cc : Cw;
    const float* W = which? Wpc : Wpw;
    cs[tid] = C[(o*Dn+tid)*3+k];
    __syncthreads();
    float acc=0.f;
    #pragma unroll 8
    for (int d=0; d<Dn; d++)
      acc = fmaf(cs[d], W[d*Dn+tid], acc);
    g_Ceff[((which*8+o)*3+k)*Dn + tid] = acc;
  } else if (bi < 946){
    int which = bi-944;
    const float* C = which? Cc: Cw; const float* bp = which? bpc : bpw; const float* cb = which? cbc : cbw;
    int wp = tid>>5, lane = tid&31;
    for (int pr=wp; pr<24; pr+=8){
      int o = pr/3, var = pr%3;
      int k0 = (var==0)?1:0, k1 = (var==2)?1:2;
      float acc = 0.f;
      #pragma unroll
      for (int i=0;i<8;i++){
        int d = lane + 32*i;
        float bv = bp[d];
        for (int k=k0;k<=k1;k++) acc = fmaf(C[(o*Dn+d)*3+k], bv, acc);
      }
      #pragma unroll
      for (int off=16;off;off>>=1) acc += __shfl_xor_sync(0xffffffffu, acc, off);
      if (lane==0) g_beff[(which*8+o)*3+var] = acc + cb[o];
    }
  } else if (bi < 962){
    int b = bi-946;
    float* s = &tile[0][0];
    if (tid < Ln) s[tid] = dur[b*Ln+tid];
    __syncthreads();
    if (tid == 0){
      float acc = 0.f; int plen = 0;
      for (int l=0;l<Ln;l++){ g_sk[b*Ln+l]=acc; float d=s[l]; acc+=d; if (d>0.f) plen=l+1; }
      g_plen[b]=plen;
      int fl = (int)rintf(acc); fl = fl<0?0:(fl>Tn?Tn:fl);
      g_flen[b]=fl; sfl=fl;
      out[OFF_FL + b] = (float)fl;
    }
    __syncthreads();
    int fl = sfl;
    for (int t=tid;t<Tn;t+=256) out[OFF_FM + (size_t)b*Tn + t] = (t<fl)?1.f:0.f;
  } else if (bi < 964){
    // WoT hi/lo split
    int n = (bi-962)*256 + tid;
    for (int kc=0;kc<32;kc++){
      __align__(16) unsigned short h8[8];
      __align__(16) unsigned short l8[8];
      #pragma unroll
      for (int j=0;j<8;j++){
        float w = Wo[(size_t)(kc*8+j)*512 + n];
        bf_split(w, h8[j], l8[j]);
      }
      *(uint4*)&g_woThi[n*256 + kc*8] = *(uint4*)h8;
      *(uint4*)&g_woTlo[n*256 + kc*8] = *(uint4*)l8;
    }
  } else if (bi < 980){
    // P' extra rows: k=800..807 = Lc, k=808 = lbw+lbc, 809..831 = 0
    int b = bi-964;
    size_t base = ((size_t)b*Dn + tid)*KW;
    #pragma unroll
    for (int i=0;i<8;i++){
      unsigned short h,l; bf_split(Lcm[i*Dn+tid], h, l);
      g_pbf_hi[base+800+i]=h; g_pbf_lo[base+800+i]=l;
    }
    {
      unsigned short h,l; bf_split(lbw[tid]+lbc[tid], h, l);
      g_pbf_hi[base+808]=h; g_pbf_lo[base+808]=l;
    }
    for (int k=809;k<KW;k++){ g_pbf_hi[base+k]=0; g_pbf_lo[base+k]=0; }
  } else {
    // LwT split-transpose: LwT[q][d][dd] = Lw[q*256+dd][d]
    int idx = bi-980;            // 0..255
    int q = idx>>6;
    int rem = idx&63;
    int dd0 = (rem&7)*32;
    int d0  = (rem>>3)*32;
    int tx = tid&31, ty = tid>>5;
    #pragma unroll
    for (int r=0;r<4;r++)
      tile[ty+8*r][tx] = Lw[(size_t)(q*256 + dd0+ty+8*r)*Dn + d0+tx];
    __syncthreads();
    #pragma unroll
    for (int r=0;r<4;r++){
      float v = tile[tx][ty+8*r];
      unsigned short h,l; bf_split(v,h,l);
      size_t o = ((size_t)q*Dn + d0+ty+8*r)*Dn + dd0+tx;
      g_lwbf_hi[o]=h; g_lwbf_lo[o]=l;
    }
  }
}

// ================= K_MID: conv only =================
__global__ void k_mid(){
  __shared__ float xs[10*Dn];
  int bi = blockIdx.x, tid = threadIdx.x;
  int b = bi/25, l0 = (bi%25)*8;
  for (int i=tid; i<10*Dn; i+=256){
    int r = i>>8, dp = i&255, col = l0-1+r;
    xs[r*Dn+dp] = (col>=0 && col<Ln) ? g_phonT[((size_t)b*Ln+col)*Dn+dp] : 0.f;
  }
  __syncthreads();
  int warp = tid>>5, lane = tid&31;
  int l = l0 + warp;
  int plen = g_plen[b];
  for (int idx=0; idx<16; idx++){
    int which = idx>>3, o = idx&7;
    const float* ce = g_Ceff + ((which*8+o)*3)*Dn;
    float acc = 0.f;
    for (int i=lane; i<3*Dn; i+=32){
      int k = i>>8, dp = i&255;
      acc = fmaf(ce[k*Dn+dp], xs[((l-l0)+k)*Dn+dp], acc);
    }
    #pragma unroll
    for (int off=16; off; off>>=1) acc += __shfl_xor_sync(0xffffffffu, acc, off);
    if (lane==0){
      int var = (l==0)?0:((l==Ln-1)?2:1);
      float h = silu_f(acc + g_beff[(which*8+o)*3+var]);
      h = (l < plen) ? h : 0.f;
      float* dst = which ? g_hc : g_hw;
      dst[((size_t)b*Ln+l)*8 + o] = h;
    }
  }
}

// ================= K_PGM: P'[d][q*200+l] = LwT[q] @ phonT[b]  (mma, hi/lo x3) =================
// stage (64 k): A_hi 16K | A_lo 16K | B_hi 8K | B_lo 8K = 48KB; x2 = 96KB
#define KP_ST 49152
#define KP_SMEM 98304

__global__ __launch_bounds__(256,2) void k_pgm(){
  extern __shared__ float smf[];
  char* smc = (char*)smf;
  uint32_t sb = smem_u32(smc);
  int tid = threadIdx.x, wid = tid>>5, lane = tid&31;
  int mtile = blockIdx.x, ntile = blockIdx.y;
  int b = blockIdx.z>>2, q = blockIdx.z&3;

  float acc[2][4][4];
  #pragma unroll
  for (int mt=0;mt<2;mt++)
    #pragma unroll
    for (int ng=0;ng<4;ng++){ acc[mt][ng][0]=0.f; acc[mt][ng][1]=0.f; acc[mt][ng][2]=0.f; acc[mt][ng][3]=0.f; }

  int m0 = (wid&3)*32, n0 = (wid>>2)*32;

  const uint4* aH_g = ((const uint4*)g_lwbf_hi) + (size_t)(q*Dn + mtile*128)*32;
  const uint4* aL_g = ((const uint4*)g_lwbf_lo) + (size_t)(q*Dn + mtile*128)*32;
  const uint4* bH_g = ((const uint4*)g_phbf_hi) + (size_t)(b*Ln)*32;
  const uint4* bL_g = ((const uint4*)g_phbf_lo) + (size_t)(b*Ln)*32;

  int srow = tid>>3, sch = tid&7;
  uint32_t soff = (uint32_t)(srow*128 + ((sch ^ (srow&7))<<4));

  #define KP_ISSUE(c, s) do{                                              \
    uint32_t base_ = sb + (uint32_t)(s)*KP_ST;                            \
    _Pragma("unroll")                                                     \
    for (int i_=0;i_<4;i_++){                                             \
      uint32_t off_ = soff + (uint32_t)(i_*32*128);                       \
      size_t g_ = (size_t)(srow + i_*32)*32 + (c)*8 + sch;                \
      CP16(base_ + off_,         aH_g + g_);                              \
      CP16(base_ + 16384 + off_, aL_g + g_);                              \
    }                                                                     \
    _Pragma("unroll")                                                     \
    for (int i_=0;i_<2;i_++){                                             \
      uint32_t off_ = soff + (uint32_t)(i_*32*128);                       \
      int lr_ = ntile*64 + srow + i_*32; if (lr_ > Ln-1) lr_ = Ln-1;      \
      size_t g_ = (size_t)lr_*32 + (c)*8 + sch;                           \
      CP16(base_ + 32768 + off_, bH_g + g_);                              \
      CP16(base_ + 40960 + off_, bL_g + g_);                              \
    }                                                                     \
    CP_COMMIT();                                                          \
  }while(0)

  KP_ISSUE(0, 0);
  for (int c=0;c<4;c++){
    int s = c & 1;
    if (c+1 < 4){ KP_ISSUE(c+1, s^1); CP_WAIT1(); }
    else        { CP_WAIT0(); }
    __syncthreads();
    uint32_t stb = sb + (uint32_t)s*KP_ST;
    #pragma unroll
    for (int kk=0;kk<4;kk++){
      uint32_t aH[2][4], aL[2][4];
      #pragma unroll
      for (int mt=0;mt<2;mt++){
        int arow = m0 + mt*16 + (lane&15);
        uint32_t aoff = (uint32_t)(arow*128 + (((kk*2 + (lane>>4)) ^ (arow&7))<<4));
        ldsm4(aH[mt][0],aH[mt][1],aH[mt][2],aH[mt][3], stb + aoff);
        ldsm4(aL[mt][0],aL[mt][1],aL[mt][2],aL[mt][3], stb + 16384 + aoff);
      }
      #pragma unroll
      for (int g2=0;g2<2;g2++){
        int nrow = n0 + g2*16 + ((lane>>4)<<3) + (lane&7);
        uint32_t boff = (uint32_t)(nrow*128 + (((kk*2 + ((lane>>3)&1)) ^ (nrow&7))<<4));
        uint32_t bh0,bh1,bh2,bh3, bl0,bl1,bl2,bl3;
        ldsm4(bh0,bh1,bh2,bh3, stb + 32768 + boff);
        ldsm4(bl0,bl1,bl2,bl3, stb + 40960 + boff);
        #pragma unroll
        for (int mt=0;mt<2;mt++){
          mma16816(acc[mt][g2*2],   aH[mt], bh0, bh1);
          mma16816(acc[mt][g2*2],   aL[mt], bh0, bh1);
          mma16816(acc[mt][g2*2],   aH[mt], bl0, bl1);
          mma16816(acc[mt][g2*2+1], aH[mt], bh2, bh3);
          mma16816(acc[mt][g2*2+1], aL[mt], bh2, bh3);
          mma16816(acc[mt][g2*2+1], aH[mt], bl2, bl3);
        }
      }
    }
    __syncthreads();
  }

  // epilogue: P'[b][d][q*200+col] bf16 hi/lo (guard col < 200)
  #pragma unroll
  for (int mt=0;mt<2;mt++){
    #pragma unroll
    for (int ng=0;ng<4;ng++){
      int col = ntile*64 + n0 + ng*8 + 2*(lane&3);
      if (col < Ln){
        #pragma unroll
        for (int half=0;half<2;half++){
          int d = mtile*128 + m0 + mt*16 + (lane>>2) + half*8;
          size_t idx = ((size_t)(b*Dn) + d)*KW + q*200 + col;
          unsigned short h0,l0,h1,l1;
          bf_split(acc[mt][ng][half*2+0], h0, l0);
          bf_split(acc[mt][ng][half*2+1], h1, l1);
          ushort2 hh; hh.x=h0; hh.y=h1;
          ushort2 ll; ll.x=l0; ll.y=l1;
          *(ushort2*)&g_pbf_hi[idx] = hh;
          *(ushort2*)&g_pbf_lo[idx] = ll;
        }
      }
    }
  }
}

// ================= K_MAIN: phases 1-2 with fused W' export =================
// dyn smem (floats): w_s 0..12800 | sk 12800..13000 | bc 13000..13400 | wc 13400..13528 | prm 13528..13594
#define SMEM_BYTES 54376

__global__ __launch_bounds__(256,3) void k_main(
  const float* __restrict__ dur,
  const float* __restrict__ Mw, const float* __restrict__ mbw,
  const float* __restrict__ Mc, const float* __restrict__ mbc,
  float* __restrict__ out)
{
  extern __shared__ float sm[];
  float* w_s  = sm;
  float* sk_s = sm + 12800;
  float* bc_s = sm + 13000;
  float* wc_s = sm + 13400;
  float* prm  = sm + 13528;

  int b = blockIdx.y;
  int t0 = blockIdx.x * TT;
  int tid = threadIdx.x;
  int plen = g_plen[b], flen = g_flen[b];
  bool active = (t0 < flen);

  if (active){
    if (tid < 40)      prm[tid] = Mw[tid];
    else if (tid < 44) prm[tid] = mbw[tid-40];
    else if (tid < 64) prm[tid] = Mc[tid-44];
    else if (tid < 66) prm[tid] = mbc[tid-64];
    __syncthreads();

    // ---- phase 1 ----
    if (tid < Ln){
      int l = tid;
      float dv = dur[b*Ln + l];
      float sk = g_sk[b*Ln + l];
      sk_s[l] = sk;
      const float* hwp = g_hw + ((size_t)b*Ln+l)*8;
      const float* hcp = g_hc + ((size_t)b*Ln+l)*8;
      float bw[4], bc[2];
      #pragma unroll
      for (int q=0;q<4;q++){
        float a = prm[40+q] + dv*prm[4+q];
        #pragma unroll
        for (int j=0;j<8;j++) a = fmaf(hwp[j], prm[(2+j)*4+q], a);
        bw[q]=a;
      }
      #pragma unroll
      for (int p=0;p<2;p++){
        float a = prm[64+p] + dv*prm[46+p];
        #pragma unroll
        for (int j=0;j<8;j++) a = fmaf(hcp[j], prm[44+(2+j)*2+p], a);
        bc[p]=a;
      }
      bc_s[2*l]   = bc[0];
      bc_s[2*l+1] = bc[1];
      bool lv = l < plen;
      float4* wl = (float4*)(w_s + l*64);
      #pragma unroll
      for (int t=0;t<TT;t++){
        int tt = t0+t;
        float4 av = {0.f,0.f,0.f,0.f};
        if (lv && tt < flen){
          float S = (float)(tt+1) - sk;
          av.x = silu_f(fmaf(S, prm[0], bw[0]));
          av.y = silu_f(fmaf(S, prm[1], bw[1]));
          av.z = silu_f(fmaf(S, prm[2], bw[2]));
          av.w = silu_f(fmaf(S, prm[3], bw[3]));
        }
        wl[t] = av;
      }
    }
    __syncthreads();

    // ---- phase 2: softmax + f32 w out + bf16 W' export + wc reduce ----
    {
      int wp = tid>>5, lane = tid&31;
      float mc0 = prm[44], mc1 = prm[45];
      const size_t qs = (size_t)Tn*Ln;
      for (int t=wp; t<TT; t+=8){
        int tt = t0+t;
        if (tt >= Tn) continue;
        size_t wb = OFF_W + ((size_t)(b*4)*Tn + tt)*Ln;
        size_t rw = ((size_t)(b*1024)+tt)*KW;
        if (tt >= flen){
          for (int l=lane; l<Ln; l+=32){
            out[wb+l]=0.f; out[wb+qs+l]=0.f; out[wb+2*qs+l]=0.f; out[wb+3*qs+l]=0.f;
          }
          for (int k=lane; k<KW; k+=32){ g_wbf_hi[rw+k]=0; g_wbf_lo[rw+k]=0; }
          if (lane<8) wc_s[t*8+lane]=0.f;
          continue;
        }
        float4 wv[7];
        float m0=-3e38f,m1=-3e38f,m2=-3e38f,m3=-3e38f;
        #pragma unroll
        for (int i=0;i<7;i++){
          int l = lane + 32*i;
          if (l < plen){
            wv[i] = *(const float4*)(w_s + l*64 + t*4);
            m0=fmaxf(m0,wv[i].x); m1=fmaxf(m1,wv[i].y); m2=fmaxf(m2,wv[i].z); m3=fmaxf(m3,wv[i].w);
          }
        }
        #pragma unroll
        for (int off=16;off;off>>=1){
          m0=fmaxf(m0,__shfl_xor_sync(0xffffffffu,m0,off));
          m1=fmaxf(m1,__shfl_xor_sync(0xffffffffu,m1,off));
          m2=fmaxf(m2,__shfl_xor_sync(0xffffffffu,m2,off));
          m3=fmaxf(m3,__shfl_xor_sync(0xffffffffu,m3,off));
        }
        float s0=0.f,s1=0.f,s2=0.f,s3=0.f;
        #pragma unroll
        for (int i=0;i<7;i++){
          int l = lane + 32*i;
          if (l < plen){
            wv[i].x=__expf(wv[i].x-m0); wv[i].y=__expf(wv[i].y-m1);
            wv[i].z=__expf(wv[i].z-m2); wv[i].w=__expf(wv[i].w-m3);
            s0+=wv[i].x; s1+=wv[i].y; s2+=wv[i].z; s3+=wv[i].w;
          }
        }
        #pragma unroll
        for (int off=16;off;off>>=1){
          s0+=__shfl_xor_sync(0xffffffffu,s0,off);
          s1+=__shfl_xor_sync(0xffffffffu,s1,off);
          s2+=__shfl_xor_sync(0xffffffffu,s2,off);
          s3+=__shfl_xor_sync(0xffffffffu,s3,off);
        }
        float i0=__fdividef(1.f,s0), i1=__fdividef(1.f,s1), i2=__fdividef(1.f,s2), i3=__fdividef(1.f,s3);
        float Sb = (float)(tt+1);
        float r0=0.f,r1=0.f,r2=0.f,r3=0.f,r4=0.f,r5=0.f,r6=0.f,r7=0.f;
        #pragma unroll
        for (int i=0;i<7;i++){
          int l = lane + 32*i;
          if (l < plen){
            float4 v; v.x=wv[i].x*i0; v.y=wv[i].y*i1; v.z=wv[i].z*i2; v.w=wv[i].w*i3;
            out[wb+l]=v.x; out[wb+qs+l]=v.y; out[wb+2*qs+l]=v.z; out[wb+3*qs+l]=v.w;
            unsigned short h,lo;
            bf_split(v.x,h,lo); g_wbf_hi[rw+l]=h;     g_wbf_lo[rw+l]=lo;
            bf_split(v.y,h,lo); g_wbf_hi[rw+200+l]=h; g_wbf_lo[rw+200+l]=lo;
            bf_split(v.z,h,lo); g_wbf_hi[rw+400+l]=h; g_wbf_lo[rw+400+l]=lo;
            bf_split(v.w,h,lo); g_wbf_hi[rw+600+l]=h; g_wbf_lo[rw+600+l]=lo;
            float S = Sb - sk_s[l];
            float cx = silu_f(fmaf(S, mc0, bc_s[2*l]));
            float cy = silu_f(fmaf(S, mc1, bc_s[2*l+1]));
            r0=fmaf(v.x,cx,r0); r1=fmaf(v.x,cy,r1);
            r2=fmaf(v.y,cx,r2); r3=fmaf(v.y,cy,r3);
            r4=fmaf(v.z,cx,r4); r5=fmaf(v.z,cy,r5);
            r6=fmaf(v.w,cx,r6); r7=fmaf(v.w,cy,r7);
          } else if (l < Ln){
            out[wb+l]=0.f; out[wb+qs+l]=0.f; out[wb+2*qs+l]=0.f; out[wb+3*qs+l]=0.f;
            g_wbf_hi[rw+l]=0;     g_wbf_lo[rw+l]=0;
            g_wbf_hi[rw+200+l]=0; g_wbf_lo[rw+200+l]=0;
            g_wbf_hi[rw+400+l]=0; g_wbf_lo[rw+400+l]=0;
            g_wbf_hi[rw+600+l]=0; g_wbf_lo[rw+600+l]=0;
          }
        }
        #pragma unroll
        for (int off=16;off;off>>=1){
          r0+=__shfl_xor_sync(0xffffffffu,r0,off); r1+=__shfl_xor_sync(0xffffffffu,r1,off);
          r2+=__shfl_xor_sync(0xffffffffu,r2,off); r3+=__shfl_xor_sync(0xffffffffu,r3,off);
          r4+=__shfl_xor_sync(0xffffffffu,r4,off); r5+=__shfl_xor_sync(0xffffffffu,r5,off);
          r6+=__shfl_xor_sync(0xffffffffu,r6,off); r7+=__shfl_xor_sync(0xffffffffu,r7,off);
        }
        if (lane==0){
          wc_s[t*8+0]=r0; wc_s[t*8+1]=r1; wc_s[t*8+2]=r2; wc_s[t*8+3]=r3;
          wc_s[t*8+4]=r4; wc_s[t*8+5]=r5; wc_s[t*8+6]=r6; wc_s[t*8+7]=r7;
        }
      }
    }
    __syncthreads();

    // ---- tail: W' rows k=800..831 (wc, bias, pad) ----
    for (int x=tid; x<TT*32; x+=256){
      int t = x>>5, j = x&31;
      int tt = t0+t;
      if (tt >= Tn) continue;
      float v = 0.f;
      if (j < 8)      v = wc_s[t*8+j];
      else if (j == 8) v = (tt < flen) ? 1.f : 0.f;
      unsigned short h,lo; bf_split(v,h,lo);
      size_t rw = ((size_t)(b*1024)+tt)*KW;
      g_wbf_hi[rw+800+j]=h; g_wbf_lo[rw+800+j]=lo;
    }
  } else {
    // inactive: zero w planes + zero W' rows
    int wp = tid>>5, lane = tid&31;
    const size_t qs = (size_t)Tn*Ln;
    for (int t=wp; t<TT; t+=8){
      int tt = t0+t;
      if (tt >= Tn) continue;
      size_t wb = OFF_W + ((size_t)(b*4)*Tn + tt)*Ln;
      for (int l=lane; l<Ln; l+=32){
        out[wb+l]=0.f; out[wb+qs+l]=0.f; out[wb+2*qs+l]=0.f; out[wb+3*qs+l]=0.f;
      }
    }
    for (int t=0;t<TT;t++){
      int tt = t0+t;
      if (tt >= Tn) break;
      size_t rw = ((size_t)(b*1024)+tt)*KW;
      for (int k=tid;k<KW;k+=256){ g_wbf_hi[rw+k]=0; g_wbf_lo[rw+k]=0; }
    }
  }
}

// ================= K_COMB: Y = W' @ P'  (cp.async double-buffered, M128xN64) =================
#define KC_ST 49152
#define KC_SMEM 98304

__global__ __launch_bounds__(256,2) void k_comb(){
  extern __shared__ float smf[];
  char* smc = (char*)smf;
  uint32_t sb = smem_u32(smc);
  int tid = threadIdx.x, wid = tid>>5, lane = tid&31;
  int mtile = blockIdx.x, ntile = blockIdx.y, b = blockIdx.z;

  if (mtile*128 >= g_flen[b]){
    uint4 z; z.x=0u; z.y=0u; z.z=0u; z.w=0u;
    #pragma unroll
    for (int i=0;i<4;i++){
      int lin = i*256 + tid;
      int r = lin>>3, ch = lin&7;
      int t = mtile*128 + r;
      if (t < Tn){
        size_t row = (size_t)b*Tn + t;
        ((uint4*)(g_yhi + row*Dn + ntile*64))[ch] = z;
        ((uint4*)(g_ylo + row*Dn + ntile*64))[ch] = z;
      }
    }
    return;
  }

  float acc[2][4][4];
  #pragma unroll
  for (int mt=0;mt<2;mt++)
    #pragma unroll
    for (int ng=0;ng<4;ng++){ acc[mt][ng][0]=0.f; acc[mt][ng][1]=0.f; acc[mt][ng][2]=0.f; acc[mt][ng][3]=0.f; }

  int m0 = (wid&3)*32, n0 = (wid>>2)*32;

  const uint4* gwh = (const uint4*)(g_wbf_hi + ((size_t)(b*1024) + (size_t)mtile*128)*KW);
  const uint4* gwl = (const uint4*)(g_wbf_lo + ((size_t)(b*1024) + (size_t)mtile*128)*KW);
  const uint4* gph = (const uint4*)(g_pbf_hi + ((size_t)(b*Dn) + (size_t)ntile*64)*KW);
  const uint4* gpl = (const uint4*)(g_pbf_lo + ((size_t)(b*Dn) + (size_t)ntile*64)*KW);
  const int rs = KW/8;   // 104

  int srow = tid>>3, sch = tid&7;
  uint32_t soff = (uint32_t)(srow*128 + ((sch ^ (srow&7))<<4));

  #define KC_ISSUE(c, s) do{                                              \
    uint32_t base_ = sb + (uint32_t)(s)*KC_ST;                            \
    _Pragma("unroll")                                                     \
    for (int i_=0;i_<4;i_++){                                             \
      uint32_t off_ = soff + (uint32_t)(i_*32*128);                       \
      size_t g_ = (size_t)(srow + i_*32)*rs + (c)*8 + sch;                \
      CP16(base_ + off_,          gwh + g_);                              \
      CP16(base_ + 16384 + off_,  gwl + g_);                              \
    }                                                                     \
    _Pragma("unroll")                                                     \
    for (int i_=0;i_<2;i_++){                                             \
      uint32_t off_ = soff + (uint32_t)(i_*32*128);                       \
      size_t g_ = (size_t)(srow + i_*32)*rs + (c)*8 + sch;                \
      CP16(base_ + 32768 + off_,  gph + g_);                              \
      CP16(base_ + 40960 + off_,  gpl + g_);                              \
    }                                                                     \
    CP_COMMIT();                                                          \
  }while(0)

  KC_ISSUE(0, 0);
  for (int c=0;c<13;c++){
    int s = c & 1;
    if (c+1 < 13){ KC_ISSUE(c+1, s^1); CP_WAIT1(); }
    else         { CP_WAIT0(); }
    __syncthreads();
    uint32_t stb = sb + (uint32_t)s*KC_ST;
    #pragma unroll
    for (int kk=0;kk<4;kk++){
      uint32_t aH[2][4], aL[2][4];
      #pragma unroll
      for (int mt=0;mt<2;mt++){
        int arow = m0 + mt*16 + (lane&15);
        uint32_t aoff = (uint32_t)(arow*128 + (((kk*2 + (lane>>4)) ^ (arow&7))<<4));
        ldsm4(aH[mt][0],aH[mt][1],aH[mt][2],aH[mt][3], stb + aoff);
        ldsm4(aL[mt][0],aL[mt][1],aL[mt][2],aL[mt][3], stb + 16384 + aoff);
      }
      #pragma unroll
      for (int g2=0;g2<2;g2++){
        int nrow = n0 + g2*16 + ((lane>>4)<<3) + (lane&7);
        uint32_t boff = (uint32_t)(nrow*128 + (((kk*2 + ((lane>>3)&1)) ^ (nrow&7))<<4));
        uint32_t bh0,bh1,bh2,bh3, bl0,bl1,bl2,bl3;
        ldsm4(bh0,bh1,bh2,bh3, stb + 32768 + boff);
        ldsm4(bl0,bl1,bl2,bl3, stb + 40960 + boff);
        #pragma unroll
        for (int mt=0;mt<2;mt++){
          mma16816(acc[mt][g2*2],   aH[mt], bh0, bh1);
          mma16816(acc[mt][g2*2],   aL[mt], bh0, bh1);
          mma16816(acc[mt][g2*2],   aH[mt], bl0, bl1);
          mma16816(acc[mt][g2*2+1], aH[mt], bh2, bh3);
          mma16816(acc[mt][g2*2+1], aL[mt], bh2, bh3);
          mma16816(acc[mt][g2*2+1], aH[mt], bl2, bl3);
        }
      }
    }
    __syncthreads();
  }

  #pragma unroll
  for (int mt=0;mt<2;mt++){
    #pragma unroll
    for (int ng=0;ng<4;ng++){
      int d = ntile*64 + n0 + ng*8 + (lane&3)*2;
      #pragma unroll
      for (int half=0;half<2;half++){
        int t = mtile*128 + m0 + mt*16 + (lane>>2) + half*8;
        if (t < Tn){
          size_t row = (size_t)b*Tn + t;
          unsigned short h0,l0,h1,l1;
          bf_split(acc[mt][ng][half*2+0], h0, l0);
          bf_split(acc[mt][ng][half*2+1], h1, l1);
          ushort2 hh; hh.x=h0; hh.y=h1;
          ushort2 ll; ll.x=l0; ll.y=l1;
          *(ushort2*)&g_yhi[row*Dn + d] = hh;
          *(ushort2*)&g_ylo[row*Dn + d] = ll;
        }
      }
    }
  }
}

// ================= K_OUT: out = y @ Wo + bo  (cp.async double-buffered) =================
#define KO_ST 49152
#define KO_SMEM 98304

__global__ __launch_bounds__(256,2) void k_out(const float* __restrict__ bo,
                                               float* __restrict__ out){
  extern __shared__ float smf[];
  char* smc = (char*)smf;
  uint32_t sb = smem_u32(smc);
  int tid = threadIdx.x, wid = tid>>5, lane = tid&31;
  int mtile = blockIdx.x, ntile = blockIdx.y;

  {
    int mstart = mtile*128;
    int b0 = mstart/Tn, b1 = (mstart+127)/Tn;
    int t_start = mstart - b0*Tn;
    bool dead = (t_start >= g_flen[b0]) && (b1==b0 || g_flen[b1]<=0);
    if (dead){
      int r = tid & 127;
      int m = mtile*128 + r;
      int b = m/Tn, t = m - b*Tn;
      size_t plane = (ntile<4)?OFF_MEAN:OFF_LOG;
      int colbase = ntile*64 - ((ntile>=4)?256:0);
      const float* bop = bo + ntile*64;
      for (int i = tid>>7; i<64; i+=2)
        out[plane + ((size_t)(b*Dn + colbase + i))*Tn + t] = bop[i];
      return;
    }
  }

  float acc[2][4][4];
  #pragma unroll
  for (int mt=0;mt<2;mt++)
    #pragma unroll
    for (int ng=0;ng<4;ng++){ acc[mt][ng][0]=0.f; acc[mt][ng][1]=0.f; acc[mt][ng][2]=0.f; acc[mt][ng][3]=0.f; }

  int m0 = (wid&3)*32, n0 = (wid>>2)*32;

  const uint4* aH_g = (const uint4*)(g_yhi + (size_t)(mtile*128)*Dn);
  const uint4* aL_g = (const uint4*)(g_ylo + (size_t)(mtile*128)*Dn);
  const uint4* bH_g = (const uint4*)(g_woThi + (size_t)(ntile*64)*256);
  const uint4* bL_g = (const uint4*)(g_woTlo + (size_t)(ntile*64)*256);

  int srow = tid>>3, sch = tid&7;
  uint32_t soff = (uint32_t)(srow*128 + ((sch ^ (srow&7))<<4));

  #define KO_ISSUE(c, s) do{                                              \
    uint32_t base_ = sb + (uint32_t)(s)*KO_ST;                            \
    _Pragma("unroll")                                                     \
    for (int i_=0;i_<4;i_++){                                             \
      uint32_t off_ = soff + (uint32_t)(i_*32*128);                       \
      size_t g_ = (size_t)(srow + i_*32)*32 + (c)*8 + sch;                \
      CP16(base_ + off_,         aH_g + g_);                              \
      CP16(base_ + 16384 + off_, aL_g + g_);                              \
    }                                                                     \
    _Pragma("unroll")                                                     \
    for (int i_=0;i_<2;i_++){                                             \
      uint32_t off_ = soff + (uint32_t)(i_*32*128);                       \
      size_t g_ = (size_t)(srow + i_*32)*32 + (c)*8 + sch;                \
      CP16(base_ + 32768 + off_, bH_g + g_);                              \
      CP16(base_ + 40960 + off_, bL_g + g_);                              \
    }                                                                     \
    CP_COMMIT();                                                          \
  }while(0)

  KO_ISSUE(0, 0);
  for (int c=0;c<4;c++){
    int s = c & 1;
    if (c+1 < 4){ KO_ISSUE(c+1, s^1); CP_WAIT1(); }
    else        { CP_WAIT0(); }
    __syncthreads();
    uint32_t stb = sb + (uint32_t)s*KO_ST;
    #pragma unroll
    for (int kk=0;kk<4;kk++){
      uint32_t aH[2][4], aL[2][4];
      #pragma unroll
      for (int mt=0;mt<2;mt++){
        int arow = m0 + mt*16 + (lane&15);
        uint32_t aoff = (uint32_t)(arow*128 + (((kk*2 + (lane>>4)) ^ (arow&7))<<4));
        ldsm4(aH[mt][0],aH[mt][1],aH[mt][2],aH[mt][3], stb + aoff);
        ldsm4(aL[mt][0],aL[mt][1],aL[mt][2],aL[mt][3], stb + 16384 + aoff);
      }
      #pragma unroll
      for (int g2=0;g2<2;g2++){
        int nrow = n0 + g2*16 + ((lane>>4)<<3) + (lane&7);
        uint32_t boff = (uint32_t)(nrow*128 + (((kk*2 + ((lane>>3)&1)) ^ (nrow&7))<<4));
        uint32_t bh0,bh1,bh2,bh3, bl0,bl1,bl2,bl3;
        ldsm4(bh0,bh1,bh2,bh3, stb + 32768 + boff);
        ldsm4(bl0,bl1,bl2,bl3, stb + 40960 + boff);
        #pragma unroll
        for (int mt=0;mt<2;mt++){
          mma16816(acc[mt][g2*2],   aH[mt], bh0, bh1);
          mma16816(acc[mt][g2*2],   aL[mt], bh0, bh1);
          mma16816(acc[mt][g2*2],   aH[mt], bl0, bl1);
          mma16816(acc[mt][g2*2+1], aH[mt], bh2, bh3);
          mma16816(acc[mt][g2*2+1], aL[mt], bh2, bh3);
          mma16816(acc[mt][g2*2+1], aH[mt], bl2, bl3);
        }
      }
    }
    __syncthreads();
  }

  {
    size_t plane = (ntile < 4) ? OFF_MEAN : OFF_LOG;
    int colbase = ntile*64 - ((ntile>=4)?256:0);
    const float* bop = bo + ntile*64;
    #pragma unroll
    for (int mt=0;mt<2;mt++){
      #pragma unroll
      for (int ng=0;ng<4;ng++){
        int cin = n0 + ng*8 + 2*(lane&3);
        float b0v = bop[cin], b1v = bop[cin+1];
        #pragma unroll
        for (int half=0;half<2;half++){
          int m_g = mtile*128 + m0 + mt*16 + (lane>>2) + half*8;
          int b = m_g / Tn;
          int t = m_g - b*Tn;
          size_t base = plane + ((size_t)(b*Dn + colbase + cin))*Tn + t;
          out[base]      = acc[mt][ng][half*2+0] + b0v;
          out[base + Tn] = acc[mt][ng][half*2+1] + b1v;
        }
      }
    }
  }
}

// ---------------- launcher ----------------
extern "C" void kernel_launch(void* const* d_in, const int* in_sizes, int n_in,
                              void* d_out, int out_size){
  (void)in_sizes; (void)n_in; (void)out_size;
  const float* dur = (const float*)d_in[0];
  const float* phon= (const float*)d_in[1];
  const float* Wpw = (const float*)d_in[3];
  const float* bpw = (const float*)d_in[4];
  const float* Cw  = (const float*)d_in[5];
  const float* cbw = (const float*)d_in[6];
  const float* Mw  = (const float*)d_in[7];
  const float* mbw = (const float*)d_in[8];
  const float* Lw  = (const float*)d_in[9];
  const float* lbw = (const float*)d_in[10];
  const float* Wpc = (const float*)d_in[11];
  const float* bpc = (const float*)d_in[12];
  const float* Cc  = (const float*)d_in[13];
  const float* cbc = (const float*)d_in[14];
  const float* Mc  = (const float*)d_in[15];
  const float* mbc = (const float*)d_in[16];
  const float* Lcm = (const float*)d_in[17];
  const float* lbc = (const float*)d_in[18];
  const float* Wo  = (const float*)d_in[19];
  const float* bo  = (const float*)d_in[20];
  float* out = (float*)d_out;

  cudaFuncSetAttribute((const void*)k_main, cudaFuncAttributeMaxDynamicSharedMemorySize,
                       SMEM_BYTES);
  cudaFuncSetAttribute((const void*)k_pgm, cudaFuncAttributeMaxDynamicSharedMemorySize,
                       KP_SMEM);
  cudaFuncSetAttribute((const void*)k_comb, cudaFuncAttributeMaxDynamicSharedMemorySize,
                       KC_SMEM);
  cudaFuncSetAttribute((const void*)k_out, cudaFuncAttributeMaxDynamicSharedMemorySize,
                       KO_SMEM);

  k_pre<<<1236,256>>>(dur, phon, Cw, Wpw, Cc, Wpc, bpw, cbw, bpc, cbc, Wo, Lw, Lcm, lbw, lbc, out);
  k_mid<<<400,256>>>();
  k_pgm<<<dim3(2,4,64),256,KP_SMEM>>>();
  k_main<<<dim3(NB,Bn),256,SMEM_BYTES>>>(dur,Mw,mbw,Mc,mbc,out);
  k_comb<<<dim3(8,4,Bn),256,KC_SMEM>>>();
  k_out<<<dim3(125,8),256,KO_SMEM>>>(bo,out);
}

// round 15
// speedup vs baseline: 2.4146x; 1.0569x over previous
#include <cuda_runtime.h>
#include <cuda_bf16.h>
#include <cstdint>
#include <math.h>

typedef unsigned long long ull;

#define Bn 16
#define Dn 256
#define Ln 200
#define Tn 1000
#define TT 16
#define NB 63            // ceil(1000/16)
#define KW 832           // padded K: [q*200+l] (800) | wc (8) | bias (1) | pad (23)
#define WS 208           // w_s plane stride (floats)

#define OFF_MEAN ((size_t)0)
#define OFF_LOG  ((size_t)4096000)
#define OFF_FM   ((size_t)8192000)
#define OFF_FL   ((size_t)8208000)
#define OFF_W    ((size_t)8208016)

// ---------------- device scratch ----------------
__device__ float g_sk[Bn*Ln];
__device__ int   g_plen[Bn];
__device__ int   g_flen[Bn];
__device__ float g_phonT[(size_t)Bn*Ln*Dn];          // [b][l][d] f32 (conv)
__device__ unsigned short g_phbf_hi[(size_t)Bn*Ln*Dn];  // bf16 split of phonT
__device__ unsigned short g_phbf_lo[(size_t)Bn*Ln*Dn];
__device__ unsigned short g_lwbf_hi[4*Dn*Dn];        // LwT [q][d][dd] bf16
__device__ unsigned short g_lwbf_lo[4*Dn*Dn];
__device__ float g_hw[(size_t)Bn*Ln*8];
__device__ float g_hc[(size_t)Bn*Ln*8];
__device__ float g_Ceff[2*8*3*Dn];
__device__ float g_beff[2*8*3];
__device__ unsigned short g_wbf_hi[(size_t)Bn*1024*KW];  // W' [b][t(1024)][k]
__device__ unsigned short g_wbf_lo[(size_t)Bn*1024*KW];
__device__ unsigned short g_pbf_hi[(size_t)Bn*Dn*KW];    // P'T [b][d][k]
__device__ unsigned short g_pbf_lo[(size_t)Bn*Dn*KW];
__device__ unsigned short g_yhi[(size_t)Bn*Tn*Dn];   // bf16 hi of y
__device__ unsigned short g_ylo[(size_t)Bn*Tn*Dn];
__device__ unsigned short g_woThi[512*256];          // bf16 WoT [n][k]
__device__ unsigned short g_woTlo[512*256];

__device__ __forceinline__ float silu_f(float x){ return __fdividef(x, 1.f + __expf(-x)); }

__device__ __forceinline__ uint32_t smem_u32(const void* p){
  uint32_t a;
  asm("{ .reg .u64 t; cvta.to.shared.u64 t, %1; cvt.u32.u64 %0, t; }" : "=r"(a) : "l"(p));
  return a;
}
__device__ __forceinline__ void bf_split(float v, unsigned short& h, unsigned short& l){
  __nv_bfloat16 hb = __float2bfloat16(v);
  h = __bfloat16_as_ushort(hb);
  l = __bfloat16_as_ushort(__float2bfloat16(v - __bfloat162float(hb)));
}

// ---------------- mma.sync / cp.async helpers ----------------
__device__ __forceinline__ void ldsm4(uint32_t& r0, uint32_t& r1, uint32_t& r2, uint32_t& r3,
                                      uint32_t addr){
  asm volatile("ldmatrix.sync.aligned.m8n8.x4.shared.b16 {%0,%1,%2,%3}, [%4];"
    : "=r"(r0), "=r"(r1), "=r"(r2), "=r"(r3) : "r"(addr));
}
__device__ __forceinline__ void mma16816(float* d, const uint32_t* a, uint32_t b0, uint32_t b1){
  asm volatile("mma.sync.aligned.m16n8k16.row.col.f32.bf16.bf16.f32 "
    "{%0,%1,%2,%3},{%4,%5,%6,%7},{%8,%9},{%0,%1,%2,%3};"
    : "+f"(d[0]), "+f"(d[1]), "+f"(d[2]), "+f"(d[3])
    : "r"(a[0]), "r"(a[1]), "r"(a[2]), "r"(a[3]), "r"(b0), "r"(b1));
}
#define CP16(dst,src) asm volatile("cp.async.cg.shared.global [%0],[%1],16;" :: "r"(dst), "l"(src) : "memory")
#define CP_COMMIT()   asm volatile("cp.async.commit_group;" ::: "memory")
#define CP_WAIT1()    asm volatile("cp.async.wait_group 1;" ::: "memory")
#define CP_WAIT0()    asm volatile("cp.async.wait_group 0;" ::: "memory")

// ================= K_PRE =================
// 0..895 transpose(+bf16) | 896..943 ceff | 944..945 beff | 946..961 setup |
// 962..963 WoT | 964..979 P'-extra | 980..1235 LwT split-transpose
__global__ void k_pre(const float* __restrict__ dur, const float* __restrict__ phon,
                      const float* __restrict__ Cw, const float* __restrict__ Wpw,
                      const float* __restrict__ Cc, const float* __restrict__ Wpc,
                      const float* __restrict__ bpw, const float* __restrict__ cbw,
                      const float* __restrict__ bpc, const float* __restrict__ cbc,
                      const float* __restrict__ Wo, const float* __restrict__ Lw,
                      const float* __restrict__ Lcm, const float* __restrict__ lbw,
                      const float* __restrict__ lbc,
                      float* __restrict__ out){
  __shared__ float tile[32][33];
  __shared__ float cs[Dn];
  __shared__ int sfl;
  int bi = blockIdx.x, tid = threadIdx.x;

  if (bi < 896){
    int l0 = (bi%7)*32, d0 = ((bi/7)%8)*32, b = bi/56;
    int tx = tid&31, ty = tid>>5;
    #pragma unroll
    for (int r=0;r<4;r++){
      int dy = d0+ty+8*r, lx = l0+tx;
      tile[ty+8*r][tx] = (lx<Ln) ? phon[((size_t)b*Dn+dy)*Ln+lx] : 0.f;
    }
    __syncthreads();
    #pragma unroll
    for (int r=0;r<4;r++){
      int ly = l0+ty+8*r, dx = d0+tx;
      if (ly<Ln){
        float v = tile[tx][ty+8*r];
        size_t idx = ((size_t)b*Ln+ly)*Dn+dx;
        g_phonT[idx] = v;
        unsigned short h,l; bf_split(v,h,l);
        g_phbf_hi[idx]=h; g_phbf_lo[idx]=l;
      }
    }
  } else if (bi < 944){
    int idx = bi-896;
    int o = idx&7, k = (idx>>3)%3, which = idx/24;
    const float* C = which? Cc : Cw;
    const float* W = which? Wpc : Wpw;
    cs[tid] = C[(o*Dn+tid)*3+k];
    __syncthreads();
    float acc=0.f;
    #pragma unroll 8
    for (int d=0; d<Dn; d++)
      acc = fmaf(cs[d], W[d*Dn+tid], acc);
    g_Ceff[((which*8+o)*3+k)*Dn + tid] = acc;
  } else if (bi < 946){
    int which = bi-944;
    const float* C = which? Cc: Cw; const float* bp = which? bpc : bpw; const float* cb = which? cbc : cbw;
    int wp = tid>>5, lane = tid&31;
    for (int pr=wp; pr<24; pr+=8){
      int o = pr/3, var = pr%3;
      int k0 = (var==0)?1:0, k1 = (var==2)?1:2;
      float acc = 0.f;
      #pragma unroll
      for (int i=0;i<8;i++){
        int d = lane + 32*i;
        float bv = bp[d];
        for (int k=k0;k<=k1;k++) acc = fmaf(C[(o*Dn+d)*3+k], bv, acc);
      }
      #pragma unroll
      for (int off=16;off;off>>=1) acc += __shfl_xor_sync(0xffffffffu, acc, off);
      if (lane==0) g_beff[(which*8+o)*3+var] = acc + cb[o];
    }
  } else if (bi < 962){
    int b = bi-946;
    float* s = &tile[0][0];
    if (tid < Ln) s[tid] = dur[b*Ln+tid];
    __syncthreads();
    if (tid == 0){
      float acc = 0.f; int plen = 0;
      for (int l=0;l<Ln;l++){ g_sk[b*Ln+l]=acc; float d=s[l]; acc+=d; if (d>0.f) plen=l+1; }
      g_plen[b]=plen;
      int fl = (int)rintf(acc); fl = fl<0?0:(fl>Tn?Tn:fl);
      g_flen[b]=fl; sfl=fl;
      out[OFF_FL + b] = (float)fl;
    }
    __syncthreads();
    int fl = sfl;
    for (int t=tid;t<Tn;t+=256) out[OFF_FM + (size_t)b*Tn + t] = (t<fl)?1.f:0.f;
  } else if (bi < 964){
    // WoT hi/lo split
    int n = (bi-962)*256 + tid;
    for (int kc=0;kc<32;kc++){
      __align__(16) unsigned short h8[8];
      __align__(16) unsigned short l8[8];
      #pragma unroll
      for (int j=0;j<8;j++){
        float w = Wo[(size_t)(kc*8+j)*512 + n];
        bf_split(w, h8[j], l8[j]);
      }
      *(uint4*)&g_woThi[n*256 + kc*8] = *(uint4*)h8;
      *(uint4*)&g_woTlo[n*256 + kc*8] = *(uint4*)l8;
    }
  } else if (bi < 980){
    // P' extra rows: k=800..807 = Lc, k=808 = lbw+lbc, 809..831 = 0
    int b = bi-964;
    size_t base = ((size_t)b*Dn + tid)*KW;
    #pragma unroll
    for (int i=0;i<8;i++){
      unsigned short h,l; bf_split(Lcm[i*Dn+tid], h, l);
      g_pbf_hi[base+800+i]=h; g_pbf_lo[base+800+i]=l;
    }
    {
      unsigned short h,l; bf_split(lbw[tid]+lbc[tid], h, l);
      g_pbf_hi[base+808]=h; g_pbf_lo[base+808]=l;
    }
    for (int k=809;k<KW;k++){ g_pbf_hi[base+k]=0; g_pbf_lo[base+k]=0; }
  } else {
    // LwT split-transpose: LwT[q][d][dd] = Lw[q*256+dd][d]
    int idx = bi-980;            // 0..255
    int q = idx>>6;
    int rem = idx&63;
    int dd0 = (rem&7)*32;
    int d0  = (rem>>3)*32;
    int tx = tid&31, ty = tid>>5;
    #pragma unroll
    for (int r=0;r<4;r++)
      tile[ty+8*r][tx] = Lw[(size_t)(q*256 + dd0+ty+8*r)*Dn + d0+tx];
    __syncthreads();
    #pragma unroll
    for (int r=0;r<4;r++){
      float v = tile[tx][ty+8*r];
      unsigned short h,l; bf_split(v,h,l);
      size_t o = ((size_t)q*Dn + d0+ty+8*r)*Dn + dd0+tx;
      g_lwbf_hi[o]=h; g_lwbf_lo[o]=l;
    }
  }
}

// ================= K_MID: conv only =================
__global__ void k_mid(){
  __shared__ float xs[10*Dn];
  int bi = blockIdx.x, tid = threadIdx.x;
  int b = bi/25, l0 = (bi%25)*8;
  for (int i=tid; i<10*Dn; i+=256){
    int r = i>>8, dp = i&255, col = l0-1+r;
    xs[r*Dn+dp] = (col>=0 && col<Ln) ? g_phonT[((size_t)b*Ln+col)*Dn+dp] : 0.f;
  }
  __syncthreads();
  int warp = tid>>5, lane = tid&31;
  int l = l0 + warp;
  int plen = g_plen[b];
  for (int idx=0; idx<16; idx++){
    int which = idx>>3, o = idx&7;
    const float* ce = g_Ceff + ((which*8+o)*3)*Dn;
    float acc = 0.f;
    for (int i=lane; i<3*Dn; i+=32){
      int k = i>>8, dp = i&255;
      acc = fmaf(ce[k*Dn+dp], xs[((l-l0)+k)*Dn+dp], acc);
    }
    #pragma unroll
    for (int off=16; off; off>>=1) acc += __shfl_xor_sync(0xffffffffu, acc, off);
    if (lane==0){
      int var = (l==0)?0:((l==Ln-1)?2:1);
      float h = silu_f(acc + g_beff[(which*8+o)*3+var]);
      h = (l < plen) ? h : 0.f;
      float* dst = which ? g_hc : g_hw;
      dst[((size_t)b*Ln+l)*8 + o] = h;
    }
  }
}

// ================= K_PGM: P'[d][q*200+l] = LwT[q] @ phonT[b]  (mma, hi/lo x3) =================
#define KP_ST 49152
#define KP_SMEM 98304

__global__ __launch_bounds__(256,2) void k_pgm(){
  extern __shared__ float smf[];
  char* smc = (char*)smf;
  uint32_t sb = smem_u32(smc);
  int tid = threadIdx.x, wid = tid>>5, lane = tid&31;
  int mtile = blockIdx.x, ntile = blockIdx.y;
  int b = blockIdx.z>>2, q = blockIdx.z&3;

  float acc[2][4][4];
  #pragma unroll
  for (int mt=0;mt<2;mt++)
    #pragma unroll
    for (int ng=0;ng<4;ng++){ acc[mt][ng][0]=0.f; acc[mt][ng][1]=0.f; acc[mt][ng][2]=0.f; acc[mt][ng][3]=0.f; }

  int m0 = (wid&3)*32, n0 = (wid>>2)*32;

  const uint4* aH_g = ((const uint4*)g_lwbf_hi) + (size_t)(q*Dn + mtile*128)*32;
  const uint4* aL_g = ((const uint4*)g_lwbf_lo) + (size_t)(q*Dn + mtile*128)*32;
  const uint4* bH_g = ((const uint4*)g_phbf_hi) + (size_t)(b*Ln)*32;
  const uint4* bL_g = ((const uint4*)g_phbf_lo) + (size_t)(b*Ln)*32;

  int srow = tid>>3, sch = tid&7;
  uint32_t soff = (uint32_t)(srow*128 + ((sch ^ (srow&7))<<4));

  #define KP_ISSUE(c, s) do{                                              \
    uint32_t base_ = sb + (uint32_t)(s)*KP_ST;                            \
    _Pragma("unroll")                                                     \
    for (int i_=0;i_<4;i_++){                                             \
      uint32_t off_ = soff + (uint32_t)(i_*32*128);                       \
      size_t g_ = (size_t)(srow + i_*32)*32 + (c)*8 + sch;                \
      CP16(base_ + off_,         aH_g + g_);                              \
      CP16(base_ + 16384 + off_, aL_g + g_);                              \
    }                                                                     \
    _Pragma("unroll")                                                     \
    for (int i_=0;i_<2;i_++){                                             \
      uint32_t off_ = soff + (uint32_t)(i_*32*128);                       \
      int lr_ = ntile*64 + srow + i_*32; if (lr_ > Ln-1) lr_ = Ln-1;      \
      size_t g_ = (size_t)lr_*32 + (c)*8 + sch;                           \
      CP16(base_ + 32768 + off_, bH_g + g_);                              \
      CP16(base_ + 40960 + off_, bL_g + g_);                              \
    }                                                                     \
    CP_COMMIT();                                                          \
  }while(0)

  KP_ISSUE(0, 0);
  for (int c=0;c<4;c++){
    int s = c & 1;
    if (c+1 < 4){ KP_ISSUE(c+1, s^1); CP_WAIT1(); }
    else        { CP_WAIT0(); }
    __syncthreads();
    uint32_t stb = sb + (uint32_t)s*KP_ST;
    #pragma unroll
    for (int kk=0;kk<4;kk++){
      uint32_t aH[2][4], aL[2][4];
      #pragma unroll
      for (int mt=0;mt<2;mt++){
        int arow = m0 + mt*16 + (lane&15);
        uint32_t aoff = (uint32_t)(arow*128 + (((kk*2 + (lane>>4)) ^ (arow&7))<<4));
        ldsm4(aH[mt][0],aH[mt][1],aH[mt][2],aH[mt][3], stb + aoff);
        ldsm4(aL[mt][0],aL[mt][1],aL[mt][2],aL[mt][3], stb + 16384 + aoff);
      }
      #pragma unroll
      for (int g2=0;g2<2;g2++){
        int nrow = n0 + g2*16 + ((lane>>4)<<3) + (lane&7);
        uint32_t boff = (uint32_t)(nrow*128 + (((kk*2 + ((lane>>3)&1)) ^ (nrow&7))<<4));
        uint32_t bh0,bh1,bh2,bh3, bl0,bl1,bl2,bl3;
        ldsm4(bh0,bh1,bh2,bh3, stb + 32768 + boff);
        ldsm4(bl0,bl1,bl2,bl3, stb + 40960 + boff);
        #pragma unroll
        for (int mt=0;mt<2;mt++){
          mma16816(acc[mt][g2*2],   aH[mt], bh0, bh1);
          mma16816(acc[mt][g2*2],   aL[mt], bh0, bh1);
          mma16816(acc[mt][g2*2],   aH[mt], bl0, bl1);
          mma16816(acc[mt][g2*2+1], aH[mt], bh2, bh3);
          mma16816(acc[mt][g2*2+1], aL[mt], bh2, bh3);
          mma16816(acc[mt][g2*2+1], aH[mt], bl2, bl3);
        }
      }
    }
    __syncthreads();
  }

  // epilogue: P'[b][d][q*200+col] bf16 hi/lo (guard col < 200)
  #pragma unroll
  for (int mt=0;mt<2;mt++){
    #pragma unroll
    for (int ng=0;ng<4;ng++){
      int col = ntile*64 + n0 + ng*8 + 2*(lane&3);
      if (col < Ln){
        #pragma unroll
        for (int half=0;half<2;half++){
          int d = mtile*128 + m0 + mt*16 + (lane>>2) + half*8;
          size_t idx = ((size_t)(b*Dn) + d)*KW + q*200 + col;
          unsigned short h0,l0,h1,l1;
          bf_split(acc[mt][ng][half*2+0], h0, l0);
          bf_split(acc[mt][ng][half*2+1], h1, l1);
          ushort2 hh; hh.x=h0; hh.y=h1;
          ushort2 ll; ll.x=l0; ll.y=l1;
          *(ushort2*)&g_pbf_hi[idx] = hh;
          *(ushort2*)&g_pbf_lo[idx] = ll;
        }
      }
    }
  }
}

// ================= K_MAIN: phases 1-2 with fused W' export =================
// dyn smem (floats): w_s [64][WS=208] 0..13312 | sk 13312..13512 | bc 13512..13912 |
//                    wc 13912..14040 | prm 14040..14106
#define SMEM_BYTES 56424

__global__ __launch_bounds__(256,3) void k_main(
  const float* __restrict__ dur,
  const float* __restrict__ Mw, const float* __restrict__ mbw,
  const float* __restrict__ Mc, const float* __restrict__ mbc,
  float* __restrict__ out)
{
  extern __shared__ float sm[];
  float* w_s  = sm;                      // plane (t*4+q): w_s[(t*4+q)*WS + l]
  float* sk_s = sm + 13312;
  float* bc_s = sm + 13512;
  float* wc_s = sm + 13912;
  float* prm  = sm + 14040;

  int b = blockIdx.y;
  int t0 = blockIdx.x * TT;
  int tid = threadIdx.x;
  int plen = g_plen[b], flen = g_flen[b];
  bool active = (t0 < flen);

  if (active){
    if (tid < 40)      prm[tid] = Mw[tid];
    else if (tid < 44) prm[tid] = mbw[tid-40];
    else if (tid < 64) prm[tid] = Mc[tid-44];
    else if (tid < 66) prm[tid] = mbc[tid-64];
    __syncthreads();

    // ---- phase 1: conflict-free scalar plane stores ----
    if (tid < Ln){
      int l = tid;
      float dv = dur[b*Ln + l];
      float sk = g_sk[b*Ln + l];
      sk_s[l] = sk;
      const float* hwp = g_hw + ((size_t)b*Ln+l)*8;
      const float* hcp = g_hc + ((size_t)b*Ln+l)*8;
      float bw[4], bc[2];
      #pragma unroll
      for (int q=0;q<4;q++){
        float a = prm[40+q] + dv*prm[4+q];
        #pragma unroll
        for (int j=0;j<8;j++) a = fmaf(hwp[j], prm[(2+j)*4+q], a);
        bw[q]=a;
      }
      #pragma unroll
      for (int p=0;p<2;p++){
        float a = prm[64+p] + dv*prm[46+p];
        #pragma unroll
        for (int j=0;j<8;j++) a = fmaf(hcp[j], prm[44+(2+j)*2+p], a);
        bc[p]=a;
      }
      bc_s[2*l]   = bc[0];
      bc_s[2*l+1] = bc[1];
      bool lv = l < plen;
      #pragma unroll
      for (int t=0;t<TT;t++){
        int tt = t0+t;
        float4 av = {0.f,0.f,0.f,0.f};
        if (lv && tt < flen){
          float S = (float)(tt+1) - sk;
          av.x = silu_f(fmaf(S, prm[0], bw[0]));
          av.y = silu_f(fmaf(S, prm[1], bw[1]));
          av.z = silu_f(fmaf(S, prm[2], bw[2]));
          av.w = silu_f(fmaf(S, prm[3], bw[3]));
        }
        float* wp_ = w_s + (t*4)*WS + l;
        wp_[0]      = av.x;
        wp_[WS]     = av.y;
        wp_[2*WS]   = av.z;
        wp_[3*WS]   = av.w;
      }
    }
    __syncthreads();

    // ---- phase 2: softmax + f32 w out + bf16 W' export + wc reduce ----
    {
      int wp = tid>>5, lane = tid&31;
      float mc0 = prm[44], mc1 = prm[45];
      const size_t qs = (size_t)Tn*Ln;
      for (int t=wp; t<TT; t+=8){
        int tt = t0+t;
        if (tt >= Tn) continue;
        size_t wb = OFF_W + ((size_t)(b*4)*Tn + tt)*Ln;
        size_t rw = ((size_t)(b*1024)+tt)*KW;
        if (tt >= flen){
          for (int l=lane; l<Ln; l+=32){
            out[wb+l]=0.f; out[wb+qs+l]=0.f; out[wb+2*qs+l]=0.f; out[wb+3*qs+l]=0.f;
          }
          for (int k=lane; k<KW; k+=32){ g_wbf_hi[rw+k]=0; g_wbf_lo[rw+k]=0; }
          if (lane<8) wc_s[t*8+lane]=0.f;
          continue;
        }
        const float* wp0 = w_s + (t*4)*WS;
        float4 wv[7];
        float m0=-3e38f,m1=-3e38f,m2=-3e38f,m3=-3e38f;
        #pragma unroll
        for (int i=0;i<7;i++){
          int l = lane + 32*i;
          if (l < plen){
            wv[i].x = wp0[l];
            wv[i].y = wp0[WS+l];
            wv[i].z = wp0[2*WS+l];
            wv[i].w = wp0[3*WS+l];
            m0=fmaxf(m0,wv[i].x); m1=fmaxf(m1,wv[i].y); m2=fmaxf(m2,wv[i].z); m3=fmaxf(m3,wv[i].w);
          }
        }
        #pragma unroll
        for (int off=16;off;off>>=1){
          m0=fmaxf(m0,__shfl_xor_sync(0xffffffffu,m0,off));
          m1=fmaxf(m1,__shfl_xor_sync(0xffffffffu,m1,off));
          m2=fmaxf(m2,__shfl_xor_sync(0xffffffffu,m2,off));
          m3=fmaxf(m3,__shfl_xor_sync(0xffffffffu,m3,off));
        }
        float s0=0.f,s1=0.f,s2=0.f,s3=0.f;
        #pragma unroll
        for (int i=0;i<7;i++){
          int l = lane + 32*i;
          if (l < plen){
            wv[i].x=__expf(wv[i].x-m0); wv[i].y=__expf(wv[i].y-m1);
            wv[i].z=__expf(wv[i].z-m2); wv[i].w=__expf(wv[i].w-m3);
            s0+=wv[i].x; s1+=wv[i].y; s2+=wv[i].z; s3+=wv[i].w;
          }
        }
        #pragma unroll
        for (int off=16;off;off>>=1){
          s0+=__shfl_xor_sync(0xffffffffu,s0,off);
          s1+=__shfl_xor_sync(0xffffffffu,s1,off);
          s2+=__shfl_xor_sync(0xffffffffu,s2,off);
          s3+=__shfl_xor_sync(0xffffffffu,s3,off);
        }
        float i0=__fdividef(1.f,s0), i1=__fdividef(1.f,s1), i2=__fdividef(1.f,s2), i3=__fdividef(1.f,s3);
        float Sb = (float)(tt+1);
        float r0=0.f,r1=0.f,r2=0.f,r3=0.f,r4=0.f,r5=0.f,r6=0.f,r7=0.f;
        #pragma unroll
        for (int i=0;i<7;i++){
          int l = lane + 32*i;
          if (l < plen){
            float4 v; v.x=wv[i].x*i0; v.y=wv[i].y*i1; v.z=wv[i].z*i2; v.w=wv[i].w*i3;
            out[wb+l]=v.x; out[wb+qs+l]=v.y; out[wb+2*qs+l]=v.z; out[wb+3*qs+l]=v.w;
            unsigned short h,lo;
            bf_split(v.x,h,lo); g_wbf_hi[rw+l]=h;     g_wbf_lo[rw+l]=lo;
            bf_split(v.y,h,lo); g_wbf_hi[rw+200+l]=h; g_wbf_lo[rw+200+l]=lo;
            bf_split(v.z,h,lo); g_wbf_hi[rw+400+l]=h; g_wbf_lo[rw+400+l]=lo;
            bf_split(v.w,h,lo); g_wbf_hi[rw+600+l]=h; g_wbf_lo[rw+600+l]=lo;
            float S = Sb - sk_s[l];
            float cx = silu_f(fmaf(S, mc0, bc_s[2*l]));
            float cy = silu_f(fmaf(S, mc1, bc_s[2*l+1]));
            r0=fmaf(v.x,cx,r0); r1=fmaf(v.x,cy,r1);
            r2=fmaf(v.y,cx,r2); r3=fmaf(v.y,cy,r3);
            r4=fmaf(v.z,cx,r4); r5=fmaf(v.z,cy,r5);
            r6=fmaf(v.w,cx,r6); r7=fmaf(v.w,cy,r7);
          } else if (l < Ln){
            out[wb+l]=0.f; out[wb+qs+l]=0.f; out[wb+2*qs+l]=0.f; out[wb+3*qs+l]=0.f;
            g_wbf_hi[rw+l]=0;     g_wbf_lo[rw+l]=0;
            g_wbf_hi[rw+200+l]=0; g_wbf_lo[rw+200+l]=0;
            g_wbf_hi[rw+400+l]=0; g_wbf_lo[rw+400+l]=0;
            g_wbf_hi[rw+600+l]=0; g_wbf_lo[rw+600+l]=0;
          }
        }
        #pragma unroll
        for (int off=16;off;off>>=1){
          r0+=__shfl_xor_sync(0xffffffffu,r0,off); r1+=__shfl_xor_sync(0xffffffffu,r1,off);
          r2+=__shfl_xor_sync(0xffffffffu,r2,off); r3+=__shfl_xor_sync(0xffffffffu,r3,off);
          r4+=__shfl_xor_sync(0xffffffffu,r4,off); r5+=__shfl_xor_sync(0xffffffffu,r5,off);
          r6+=__shfl_xor_sync(0xffffffffu,r6,off); r7+=__shfl_xor_sync(0xffffffffu,r7,off);
        }
        if (lane==0){
          wc_s[t*8+0]=r0; wc_s[t*8+1]=r1; wc_s[t*8+2]=r2; wc_s[t*8+3]=r3;
          wc_s[t*8+4]=r4; wc_s[t*8+5]=r5; wc_s[t*8+6]=r6; wc_s[t*8+7]=r7;
        }
      }
    }
    __syncthreads();

    // ---- tail: W' rows k=800..831 (wc, bias, pad) ----
    for (int x=tid; x<TT*32; x+=256){
      int t = x>>5, j = x&31;
      int tt = t0+t;
      if (tt >= Tn) continue;
      float v = 0.f;
      if (j < 8)      v = wc_s[t*8+j];
      else if (j == 8) v = (tt < flen) ? 1.f : 0.f;
      unsigned short h,lo; bf_split(v,h,lo);
      size_t rw = ((size_t)(b*1024)+tt)*KW;
      g_wbf_hi[rw+800+j]=h; g_wbf_lo[rw+800+j]=lo;
    }
  } else {
    // inactive: zero w planes + zero W' rows
    int wp = tid>>5, lane = tid&31;
    const size_t qs = (size_t)Tn*Ln;
    for (int t=wp; t<TT; t+=8){
      int tt = t0+t;
      if (tt >= Tn) continue;
      size_t wb = OFF_W + ((size_t)(b*4)*Tn + tt)*Ln;
      for (int l=lane; l<Ln; l+=32){
        out[wb+l]=0.f; out[wb+qs+l]=0.f; out[wb+2*qs+l]=0.f; out[wb+3*qs+l]=0.f;
      }
    }
    for (int t=0;t<TT;t++){
      int tt = t0+t;
      if (tt >= Tn) break;
      size_t rw = ((size_t)(b*1024)+tt)*KW;
      for (int k=tid;k<KW;k+=256){ g_wbf_hi[rw+k]=0; g_wbf_lo[rw+k]=0; }
    }
  }
}

// ================= K_COMB: Y = W' @ P'  (cp.async double-buffered, M128xN64) =================
#define KC_ST 49152
#define KC_SMEM 98304

__global__ __launch_bounds__(256,2) void k_comb(){
  extern __shared__ float smf[];
  char* smc = (char*)smf;
  uint32_t sb = smem_u32(smc);
  int tid = threadIdx.x, wid = tid>>5, lane = tid&31;
  int mtile = blockIdx.x, ntile = blockIdx.y, b = blockIdx.z;

  if (mtile*128 >= g_flen[b]){
    uint4 z; z.x=0u; z.y=0u; z.z=0u; z.w=0u;
    #pragma unroll
    for (int i=0;i<4;i++){
      int lin = i*256 + tid;
      int r = lin>>3, ch = lin&7;
      int t = mtile*128 + r;
      if (t < Tn){
        size_t row = (size_t)b*Tn + t;
        ((uint4*)(g_yhi + row*Dn + ntile*64))[ch] = z;
        ((uint4*)(g_ylo + row*Dn + ntile*64))[ch] = z;
      }
    }
    return;
  }

  float acc[2][4][4];
  #pragma unroll
  for (int mt=0;mt<2;mt++)
    #pragma unroll
    for (int ng=0;ng<4;ng++){ acc[mt][ng][0]=0.f; acc[mt][ng][1]=0.f; acc[mt][ng][2]=0.f; acc[mt][ng][3]=0.f; }

  int m0 = (wid&3)*32, n0 = (wid>>2)*32;

  const uint4* gwh = (const uint4*)(g_wbf_hi + ((size_t)(b*1024) + (size_t)mtile*128)*KW);
  const uint4* gwl = (const uint4*)(g_wbf_lo + ((size_t)(b*1024) + (size_t)mtile*128)*KW);
  const uint4* gph = (const uint4*)(g_pbf_hi + ((size_t)(b*Dn) + (size_t)ntile*64)*KW);
  const uint4* gpl = (const uint4*)(g_pbf_lo + ((size_t)(b*Dn) + (size_t)ntile*64)*KW);
  const int rs = KW/8;   // 104

  int srow = tid>>3, sch = tid&7;
  uint32_t soff = (uint32_t)(srow*128 + ((sch ^ (srow&7))<<4));

  #define KC_ISSUE(c, s) do{                                              \
    uint32_t base_ = sb + (uint32_t)(s)*KC_ST;                            \
    _Pragma("unroll")                                                     \
    for (int i_=0;i_<4;i_++){                                             \
      uint32_t off_ = soff + (uint32_t)(i_*32*128);                       \
      size_t g_ = (size_t)(srow + i_*32)*rs + (c)*8 + sch;                \
      CP16(base_ + off_,          gwh + g_);                              \
      CP16(base_ + 16384 + off_,  gwl + g_);                              \
    }                                                                     \
    _Pragma("unroll")                                                     \
    for (int i_=0;i_<2;i_++){                                             \
      uint32_t off_ = soff + (uint32_t)(i_*32*128);                       \
      size_t g_ = (size_t)(srow + i_*32)*rs + (c)*8 + sch;                \
      CP16(base_ + 32768 + off_,  gph + g_);                              \
      CP16(base_ + 40960 + off_,  gpl + g_);                              \
    }                                                                     \
    CP_COMMIT();                                                          \
  }while(0)

  KC_ISSUE(0, 0);
  for (int c=0;c<13;c++){
    int s = c & 1;
    if (c+1 < 13){ KC_ISSUE(c+1, s^1); CP_WAIT1(); }
    else         { CP_WAIT0(); }
    __syncthreads();
    uint32_t stb = sb + (uint32_t)s*KC_ST;
    #pragma unroll
    for (int kk=0;kk<4;kk++){
      uint32_t aH[2][4], aL[2][4];
      #pragma unroll
      for (int mt=0;mt<2;mt++){
        int arow = m0 + mt*16 + (lane&15);
        uint32_t aoff = (uint32_t)(arow*128 + (((kk*2 + (lane>>4)) ^ (arow&7))<<4));
        ldsm4(aH[mt][0],aH[mt][1],aH[mt][2],aH[mt][3], stb + aoff);
        ldsm4(aL[mt][0],aL[mt][1],aL[mt][2],aL[mt][3], stb + 16384 + aoff);
      }
      #pragma unroll
      for (int g2=0;g2<2;g2++){
        int nrow = n0 + g2*16 + ((lane>>4)<<3) + (lane&7);
        uint32_t boff = (uint32_t)(nrow*128 + (((kk*2 + ((lane>>3)&1)) ^ (nrow&7))<<4));
        uint32_t bh0,bh1,bh2,bh3, bl0,bl1,bl2,bl3;
        ldsm4(bh0,bh1,bh2,bh3, stb + 32768 + boff);
        ldsm4(bl0,bl1,bl2,bl3, stb + 40960 + boff);
        #pragma unroll
        for (int mt=0;mt<2;mt++){
          mma16816(acc[mt][g2*2],   aH[mt], bh0, bh1);
          mma16816(acc[mt][g2*2],   aL[mt], bh0, bh1);
          mma16816(acc[mt][g2*2],   aH[mt], bl0, bl1);
          mma16816(acc[mt][g2*2+1], aH[mt], bh2, bh3);
          mma16816(acc[mt][g2*2+1], aL[mt], bh2, bh3);
          mma16816(acc[mt][g2*2+1], aH[mt], bl2, bl3);
        }
      }
    }
    __syncthreads();
  }

  #pragma unroll
  for (int mt=0;mt<2;mt++){
    #pragma unroll
    for (int ng=0;ng<4;ng++){
      int d = ntile*64 + n0 + ng*8 + (lane&3)*2;
      #pragma unroll
      for (int half=0;half<2;half++){
        int t = mtile*128 + m0 + mt*16 + (lane>>2) + half*8;
        if (t < Tn){
          size_t row = (size_t)b*Tn + t;
          unsigned short h0,l0,h1,l1;
          bf_split(acc[mt][ng][half*2+0], h0, l0);
          bf_split(acc[mt][ng][half*2+1], h1, l1);
          ushort2 hh; hh.x=h0; hh.y=h1;
          ushort2 ll; ll.x=l0; ll.y=l1;
          *(ushort2*)&g_yhi[row*Dn + d] = hh;
          *(ushort2*)&g_ylo[row*Dn + d] = ll;
        }
      }
    }
  }
}

// ================= K_OUT: out = y @ Wo + bo  (cp.async double-buffered) =================
#define KO_ST 49152
#define KO_SMEM 98304

__global__ __launch_bounds__(256,2) void k_out(const float* __restrict__ bo,
                                               float* __restrict__ out){
  extern __shared__ float smf[];
  char* smc = (char*)smf;
  uint32_t sb = smem_u32(smc);
  int tid = threadIdx.x, wid = tid>>5, lane = tid&31;
  int mtile = blockIdx.x, ntile = blockIdx.y;

  {
    int mstart = mtile*128;
    int b0 = mstart/Tn, b1 = (mstart+127)/Tn;
    int t_start = mstart - b0*Tn;
    bool dead = (t_start >= g_flen[b0]) && (b1==b0 || g_flen[b1]<=0);
    if (dead){
      int r = tid & 127;
      int m = mtile*128 + r;
      int b = m/Tn, t = m - b*Tn;
      size_t plane = (ntile<4)?OFF_MEAN:OFF_LOG;
      int colbase = ntile*64 - ((ntile>=4)?256:0);
      const float* bop = bo + ntile*64;
      for (int i = tid>>7; i<64; i+=2)
        out[plane + ((size_t)(b*Dn + colbase + i))*Tn + t] = bop[i];
      return;
    }
  }

  float acc[2][4][4];
  #pragma unroll
  for (int mt=0;mt<2;mt++)
    #pragma unroll
    for (int ng=0;ng<4;ng++){ acc[mt][ng][0]=0.f; acc[mt][ng][1]=0.f; acc[mt][ng][2]=0.f; acc[mt][ng][3]=0.f; }

  int m0 = (wid&3)*32, n0 = (wid>>2)*32;

  const uint4* aH_g = (const uint4*)(g_yhi + (size_t)(mtile*128)*Dn);
  const uint4* aL_g = (const uint4*)(g_ylo + (size_t)(mtile*128)*Dn);
  const uint4* bH_g = (const uint4*)(g_woThi + (size_t)(ntile*64)*256);
  const uint4* bL_g = (const uint4*)(g_woTlo + (size_t)(ntile*64)*256);

  int srow = tid>>3, sch = tid&7;
  uint32_t soff = (uint32_t)(srow*128 + ((sch ^ (srow&7))<<4));

  #define KO_ISSUE(c, s) do{                                              \
    uint32_t base_ = sb + (uint32_t)(s)*KO_ST;                            \
    _Pragma("unroll")                                                     \
    for (int i_=0;i_<4;i_++){                                             \
      uint32_t off_ = soff + (uint32_t)(i_*32*128);                       \
      size_t g_ = (size_t)(srow + i_*32)*32 + (c)*8 + sch;                \
      CP16(base_ + off_,         aH_g + g_);                              \
      CP16(base_ + 16384 + off_, aL_g + g_);                              \
    }                                                                     \
    _Pragma("unroll")                                                     \
    for (int i_=0;i_<2;i_++){                                             \
      uint32_t off_ = soff + (uint32_t)(i_*32*128);                       \
      size_t g_ = (size_t)(srow + i_*32)*32 + (c)*8 + sch;                \
      CP16(base_ + 32768 + off_, bH_g + g_);                              \
      CP16(base_ + 40960 + off_, bL_g + g_);                              \
    }                                                                     \
    CP_COMMIT();                                                          \
  }while(0)

  KO_ISSUE(0, 0);
  for (int c=0;c<4;c++){
    int s = c & 1;
    if (c+1 < 4){ KO_ISSUE(c+1, s^1); CP_WAIT1(); }
    else        { CP_WAIT0(); }
    __syncthreads();
    uint32_t stb = sb + (uint32_t)s*KO_ST;
    #pragma unroll
    for (int kk=0;kk<4;kk++){
      uint32_t aH[2][4], aL[2][4];
      #pragma unroll
      for (int mt=0;mt<2;mt++){
        int arow = m0 + mt*16 + (lane&15);
        uint32_t aoff = (uint32_t)(arow*128 + (((kk*2 + (lane>>4)) ^ (arow&7))<<4));
        ldsm4(aH[mt][0],aH[mt][1],aH[mt][2],aH[mt][3], stb + aoff);
        ldsm4(aL[mt][0],aL[mt][1],aL[mt][2],aL[mt][3], stb + 16384 + aoff);
      }
      #pragma unroll
      for (int g2=0;g2<2;g2++){
        int nrow = n0 + g2*16 + ((lane>>4)<<3) + (lane&7);
        uint32_t boff = (uint32_t)(nrow*128 + (((kk*2 + ((lane>>3)&1)) ^ (nrow&7))<<4));
        uint32_t bh0,bh1,bh2,bh3, bl0,bl1,bl2,bl3;
        ldsm4(bh0,bh1,bh2,bh3, stb + 32768 + boff);
        ldsm4(bl0,bl1,bl2,bl3, stb + 40960 + boff);
        #pragma unroll
        for (int mt=0;mt<2;mt++){
          mma16816(acc[mt][g2*2],   aH[mt], bh0, bh1);
          mma16816(acc[mt][g2*2],   aL[mt], bh0, bh1);
          mma16816(acc[mt][g2*2],   aH[mt], bl0, bl1);
          mma16816(acc[mt][g2*2+1], aH[mt], bh2, bh3);
          mma16816(acc[mt][g2*2+1], aL[mt], bh2, bh3);
          mma16816(acc[mt][g2*2+1], aH[mt], bl2, bl3);
        }
      }
    }
    __syncthreads();
  }

  {
    size_t plane = (ntile < 4) ? OFF_MEAN : OFF_LOG;
    int colbase = ntile*64 - ((ntile>=4)?256:0);
    const float* bop = bo + ntile*64;
    #pragma unroll
    for (int mt=0;mt<2;mt++){
      #pragma unroll
      for (int ng=0;ng<4;ng++){
        int cin = n0 + ng*8 + 2*(lane&3);
        float b0v = bop[cin], b1v = bop[cin+1];
        #pragma unroll
        for (int half=0;half<2;half++){
          int m_g = mtile*128 + m0 + mt*16 + (lane>>2) + half*8;
          int b = m_g / Tn;
          int t = m_g - b*Tn;
          size_t base = plane + ((size_t)(b*Dn + colbase + cin))*Tn + t;
          out[base]      = acc[mt][ng][half*2+0] + b0v;
          out[base + Tn] = acc[mt][ng][half*2+1] + b1v;
        }
      }
    }
  }
}

// ---------------- launcher ----------------
extern "C" void kernel_launch(void* const* d_in, const int* in_sizes, int n_in,
                              void* d_out, int out_size){
  (void)in_sizes; (void)n_in; (void)out_size;
  const float* dur = (const float*)d_in[0];
  const float* phon= (const float*)d_in[1];
  const float* Wpw = (const float*)d_in[3];
  const float* bpw = (const float*)d_in[4];
  const float* Cw  = (const float*)d_in[5];
  const float* cbw = (const float*)d_in[6];
  const float* Mw  = (const float*)d_in[7];
  const float* mbw = (const float*)d_in[8];
  const float* Lw  = (const float*)d_in[9];
  const float* lbw = (const float*)d_in[10];
  const float* Wpc = (const float*)d_in[11];
  const float* bpc = (const float*)d_in[12];
  const float* Cc  = (const float*)d_in[13];
  const float* cbc = (const float*)d_in[14];
  const float* Mc  = (const float*)d_in[15];
  const float* mbc = (const float*)d_in[16];
  const float* Lcm = (const float*)d_in[17];
  const float* lbc = (const float*)d_in[18];
  const float* Wo  = (const float*)d_in[19];
  const float* bo  = (const float*)d_in[20];
  float* out = (float*)d_out;

  cudaFuncSetAttribute((const void*)k_main, cudaFuncAttributeMaxDynamicSharedMemorySize,
                       SMEM_BYTES);
  cudaFuncSetAttribute((const void*)k_pgm, cudaFuncAttributeMaxDynamicSharedMemorySize,
                       KP_SMEM);
  cudaFuncSetAttribute((const void*)k_comb, cudaFuncAttributeMaxDynamicSharedMemorySize,
                       KC_SMEM);
  cudaFuncSetAttribute((const void*)k_out, cudaFuncAttributeMaxDynamicSharedMemorySize,
                       KO_SMEM);

  k_pre<<<1236,256>>>(dur, phon, Cw, Wpw, Cc, Wpc, bpw, cbw, bpc, cbc, Wo, Lw, Lcm, lbw, lbc, out);
  k_mid<<<400,256>>>();
  k_pgm<<<dim3(2,4,64),256,KP_SMEM>>>();
  k_main<<<dim3(NB,Bn),256,SMEM_BYTES>>>(dur,Mw,mbw,Mc,mbc,out);
  k_comb<<<dim3(8,4,Bn),256,KC_SMEM>>>();
  k_out<<<dim3(125,8),256,KO_SMEM>>>(bo,out);
}

// round 16
// speedup vs baseline: 2.9541x; 1.2234x over previous
#include <cuda_runtime.h>
#include <cuda_bf16.h>
#include <cstdint>
#include <math.h>

typedef unsigned long long ull;

#define Bn 16
#define Dn 256
#define Ln 200
#define Tn 1000
#define TT 16
#define NB 63            // ceil(1000/16)
#define KW 832           // padded K: [q*200+l] (800) | wc (8) | bias (1) | pad (23)
#define WS 208           // w_s plane stride (floats)

#define OFF_MEAN ((size_t)0)
#define OFF_LOG  ((size_t)4096000)
#define OFF_FM   ((size_t)8192000)
#define OFF_FL   ((size_t)8208000)
#define OFF_W    ((size_t)8208016)

// ---------------- device scratch ----------------
__device__ float g_sk[Bn*Ln];
__device__ int   g_plen[Bn];
__device__ int   g_flen[Bn];
__device__ float g_phonT[(size_t)Bn*Ln*Dn];          // [b][l][d] f32 (conv)
__device__ unsigned short g_phbf_hi[(size_t)Bn*Ln*Dn];  // bf16 split of phonT
__device__ unsigned short g_phbf_lo[(size_t)Bn*Ln*Dn];
__device__ unsigned short g_lwbf_hi[4*Dn*Dn];        // LwT [q][d][dd] bf16
__device__ unsigned short g_lwbf_lo[4*Dn*Dn];
__device__ float g_hw[(size_t)Bn*Ln*8];
__device__ float g_hc[(size_t)Bn*Ln*8];
__device__ float g_Ceff[2*8*3*Dn];
__device__ float g_beff[2*8*3];
__device__ unsigned short g_wbf_hi[(size_t)Bn*1024*KW];  // W' [b][t(1024)][k]
__device__ unsigned short g_wbf_lo[(size_t)Bn*1024*KW];
__device__ unsigned short g_pbf_hi[(size_t)Bn*Dn*KW];    // P'T [b][d][k]
__device__ unsigned short g_pbf_lo[(size_t)Bn*Dn*KW];
__device__ unsigned short g_yhi[(size_t)Bn*Tn*Dn];   // bf16 hi of y
__device__ unsigned short g_ylo[(size_t)Bn*Tn*Dn];
__device__ unsigned short g_woThi[512*256];          // bf16 WoT [n][k]
__device__ unsigned short g_woTlo[512*256];

__device__ __forceinline__ float silu_f(float x){ return __fdividef(x, 1.f + __expf(-x)); }

__device__ __forceinline__ uint32_t smem_u32(const void* p){
  uint32_t a;
  asm("{ .reg .u64 t; cvta.to.shared.u64 t, %1; cvt.u32.u64 %0, t; }" : "=r"(a) : "l"(p));
  return a;
}
__device__ __forceinline__ void bf_split(float v, unsigned short& h, unsigned short& l){
  __nv_bfloat16 hb = __float2bfloat16(v);
  h = __bfloat16_as_ushort(hb);
  l = __bfloat16_as_ushort(__float2bfloat16(v - __bfloat162float(hb)));
}

// ---------------- mma.sync / cp.async helpers ----------------
__device__ __forceinline__ void ldsm4(uint32_t& r0, uint32_t& r1, uint32_t& r2, uint32_t& r3,
                                      uint32_t addr){
  asm volatile("ldmatrix.sync.aligned.m8n8.x4.shared.b16 {%0,%1,%2,%3}, [%4];"
    : "=r"(r0), "=r"(r1), "=r"(r2), "=r"(r3) : "r"(addr));
}
__device__ __forceinline__ void mma16816(float* d, const uint32_t* a, uint32_t b0, uint32_t b1){
  asm volatile("mma.sync.aligned.m16n8k16.row.col.f32.bf16.bf16.f32 "
    "{%0,%1,%2,%3},{%4,%5,%6,%7},{%8,%9},{%0,%1,%2,%3};"
    : "+f"(d[0]), "+f"(d[1]), "+f"(d[2]), "+f"(d[3])
    : "r"(a[0]), "r"(a[1]), "r"(a[2]), "r"(a[3]), "r"(b0), "r"(b1));
}
#define CP16(dst,src) asm volatile("cp.async.cg.shared.global [%0],[%1],16;" :: "r"(dst), "l"(src) : "memory")
#define CP_COMMIT()   asm volatile("cp.async.commit_group;" ::: "memory")
#define CP_WAIT1()    asm volatile("cp.async.wait_group 1;" ::: "memory")
#define CP_WAIT0()    asm volatile("cp.async.wait_group 0;" ::: "memory")

// ================= K_PRE =================
// 0..895 transpose(+bf16) | 896..943 ceff | 944..945 beff | 946..961 setup |
// 962..963 WoT | 964..979 P'-extra | 980..1235 LwT split-transpose
__global__ void k_pre(const float* __restrict__ dur, const float* __restrict__ phon,
                      const float* __restrict__ Cw, const float* __restrict__ Wpw,
                      const float* __restrict__ Cc, const float* __restrict__ Wpc,
                      const float* __restrict__ bpw, const float* __restrict__ cbw,
                      const float* __restrict__ bpc, const float* __restrict__ cbc,
                      const float* __restrict__ Wo, const float* __restrict__ Lw,
                      const float* __restrict__ Lcm, const float* __restrict__ lbw,
                      const float* __restrict__ lbc,
                      float* __restrict__ out){
  __shared__ float tile[32][33];
  __shared__ float cs[Dn];
  __shared__ int sfl;
  int bi = blockIdx.x, tid = threadIdx.x;

  if (bi < 896){
    int l0 = (bi%7)*32, d0 = ((bi/7)%8)*32, b = bi/56;
    int tx = tid&31, ty = tid>>5;
    #pragma unroll
    for (int r=0;r<4;r++){
      int dy = d0+ty+8*r, lx = l0+tx;
      tile[ty+8*r][tx] = (lx<Ln) ? phon[((size_t)b*Dn+dy)*Ln+lx] : 0.f;
    }
    __syncthreads();
    #pragma unroll
    for (int r=0;r<4;r++){
      int ly = l0+ty+8*r, dx = d0+tx;
      if (ly<Ln){
        float v = tile[tx][ty+8*r];
        size_t idx = ((size_t)b*Ln+ly)*Dn+dx;
        g_phonT[idx] = v;
        unsigned short h,l; bf_split(v,h,l);
        g_phbf_hi[idx]=h; g_phbf_lo[idx]=l;
      }
    }
  } else if (bi < 944){
    int idx = bi-896;
    int o = idx&7, k = (idx>>3)%3, which = idx/24;
    const float* C = which? Cc : Cw;
    const float* W = which? Wpc : Wpw;
    cs[tid] = C[(o*Dn+tid)*3+k];
    __syncthreads();
    float acc=0.f;
    #pragma unroll 8
    for (int d=0; d<Dn; d++)
      acc = fmaf(cs[d], W[d*Dn+tid], acc);
    g_Ceff[((which*8+o)*3+k)*Dn + tid] = acc;
  } else if (bi < 946){
    int which = bi-944;
    const float* C = which? Cc: Cw; const float* bp = which? bpc : bpw; const float* cb = which? cbc : cbw;
    int wp = tid>>5, lane = tid&31;
    for (int pr=wp; pr<24; pr+=8){
      int o = pr/3, var = pr%3;
      int k0 = (var==0)?1:0, k1 = (var==2)?1:2;
      float acc = 0.f;
      #pragma unroll
      for (int i=0;i<8;i++){
        int d = lane + 32*i;
        float bv = bp[d];
        for (int k=k0;k<=k1;k++) acc = fmaf(C[(o*Dn+d)*3+k], bv, acc);
      }
      #pragma unroll
      for (int off=16;off;off>>=1) acc += __shfl_xor_sync(0xffffffffu, acc, off);
      if (lane==0) g_beff[(which*8+o)*3+var] = acc + cb[o];
    }
  } else if (bi < 962){
    int b = bi-946;
    float* s = &tile[0][0];
    if (tid < Ln) s[tid] = dur[b*Ln+tid];
    __syncthreads();
    if (tid == 0){
      float acc = 0.f; int plen = 0;
      for (int l=0;l<Ln;l++){ g_sk[b*Ln+l]=acc; float d=s[l]; acc+=d; if (d>0.f) plen=l+1; }
      g_plen[b]=plen;
      int fl = (int)rintf(acc); fl = fl<0?0:(fl>Tn?Tn:fl);
      g_flen[b]=fl; sfl=fl;
      out[OFF_FL + b] = (float)fl;
    }
    __syncthreads();
    int fl = sfl;
    for (int t=tid;t<Tn;t+=256) out[OFF_FM + (size_t)b*Tn + t] = (t<fl)?1.f:0.f;
  } else if (bi < 964){
    // WoT hi/lo split
    int n = (bi-962)*256 + tid;
    for (int kc=0;kc<32;kc++){
      __align__(16) unsigned short h8[8];
      __align__(16) unsigned short l8[8];
      #pragma unroll
      for (int j=0;j<8;j++){
        float w = Wo[(size_t)(kc*8+j)*512 + n];
        bf_split(w, h8[j], l8[j]);
      }
      *(uint4*)&g_woThi[n*256 + kc*8] = *(uint4*)h8;
      *(uint4*)&g_woTlo[n*256 + kc*8] = *(uint4*)l8;
    }
  } else if (bi < 980){
    // P' extra rows: k=800..807 = Lc, k=808 = lbw+lbc, 809..831 = 0
    int b = bi-964;
    size_t base = ((size_t)b*Dn + tid)*KW;
    #pragma unroll
    for (int i=0;i<8;i++){
      unsigned short h,l; bf_split(Lcm[i*Dn+tid], h, l);
      g_pbf_hi[base+800+i]=h; g_pbf_lo[base+800+i]=l;
    }
    {
      unsigned short h,l; bf_split(lbw[tid]+lbc[tid], h, l);
      g_pbf_hi[base+808]=h; g_pbf_lo[base+808]=l;
    }
    for (int k=809;k<KW;k++){ g_pbf_hi[base+k]=0; g_pbf_lo[base+k]=0; }
  } else {
    // LwT split-transpose: LwT[q][d][dd] = Lw[q*256+dd][d]
    int idx = bi-980;            // 0..255
    int q = idx>>6;
    int rem = idx&63;
    int dd0 = (rem&7)*32;
    int d0  = (rem>>3)*32;
    int tx = tid&31, ty = tid>>5;
    #pragma unroll
    for (int r=0;r<4;r++)
      tile[ty+8*r][tx] = Lw[(size_t)(q*256 + dd0+ty+8*r)*Dn + d0+tx];
    __syncthreads();
    #pragma unroll
    for (int r=0;r<4;r++){
      float v = tile[tx][ty+8*r];
      unsigned short h,l; bf_split(v,h,l);
      size_t o = ((size_t)q*Dn + d0+ty+8*r)*Dn + dd0+tx;
      g_lwbf_hi[o]=h; g_lwbf_lo[o]=l;
    }
  }
}

// ================= K_MIDP: conv (0..399) + P' GEMM (400..911) in one launch =================
// pgm stage (64 k): A_hi 16K | A_lo 16K | B_hi 8K | B_lo 8K = 48KB; x2 = 96KB
#define KP_ST 49152
#define KP_SMEM 98304

__global__ __launch_bounds__(256,2) void k_midp(){
  extern __shared__ float smf[];
  char* smc = (char*)smf;
  int bi = blockIdx.x, tid = threadIdx.x;

  if (bi < 400){
    // ---- conv+silu -> h_w, h_c ----
    float* xs = smf;
    int b = bi/25, l0 = (bi%25)*8;
    for (int i=tid; i<10*Dn; i+=256){
      int r = i>>8, dp = i&255, col = l0-1+r;
      xs[r*Dn+dp] = (col>=0 && col<Ln) ? g_phonT[((size_t)b*Ln+col)*Dn+dp] : 0.f;
    }
    __syncthreads();
    int warp = tid>>5, lane = tid&31;
    int l = l0 + warp;
    int plen = g_plen[b];
    for (int idx=0; idx<16; idx++){
      int which = idx>>3, o = idx&7;
      const float* ce = g_Ceff + ((which*8+o)*3)*Dn;
      float acc = 0.f;
      for (int i=lane; i<3*Dn; i+=32){
        int k = i>>8, dp = i&255;
        acc = fmaf(ce[k*Dn+dp], xs[((l-l0)+k)*Dn+dp], acc);
      }
      #pragma unroll
      for (int off=16; off; off>>=1) acc += __shfl_xor_sync(0xffffffffu, acc, off);
      if (lane==0){
        int var = (l==0)?0:((l==Ln-1)?2:1);
        float h = silu_f(acc + g_beff[(which*8+o)*3+var]);
        h = (l < plen) ? h : 0.f;
        float* dst = which ? g_hc : g_hw;
        dst[((size_t)b*Ln+l)*8 + o] = h;
      }
    }
    return;
  }

  // ---- P' GEMM: P'[d][q*200+l] = LwT[q] @ phonT[b] ----
  uint32_t sb = smem_u32(smc);
  int wid = tid>>5, lane = tid&31;
  int pidx = bi - 400;                 // 0..511
  int mtile = pidx & 1;
  int ntile = (pidx>>1) & 3;
  int bz = pidx >> 3;                  // 0..63
  int b = bz>>2, q = bz&3;

  float acc[2][4][4];
  #pragma unroll
  for (int mt=0;mt<2;mt++)
    #pragma unroll
    for (int ng=0;ng<4;ng++){ acc[mt][ng][0]=0.f; acc[mt][ng][1]=0.f; acc[mt][ng][2]=0.f; acc[mt][ng][3]=0.f; }

  int m0 = (wid&3)*32, n0 = (wid>>2)*32;

  const uint4* aH_g = ((const uint4*)g_lwbf_hi) + (size_t)(q*Dn + mtile*128)*32;
  const uint4* aL_g = ((const uint4*)g_lwbf_lo) + (size_t)(q*Dn + mtile*128)*32;
  const uint4* bH_g = ((const uint4*)g_phbf_hi) + (size_t)(b*Ln)*32;
  const uint4* bL_g = ((const uint4*)g_phbf_lo) + (size_t)(b*Ln)*32;

  int srow = tid>>3, sch = tid&7;
  uint32_t soff = (uint32_t)(srow*128 + ((sch ^ (srow&7))<<4));

  #define KP_ISSUE(c, s) do{                                              \
    uint32_t base_ = sb + (uint32_t)(s)*KP_ST;                            \
    _Pragma("unroll")                                                     \
    for (int i_=0;i_<4;i_++){                                             \
      uint32_t off_ = soff + (uint32_t)(i_*32*128);                       \
      size_t g_ = (size_t)(srow + i_*32)*32 + (c)*8 + sch;                \
      CP16(base_ + off_,         aH_g + g_);                              \
      CP16(base_ + 16384 + off_, aL_g + g_);                              \
    }                                                                     \
    _Pragma("unroll")                                                     \
    for (int i_=0;i_<2;i_++){                                             \
      uint32_t off_ = soff + (uint32_t)(i_*32*128);                       \
      int lr_ = ntile*64 + srow + i_*32; if (lr_ > Ln-1) lr_ = Ln-1;      \
      size_t g_ = (size_t)lr_*32 + (c)*8 + sch;                           \
      CP16(base_ + 32768 + off_, bH_g + g_);                              \
      CP16(base_ + 40960 + off_, bL_g + g_);                              \
    }                                                                     \
    CP_COMMIT();                                                          \
  }while(0)

  KP_ISSUE(0, 0);
  for (int c=0;c<4;c++){
    int s = c & 1;
    if (c+1 < 4){ KP_ISSUE(c+1, s^1); CP_WAIT1(); }
    else        { CP_WAIT0(); }
    __syncthreads();
    uint32_t stb = sb + (uint32_t)s*KP_ST;
    #pragma unroll
    for (int kk=0;kk<4;kk++){
      uint32_t aH[2][4], aL[2][4];
      #pragma unroll
      for (int mt=0;mt<2;mt++){
        int arow = m0 + mt*16 + (lane&15);
        uint32_t aoff = (uint32_t)(arow*128 + (((kk*2 + (lane>>4)) ^ (arow&7))<<4));
        ldsm4(aH[mt][0],aH[mt][1],aH[mt][2],aH[mt][3], stb + aoff);
        ldsm4(aL[mt][0],aL[mt][1],aL[mt][2],aL[mt][3], stb + 16384 + aoff);
      }
      #pragma unroll
      for (int g2=0;g2<2;g2++){
        int nrow = n0 + g2*16 + ((lane>>4)<<3) + (lane&7);
        uint32_t boff = (uint32_t)(nrow*128 + (((kk*2 + ((lane>>3)&1)) ^ (nrow&7))<<4));
        uint32_t bh0,bh1,bh2,bh3, bl0,bl1,bl2,bl3;
        ldsm4(bh0,bh1,bh2,bh3, stb + 32768 + boff);
        ldsm4(bl0,bl1,bl2,bl3, stb + 40960 + boff);
        #pragma unroll
        for (int mt=0;mt<2;mt++){
          mma16816(acc[mt][g2*2],   aH[mt], bh0, bh1);
          mma16816(acc[mt][g2*2],   aL[mt], bh0, bh1);
          mma16816(acc[mt][g2*2],   aH[mt], bl0, bl1);
          mma16816(acc[mt][g2*2+1], aH[mt], bh2, bh3);
          mma16816(acc[mt][g2*2+1], aL[mt], bh2, bh3);
          mma16816(acc[mt][g2*2+1], aH[mt], bl2, bl3);
        }
      }
    }
    __syncthreads();
  }

  // epilogue: P'[b][d][q*200+col] (guard col < 200)
  #pragma unroll
  for (int mt=0;mt<2;mt++){
    #pragma unroll
    for (int ng=0;ng<4;ng++){
      int col = ntile*64 + n0 + ng*8 + 2*(lane&3);
      if (col < Ln){
        #pragma unroll
        for (int half=0;half<2;half++){
          int d = mtile*128 + m0 + mt*16 + (lane>>2) + half*8;
          size_t idx = ((size_t)(b*Dn) + d)*KW + q*200 + col;
          unsigned short h0,l0,h1,l1;
          bf_split(acc[mt][ng][half*2+0], h0, l0);
          bf_split(acc[mt][ng][half*2+1], h1, l1);
          ushort2 hh; hh.x=h0; hh.y=h1;
          ushort2 ll; ll.x=l0; ll.y=l1;
          *(ushort2*)&g_pbf_hi[idx] = hh;
          *(ushort2*)&g_pbf_lo[idx] = ll;
        }
      }
    }
  }
}

// ================= K_MAIN: phases 1-2 with fused W' export =================
// dyn smem (floats): w_s [64][WS=208] 0..13312 | sk 13312..13512 | bc 13512..13912 |
//                    wc 13912..14040 | prm 14040..14106
#define SMEM_BYTES 56424

__global__ __launch_bounds__(256,3) void k_main(
  const float* __restrict__ dur,
  const float* __restrict__ Mw, const float* __restrict__ mbw,
  const float* __restrict__ Mc, const float* __restrict__ mbc,
  float* __restrict__ out)
{
  extern __shared__ float sm[];
  float* w_s  = sm;
  float* sk_s = sm + 13312;
  float* bc_s = sm + 13512;
  float* wc_s = sm + 13912;
  float* prm  = sm + 14040;

  int b = blockIdx.y;
  int t0 = blockIdx.x * TT;
  int tid = threadIdx.x;
  int plen = g_plen[b], flen = g_flen[b];
  bool active = (t0 < flen);

  if (active){
    if (tid < 40)      prm[tid] = Mw[tid];
    else if (tid < 44) prm[tid] = mbw[tid-40];
    else if (tid < 64) prm[tid] = Mc[tid-44];
    else if (tid < 66) prm[tid] = mbc[tid-64];
    __syncthreads();

    // ---- phase 1: conflict-free scalar plane stores ----
    if (tid < Ln){
      int l = tid;
      float dv = dur[b*Ln + l];
      float sk = g_sk[b*Ln + l];
      sk_s[l] = sk;
      const float* hwp = g_hw + ((size_t)b*Ln+l)*8;
      const float* hcp = g_hc + ((size_t)b*Ln+l)*8;
      float bw[4], bc[2];
      #pragma unroll
      for (int q=0;q<4;q++){
        float a = prm[40+q] + dv*prm[4+q];
        #pragma unroll
        for (int j=0;j<8;j++) a = fmaf(hwp[j], prm[(2+j)*4+q], a);
        bw[q]=a;
      }
      #pragma unroll
      for (int p=0;p<2;p++){
        float a = prm[64+p] + dv*prm[46+p];
        #pragma unroll
        for (int j=0;j<8;j++) a = fmaf(hcp[j], prm[44+(2+j)*2+p], a);
        bc[p]=a;
      }
      bc_s[2*l]   = bc[0];
      bc_s[2*l+1] = bc[1];
      bool lv = l < plen;
      #pragma unroll
      for (int t=0;t<TT;t++){
        int tt = t0+t;
        float4 av = {0.f,0.f,0.f,0.f};
        if (lv && tt < flen){
          float S = (float)(tt+1) - sk;
          av.x = silu_f(fmaf(S, prm[0], bw[0]));
          av.y = silu_f(fmaf(S, prm[1], bw[1]));
          av.z = silu_f(fmaf(S, prm[2], bw[2]));
          av.w = silu_f(fmaf(S, prm[3], bw[3]));
        }
        float* wp_ = w_s + (t*4)*WS + l;
        wp_[0]      = av.x;
        wp_[WS]     = av.y;
        wp_[2*WS]   = av.z;
        wp_[3*WS]   = av.w;
      }
    }
    __syncthreads();

    // ---- phase 2: softmax + f32 w out + bf16 W' export + wc reduce ----
    {
      int wp = tid>>5, lane = tid&31;
      float mc0 = prm[44], mc1 = prm[45];
      const size_t qs = (size_t)Tn*Ln;
      for (int t=wp; t<TT; t+=8){
        int tt = t0+t;
        if (tt >= Tn) continue;
        size_t wb = OFF_W + ((size_t)(b*4)*Tn + tt)*Ln;
        size_t rw = ((size_t)(b*1024)+tt)*KW;
        if (tt >= flen){
          for (int l=lane; l<Ln; l+=32){
            out[wb+l]=0.f; out[wb+qs+l]=0.f; out[wb+2*qs+l]=0.f; out[wb+3*qs+l]=0.f;
          }
          for (int k=lane; k<KW; k+=32){ g_wbf_hi[rw+k]=0; g_wbf_lo[rw+k]=0; }
          if (lane<8) wc_s[t*8+lane]=0.f;
          continue;
        }
        const float* wp0 = w_s + (t*4)*WS;
        float4 wv[7];
        float m0=-3e38f,m1=-3e38f,m2=-3e38f,m3=-3e38f;
        #pragma unroll
        for (int i=0;i<7;i++){
          int l = lane + 32*i;
          if (l < plen){
            wv[i].x = wp0[l];
            wv[i].y = wp0[WS+l];
            wv[i].z = wp0[2*WS+l];
            wv[i].w = wp0[3*WS+l];
            m0=fmaxf(m0,wv[i].x); m1=fmaxf(m1,wv[i].y); m2=fmaxf(m2,wv[i].z); m3=fmaxf(m3,wv[i].w);
          }
        }
        #pragma unroll
        for (int off=16;off;off>>=1){
          m0=fmaxf(m0,__shfl_xor_sync(0xffffffffu,m0,off));
          m1=fmaxf(m1,__shfl_xor_sync(0xffffffffu,m1,off));
          m2=fmaxf(m2,__shfl_xor_sync(0xffffffffu,m2,off));
          m3=fmaxf(m3,__shfl_xor_sync(0xffffffffu,m3,off));
        }
        float s0=0.f,s1=0.f,s2=0.f,s3=0.f;
        #pragma unroll
        for (int i=0;i<7;i++){
          int l = lane + 32*i;
          if (l < plen){
            wv[i].x=__expf(wv[i].x-m0); wv[i].y=__expf(wv[i].y-m1);
            wv[i].z=__expf(wv[i].z-m2); wv[i].w=__expf(wv[i].w-m3);
            s0+=wv[i].x; s1+=wv[i].y; s2+=wv[i].z; s3+=wv[i].w;
          }
        }
        #pragma unroll
        for (int off=16;off;off>>=1){
          s0+=__shfl_xor_sync(0xffffffffu,s0,off);
          s1+=__shfl_xor_sync(0xffffffffu,s1,off);
          s2+=__shfl_xor_sync(0xffffffffu,s2,off);
          s3+=__shfl_xor_sync(0xffffffffu,s3,off);
        }
        float i0=__fdividef(1.f,s0), i1=__fdividef(1.f,s1), i2=__fdividef(1.f,s2), i3=__fdividef(1.f,s3);
        float Sb = (float)(tt+1);
        float r0=0.f,r1=0.f,r2=0.f,r3=0.f,r4=0.f,r5=0.f,r6=0.f,r7=0.f;
        #pragma unroll
        for (int i=0;i<7;i++){
          int l = lane + 32*i;
          if (l < plen){
            float4 v; v.x=wv[i].x*i0; v.y=wv[i].y*i1; v.z=wv[i].z*i2; v.w=wv[i].w*i3;
            out[wb+l]=v.x; out[wb+qs+l]=v.y; out[wb+2*qs+l]=v.z; out[wb+3*qs+l]=v.w;
            unsigned short h,lo;
            bf_split(v.x,h,lo); g_wbf_hi[rw+l]=h;     g_wbf_lo[rw+l]=lo;
            bf_split(v.y,h,lo); g_wbf_hi[rw+200+l]=h; g_wbf_lo[rw+200+l]=lo;
            bf_split(v.z,h,lo); g_wbf_hi[rw+400+l]=h; g_wbf_lo[rw+400+l]=lo;
            bf_split(v.w,h,lo); g_wbf_hi[rw+600+l]=h; g_wbf_lo[rw+600+l]=lo;
            float S = Sb - sk_s[l];
            float cx = silu_f(fmaf(S, mc0, bc_s[2*l]));
            float cy = silu_f(fmaf(S, mc1, bc_s[2*l+1]));
            r0=fmaf(v.x,cx,r0); r1=fmaf(v.x,cy,r1);
            r2=fmaf(v.y,cx,r2); r3=fmaf(v.y,cy,r3);
            r4=fmaf(v.z,cx,r4); r5=fmaf(v.z,cy,r5);
            r6=fmaf(v.w,cx,r6); r7=fmaf(v.w,cy,r7);
          } else if (l < Ln){
            out[wb+l]=0.f; out[wb+qs+l]=0.f; out[wb+2*qs+l]=0.f; out[wb+3*qs+l]=0.f;
            g_wbf_hi[rw+l]=0;     g_wbf_lo[rw+l]=0;
            g_wbf_hi[rw+200+l]=0; g_wbf_lo[rw+200+l]=0;
            g_wbf_hi[rw+400+l]=0; g_wbf_lo[rw+400+l]=0;
            g_wbf_hi[rw+600+l]=0; g_wbf_lo[rw+600+l]=0;
          }
        }
        #pragma unroll
        for (int off=16;off;off>>=1){
          r0+=__shfl_xor_sync(0xffffffffu,r0,off); r1+=__shfl_xor_sync(0xffffffffu,r1,off);
          r2+=__shfl_xor_sync(0xffffffffu,r2,off); r3+=__shfl_xor_sync(0xffffffffu,r3,off);
          r4+=__shfl_xor_sync(0xffffffffu,r4,off); r5+=__shfl_xor_sync(0xffffffffu,r5,off);
          r6+=__shfl_xor_sync(0xffffffffu,r6,off); r7+=__shfl_xor_sync(0xffffffffu,r7,off);
        }
        if (lane==0){
          wc_s[t*8+0]=r0; wc_s[t*8+1]=r1; wc_s[t*8+2]=r2; wc_s[t*8+3]=r3;
          wc_s[t*8+4]=r4; wc_s[t*8+5]=r5; wc_s[t*8+6]=r6; wc_s[t*8+7]=r7;
        }
      }
    }
    __syncthreads();

    // ---- tail: W' rows k=800..831 (wc, bias, pad) ----
    for (int x=tid; x<TT*32; x+=256){
      int t = x>>5, j = x&31;
      int tt = t0+t;
      if (tt >= Tn) continue;
      float v = 0.f;
      if (j < 8)      v = wc_s[t*8+j];
      else if (j == 8) v = (tt < flen) ? 1.f : 0.f;
      unsigned short h,lo; bf_split(v,h,lo);
      size_t rw = ((size_t)(b*1024)+tt)*KW;
      g_wbf_hi[rw+800+j]=h; g_wbf_lo[rw+800+j]=lo;
    }
  } else {
    // inactive: zero w planes + zero W' rows
    int wp = tid>>5, lane = tid&31;
    const size_t qs = (size_t)Tn*Ln;
    for (int t=wp; t<TT; t+=8){
      int tt = t0+t;
      if (tt >= Tn) continue;
      size_t wb = OFF_W + ((size_t)(b*4)*Tn + tt)*Ln;
      for (int l=lane; l<Ln; l+=32){
        out[wb+l]=0.f; out[wb+qs+l]=0.f; out[wb+2*qs+l]=0.f; out[wb+3*qs+l]=0.f;
      }
    }
    for (int t=0;t<TT;t++){
      int tt = t0+t;
      if (tt >= Tn) break;
      size_t rw = ((size_t)(b*1024)+tt)*KW;
      for (int k=tid;k<KW;k+=256){ g_wbf_hi[rw+k]=0; g_wbf_lo[rw+k]=0; }
    }
  }
}

// ================= K_COMB: Y = W' @ P'  (cp.async double-buffered, M128xN64) =================
#define KC_ST 49152
#define KC_SMEM 98304

__global__ __launch_bounds__(256,2) void k_comb(){
  extern __shared__ float smf[];
  char* smc = (char*)smf;
  uint32_t sb = smem_u32(smc);
  int tid = threadIdx.x, wid = tid>>5, lane = tid&31;
  int mtile = blockIdx.x, ntile = blockIdx.y, b = blockIdx.z;

  if (mtile*128 >= g_flen[b]){
    uint4 z; z.x=0u; z.y=0u; z.z=0u; z.w=0u;
    #pragma unroll
    for (int i=0;i<4;i++){
      int lin = i*256 + tid;
      int r = lin>>3, ch = lin&7;
      int t = mtile*128 + r;
      if (t < Tn){
        size_t row = (size_t)b*Tn + t;
        ((uint4*)(g_yhi + row*Dn + ntile*64))[ch] = z;
        ((uint4*)(g_ylo + row*Dn + ntile*64))[ch] = z;
      }
    }
    return;
  }

  float acc[2][4][4];
  #pragma unroll
  for (int mt=0;mt<2;mt++)
    #pragma unroll
    for (int ng=0;ng<4;ng++){ acc[mt][ng][0]=0.f; acc[mt][ng][1]=0.f; acc[mt][ng][2]=0.f; acc[mt][ng][3]=0.f; }

  int m0 = (wid&3)*32, n0 = (wid>>2)*32;

  const uint4* gwh = (const uint4*)(g_wbf_hi + ((size_t)(b*1024) + (size_t)mtile*128)*KW);
  const uint4* gwl = (const uint4*)(g_wbf_lo + ((size_t)(b*1024) + (size_t)mtile*128)*KW);
  const uint4* gph = (const uint4*)(g_pbf_hi + ((size_t)(b*Dn) + (size_t)ntile*64)*KW);
  const uint4* gpl = (const uint4*)(g_pbf_lo + ((size_t)(b*Dn) + (size_t)ntile*64)*KW);
  const int rs = KW/8;   // 104

  int srow = tid>>3, sch = tid&7;
  uint32_t soff = (uint32_t)(srow*128 + ((sch ^ (srow&7))<<4));

  #define KC_ISSUE(c, s) do{                                              \
    uint32_t base_ = sb + (uint32_t)(s)*KC_ST;                            \
    _Pragma("unroll")                                                     \
    for (int i_=0;i_<4;i_++){                                             \
      uint32_t off_ = soff + (uint32_t)(i_*32*128);                       \
      size_t g_ = (size_t)(srow + i_*32)*rs + (c)*8 + sch;                \
      CP16(base_ + off_,          gwh + g_);                              \
      CP16(base_ + 16384 + off_,  gwl + g_);                              \
    }                                                                     \
    _Pragma("unroll")                                                     \
    for (int i_=0;i_<2;i_++){                                             \
      uint32_t off_ = soff + (uint32_t)(i_*32*128);                       \
      size_t g_ = (size_t)(srow + i_*32)*rs + (c)*8 + sch;                \
      CP16(base_ + 32768 + off_,  gph + g_);                              \
      CP16(base_ + 40960 + off_,  gpl + g_);                              \
    }                                                                     \
    CP_COMMIT();                                                          \
  }while(0)

  KC_ISSUE(0, 0);
  for (int c=0;c<13;c++){
    int s = c & 1;
    if (c+1 < 13){ KC_ISSUE(c+1, s^1); CP_WAIT1(); }
    else         { CP_WAIT0(); }
    __syncthreads();
    uint32_t stb = sb + (uint32_t)s*KC_ST;
    #pragma unroll
    for (int kk=0;kk<4;kk++){
      uint32_t aH[2][4], aL[2][4];
      #pragma unroll
      for (int mt=0;mt<2;mt++){
        int arow = m0 + mt*16 + (lane&15);
        uint32_t aoff = (uint32_t)(arow*128 + (((kk*2 + (lane>>4)) ^ (arow&7))<<4));
        ldsm4(aH[mt][0],aH[mt][1],aH[mt][2],aH[mt][3], stb + aoff);
        ldsm4(aL[mt][0],aL[mt][1],aL[mt][2],aL[mt][3], stb + 16384 + aoff);
      }
      #pragma unroll
      for (int g2=0;g2<2;g2++){
        int nrow = n0 + g2*16 + ((lane>>4)<<3) + (lane&7);
        uint32_t boff = (uint32_t)(nrow*128 + (((kk*2 + ((lane>>3)&1)) ^ (nrow&7))<<4));
        uint32_t bh0,bh1,bh2,bh3, bl0,bl1,bl2,bl3;
        ldsm4(bh0,bh1,bh2,bh3, stb + 32768 + boff);
        ldsm4(bl0,bl1,bl2,bl3, stb + 40960 + boff);
        #pragma unroll
        for (int mt=0;mt<2;mt++){
          mma16816(acc[mt][g2*2],   aH[mt], bh0, bh1);
          mma16816(acc[mt][g2*2],   aL[mt], bh0, bh1);
          mma16816(acc[mt][g2*2],   aH[mt], bl0, bl1);
          mma16816(acc[mt][g2*2+1], aH[mt], bh2, bh3);
          mma16816(acc[mt][g2*2+1], aL[mt], bh2, bh3);
          mma16816(acc[mt][g2*2+1], aH[mt], bl2, bl3);
        }
      }
    }
    __syncthreads();
  }

  #pragma unroll
  for (int mt=0;mt<2;mt++){
    #pragma unroll
    for (int ng=0;ng<4;ng++){
      int d = ntile*64 + n0 + ng*8 + (lane&3)*2;
      #pragma unroll
      for (int half=0;half<2;half++){
        int t = mtile*128 + m0 + mt*16 + (lane>>2) + half*8;
        if (t < Tn){
          size_t row = (size_t)b*Tn + t;
          unsigned short h0,l0,h1,l1;
          bf_split(acc[mt][ng][half*2+0], h0, l0);
          bf_split(acc[mt][ng][half*2+1], h1, l1);
          ushort2 hh; hh.x=h0; hh.y=h1;
          ushort2 ll; ll.x=l0; ll.y=l1;
          *(ushort2*)&g_yhi[row*Dn + d] = hh;
          *(ushort2*)&g_ylo[row*Dn + d] = ll;
        }
      }
    }
  }
}

// ================= K_OUT: out = y @ Wo + bo  (cp.async double-buffered) =================
#define KO_ST 49152
#define KO_SMEM 98304

__global__ __launch_bounds__(256,2) void k_out(const float* __restrict__ bo,
                                               float* __restrict__ out){
  extern __shared__ float smf[];
  char* smc = (char*)smf;
  uint32_t sb = smem_u32(smc);
  int tid = threadIdx.x, wid = tid>>5, lane = tid&31;
  int mtile = blockIdx.x, ntile = blockIdx.y;

  {
    int mstart = mtile*128;
    int b0 = mstart/Tn, b1 = (mstart+127)/Tn;
    int t_start = mstart - b0*Tn;
    bool dead = (t_start >= g_flen[b0]) && (b1==b0 || g_flen[b1]<=0);
    if (dead){
      int r = tid & 127;
      int m = mtile*128 + r;
      int b = m/Tn, t = m - b*Tn;
      size_t plane = (ntile<4)?OFF_MEAN:OFF_LOG;
      int colbase = ntile*64 - ((ntile>=4)?256:0);
      const float* bop = bo + ntile*64;
      for (int i = tid>>7; i<64; i+=2)
        out[plane + ((size_t)(b*Dn + colbase + i))*Tn + t] = bop[i];
      return;
    }
  }

  float acc[2][4][4];
  #pragma unroll
  for (int mt=0;mt<2;mt++)
    #pragma unroll
    for (int ng=0;ng<4;ng++){ acc[mt][ng][0]=0.f; acc[mt][ng][1]=0.f; acc[mt][ng][2]=0.f; acc[mt][ng][3]=0.f; }

  int m0 = (wid&3)*32, n0 = (wid>>2)*32;

  const uint4* aH_g = (const uint4*)(g_yhi + (size_t)(mtile*128)*Dn);
  const uint4* aL_g = (const uint4*)(g_ylo + (size_t)(mtile*128)*Dn);
  const uint4* bH_g = (const uint4*)(g_woThi + (size_t)(ntile*64)*256);
  const uint4* bL_g = (const uint4*)(g_woTlo + (size_t)(ntile*64)*256);

  int srow = tid>>3, sch = tid&7;
  uint32_t soff = (uint32_t)(srow*128 + ((sch ^ (srow&7))<<4));

  #define KO_ISSUE(c, s) do{                                              \
    uint32_t base_ = sb + (uint32_t)(s)*KO_ST;                            \
    _Pragma("unroll")                                                     \
    for (int i_=0;i_<4;i_++){                                             \
      uint32_t off_ = soff + (uint32_t)(i_*32*128);                       \
      size_t g_ = (size_t)(srow + i_*32)*32 + (c)*8 + sch;                \
      CP16(base_ + off_,         aH_g + g_);                              \
      CP16(base_ + 16384 + off_, aL_g + g_);                              \
    }                                                                     \
    _Pragma("unroll")                                                     \
    for (int i_=0;i_<2;i_++){                                             \
      uint32_t off_ = soff + (uint32_t)(i_*32*128);                       \
      size_t g_ = (size_t)(srow + i_*32)*32 + (c)*8 + sch;                \
      CP16(base_ + 32768 + off_, bH_g + g_);                              \
      CP16(base_ + 40960 + off_, bL_g + g_);                              \
    }                                                                     \
    CP_COMMIT();                                                          \
  }while(0)

  KO_ISSUE(0, 0);
  for (int c=0;c<4;c++){
    int s = c & 1;
    if (c+1 < 4){ KO_ISSUE(c+1, s^1); CP_WAIT1(); }
    else        { CP_WAIT0(); }
    __syncthreads();
    uint32_t stb = sb + (uint32_t)s*KO_ST;
    #pragma unroll
    for (int kk=0;kk<4;kk++){
      uint32_t aH[2][4], aL[2][4];
      #pragma unroll
      for (int mt=0;mt<2;mt++){
        int arow = m0 + mt*16 + (lane&15);
        uint32_t aoff = (uint32_t)(arow*128 + (((kk*2 + (lane>>4)) ^ (arow&7))<<4));
        ldsm4(aH[mt][0],aH[mt][1],aH[mt][2],aH[mt][3], stb + aoff);
        ldsm4(aL[mt][0],aL[mt][1],aL[mt][2],aL[mt][3], stb + 16384 + aoff);
      }
      #pragma unroll
      for (int g2=0;g2<2;g2++){
        int nrow = n0 + g2*16 + ((lane>>4)<<3) + (lane&7);
        uint32_t boff = (uint32_t)(nrow*128 + (((kk*2 + ((lane>>3)&1)) ^ (nrow&7))<<4));
        uint32_t bh0,bh1,bh2,bh3, bl0,bl1,bl2,bl3;
        ldsm4(bh0,bh1,bh2,bh3, stb + 32768 + boff);
        ldsm4(bl0,bl1,bl2,bl3, stb + 40960 + boff);
        #pragma unroll
        for (int mt=0;mt<2;mt++){
          mma16816(acc[mt][g2*2],   aH[mt], bh0, bh1);
          mma16816(acc[mt][g2*2],   aL[mt], bh0, bh1);
          mma16816(acc[mt][g2*2],   aH[mt], bl0, bl1);
          mma16816(acc[mt][g2*2+1], aH[mt], bh2, bh3);
          mma16816(acc[mt][g2*2+1], aL[mt], bh2, bh3);
          mma16816(acc[mt][g2*2+1], aH[mt], bl2, bl3);
        }
      }
    }
    __syncthreads();
  }

  {
    size_t plane = (ntile < 4) ? OFF_MEAN : OFF_LOG;
    int colbase = ntile*64 - ((ntile>=4)?256:0);
    const float* bop = bo + ntile*64;
    #pragma unroll
    for (int mt=0;mt<2;mt++){
      #pragma unroll
      for (int ng=0;ng<4;ng++){
        int cin = n0 + ng*8 + 2*(lane&3);
        float b0v = bop[cin], b1v = bop[cin+1];
        #pragma unroll
        for (int half=0;half<2;half++){
          int m_g = mtile*128 + m0 + mt*16 + (lane>>2) + half*8;
          int b = m_g / Tn;
          int t = m_g - b*Tn;
          size_t base = plane + ((size_t)(b*Dn + colbase + cin))*Tn + t;
          out[base]      = acc[mt][ng][half*2+0] + b0v;
          out[base + Tn] = acc[mt][ng][half*2+1] + b1v;
        }
      }
    }
  }
}

// ---------------- launcher ----------------
extern "C" void kernel_launch(void* const* d_in, const int* in_sizes, int n_in,
                              void* d_out, int out_size){
  (void)in_sizes; (void)n_in; (void)out_size;
  const float* dur = (const float*)d_in[0];
  const float* phon= (const float*)d_in[1];
  const float* Wpw = (const float*)d_in[3];
  const float* bpw = (const float*)d_in[4];
  const float* Cw  = (const float*)d_in[5];
  const float* cbw = (const float*)d_in[6];
  const float* Mw  = (const float*)d_in[7];
  const float* mbw = (const float*)d_in[8];
  const float* Lw  = (const float*)d_in[9];
  const float* lbw = (const float*)d_in[10];
  const float* Wpc = (const float*)d_in[11];
  const float* bpc = (const float*)d_in[12];
  const float* Cc  = (const float*)d_in[13];
  const float* cbc = (const float*)d_in[14];
  const float* Mc  = (const float*)d_in[15];
  const float* mbc = (const float*)d_in[16];
  const float* Lcm = (const float*)d_in[17];
  const float* lbc = (const float*)d_in[18];
  const float* Wo  = (const float*)d_in[19];
  const float* bo  = (const float*)d_in[20];
  float* out = (float*)d_out;

  cudaFuncSetAttribute((const void*)k_main, cudaFuncAttributeMaxDynamicSharedMemorySize,
                       SMEM_BYTES);
  cudaFuncSetAttribute((const void*)k_midp, cudaFuncAttributeMaxDynamicSharedMemorySize,
                       KP_SMEM);
  cudaFuncSetAttribute((const void*)k_comb, cudaFuncAttributeMaxDynamicSharedMemorySize,
                       KC_SMEM);
  cudaFuncSetAttribute((const void*)k_out, cudaFuncAttributeMaxDynamicSharedMemorySize,
                       KO_SMEM);

  k_pre<<<1236,256>>>(dur, phon, Cw, Wpw, Cc, Wpc, bpw, cbw, bpc, cbc, Wo, Lw, Lcm, lbw, lbc, out);
  k_midp<<<912,256,KP_SMEM>>>();
  k_main<<<dim3(NB,Bn),256,SMEM_BYTES>>>(dur,Mw,mbw,Mc,mbc,out);
  k_comb<<<dim3(8,4,Bn),256,KC_SMEM>>>();
  k_out<<<dim3(125,8),256,KO_SMEM>>>(bo,out);
}